// round 1
// baseline (speedup 1.0000x reference)
#include <cuda_runtime.h>
#include <math.h>
#include <stdint.h>

#define Bq 128
#define Hq 512
#define LCq 256
#define LTq 64
#define Vq 27
#define NLq 2
#define H3q (3*Hq)
#define KT 32

// ---------------- scratch (device globals: allocation-free rule) ----------------
__device__ float g_xr[LCq*Bq*Hq];                    // [l][b][h] encoder input proj
__device__ float g_gi[(size_t)2*LCq*Bq*H3q];         // [dir][t][b][3H] precomputed input gates
__device__ float g_y0[(size_t)LCq*Bq*2*Hq];          // [t][b][2H] layer0 outputs (fwd|bwd)
__device__ float g_y1[(size_t)LCq*Bq*2*Hq];          // [t][b][2H] layer1 outputs
__device__ float g_v [(size_t)LCq*Bq*Hq];            // [l][b][h] bi_fc output
__device__ float g_vn[LCq*Bq];                       // [l][b] norms
__device__ float g_hd[2][NLq][Bq*Hq];                // decoder hidden, double buffered
__device__ float g_a [Bq*Hq];                        // attention context
__device__ float g_hid[Bq*Hq];                       // attention_fc output
__device__ int   g_vecin[Bq];                        // greedy feedback token

// ---------------- encoder input projection ----------------
__global__ void k_proj(const float* __restrict__ x, const float* __restrict__ W_enc,
                       const float* __restrict__ b_enc) {
    int idx = blockIdx.x * blockDim.x + threadIdx.x;
    if (idx >= LCq*Bq*Hq) return;
    int h = idx % Hq; int bl = idx / Hq; int b = bl % Bq; int l = bl / Bq;
    float v = x[(size_t)b*2*LCq + l] * W_enc[h*2]
            + x[(size_t)b*2*LCq + LCq + l] * W_enc[h*2+1] + b_enc[h];
    g_xr[idx] = v;
}

// ---------------- batched SGEMM: C[M,N] = A[M,K] @ W[N,K]^T + bias ----------------
// BM=128, BN=64, BK=16, 256 threads, 8x4 per thread. M fixed at LC*B via grid.y.
__device__ __forceinline__ void sgemm_body(const float* __restrict__ A,
                                           const float* __restrict__ W,
                                           const float* __restrict__ bias,
                                           float* __restrict__ C, int N, int K) {
    __shared__ float As[16][129];
    __shared__ float Ws[16][65];
    int tid = threadIdx.x;
    int tx = tid & 15, ty = tid >> 4;
    int row0 = blockIdx.y * 128, col0 = blockIdx.x * 64;
    float acc[8][4];
    #pragma unroll
    for (int i = 0; i < 8; i++)
        #pragma unroll
        for (int j = 0; j < 4; j++) acc[i][j] = 0.f;

    for (int k0 = 0; k0 < K; k0 += 16) {
        #pragma unroll
        for (int j = 0; j < 2; j++) {
            int lin = tid + j*256;
            int r = lin >> 2, kk = (lin & 3) << 2;
            float4 a4 = *(const float4*)(A + (size_t)(row0 + r)*K + k0 + kk);
            As[kk][r] = a4.x; As[kk+1][r] = a4.y; As[kk+2][r] = a4.z; As[kk+3][r] = a4.w;
        }
        {
            int n = tid >> 2, kk = (tid & 3) << 2;
            float4 w4 = *(const float4*)(W + (size_t)(col0 + n)*K + k0 + kk);
            Ws[kk][n] = w4.x; Ws[kk+1][n] = w4.y; Ws[kk+2][n] = w4.z; Ws[kk+3][n] = w4.w;
        }
        __syncthreads();
        #pragma unroll
        for (int k = 0; k < 16; k++) {
            float ar[8], wr[4];
            #pragma unroll
            for (int i = 0; i < 8; i++) ar[i] = As[k][ty*8 + i];
            #pragma unroll
            for (int j = 0; j < 4; j++) wr[j] = Ws[k][tx*4 + j];
            #pragma unroll
            for (int i = 0; i < 8; i++)
                #pragma unroll
                for (int j = 0; j < 4; j++)
                    acc[i][j] = fmaf(ar[i], wr[j], acc[i][j]);
        }
        __syncthreads();
    }
    #pragma unroll
    for (int i = 0; i < 8; i++) {
        int r = row0 + ty*8 + i;
        #pragma unroll
        for (int j = 0; j < 4; j++) {
            int c = col0 + tx*4 + j;
            C[(size_t)r*N + c] = acc[i][j] + bias[c];
        }
    }
}

__global__ void k_gemm_gi0(const float* __restrict__ Wih, const float* __restrict__ bih) {
    int dir = blockIdx.z;
    sgemm_body(g_xr, Wih + (size_t)dir*H3q*Hq, bih + dir*H3q,
               g_gi + (size_t)dir*LCq*Bq*H3q, H3q, Hq);
}
__global__ void k_gemm_gi1(const float* __restrict__ Wih, const float* __restrict__ bih) {
    int dir = blockIdx.z;
    sgemm_body(g_y0, Wih + (size_t)dir*H3q*2*Hq, bih + dir*H3q,
               g_gi + (size_t)dir*LCq*Bq*H3q, H3q, 2*Hq);
}
__global__ void k_gemm_bi(const float* __restrict__ Wb, const float* __restrict__ bb) {
    sgemm_body(g_y1, Wb, bb, g_v, Hq, 2*Hq);
}

// ---------------- encoder GRU recurrent step (both dirs per launch) ----------------
// tile: 64 batch rows x 16 h cols, 3 gate dots each. grid (32, 2, 2), 256 threads.
__global__ void k_gru_enc(const float* __restrict__ Whh2, const float* __restrict__ bhh2,
                          int layer, int s) {
    float* Y = layer ? g_y1 : g_y0;
    int dir = blockIdx.z;
    int t = dir ? (LCq-1-s) : s;
    int tprev = dir ? (t+1) : (t-1);
    const float* Whh = Whh2 + (size_t)dir*H3q*Hq;
    const float* bhh = bhh2 + dir*H3q;
    const float* gi  = g_gi + ((size_t)dir*LCq + t)*Bq*H3q;

    int tid = threadIdx.x;
    int tx = tid & 15, ty = tid >> 4;
    int col0 = blockIdx.x * 16, row0 = blockIdx.y * 64;

    __shared__ float Hs[KT][65];
    __shared__ float Ws[3][KT][17];

    float racc[4] = {0,0,0,0}, zacc[4] = {0,0,0,0}, nacc[4] = {0,0,0,0};

    if (s > 0) {
        const float* Hp = Y + (size_t)tprev*Bq*2*Hq + (size_t)dir*Hq;
        for (int k0 = 0; k0 < Hq; k0 += KT) {
            #pragma unroll
            for (int j = 0; j < 2; j++) {
                int lin = tid + j*256;
                int r = lin >> 3, kk = (lin & 7) << 2;
                float4 h4 = *(const float4*)(Hp + (size_t)(row0 + r)*2*Hq + k0 + kk);
                Hs[kk][r]=h4.x; Hs[kk+1][r]=h4.y; Hs[kk+2][r]=h4.z; Hs[kk+3][r]=h4.w;
            }
            #pragma unroll
            for (int j = 0; j < 6; j++) {
                int lin = tid + j*256;
                int rr = lin >> 5, k = lin & 31;
                int g = rr >> 4, c = rr & 15;
                Ws[g][k][c] = Whh[(size_t)(g*Hq + col0 + c)*Hq + k0 + k];
            }
            __syncthreads();
            #pragma unroll
            for (int k = 0; k < KT; k++) {
                float wr = Ws[0][k][tx], wz = Ws[1][k][tx], wn = Ws[2][k][tx];
                #pragma unroll
                for (int i = 0; i < 4; i++) {
                    float hv = Hs[k][ty + 16*i];
                    racc[i] = fmaf(hv, wr, racc[i]);
                    zacc[i] = fmaf(hv, wz, zacc[i]);
                    nacc[i] = fmaf(hv, wn, nacc[i]);
                }
            }
            __syncthreads();
        }
    }
    int c = col0 + tx;
    float br = bhh[c], bz = bhh[Hq + c], bn = bhh[2*Hq + c];
    #pragma unroll
    for (int i = 0; i < 4; i++) {
        int b = row0 + ty + 16*i;
        const float* gib = gi + (size_t)b*H3q;
        float hp = (s > 0) ? Y[((size_t)tprev*Bq + b)*2*Hq + dir*Hq + c] : 0.f;
        float r = 1.f/(1.f + expf(-(gib[c]        + racc[i] + br)));
        float z = 1.f/(1.f + expf(-(gib[Hq + c]   + zacc[i] + bz)));
        float n = tanhf(gib[2*Hq + c] + r*(nacc[i] + bn));
        Y[((size_t)t*Bq + b)*2*Hq + dir*Hq + c] = (1.f - z)*n + z*hp;
    }
}

// ---------------- decoder GRU step (one layer per launch) ----------------
// tile: 32 batch rows x 16 h cols, 6 dots each. grid (32, 4), 256 threads.
__global__ void k_gru_dec(const float* __restrict__ Wih, const float* __restrict__ Whh,
                          const float* __restrict__ bih, const float* __restrict__ bhh,
                          const float* __restrict__ emb, int layer, int p) {
    const float* hprev = g_hd[p][layer];
    const float* xin   = (layer == 0) ? (const float*)nullptr : g_hd[1-p][0];
    float* hout        = g_hd[1-p][layer];

    int tid = threadIdx.x;
    int tx = tid & 15, ty = tid >> 4;
    int col0 = blockIdx.x * 16, row0 = blockIdx.y * 32;

    __shared__ float Xs[KT][33];
    __shared__ float Hs[KT][33];
    __shared__ float Wi[3][KT][17];
    __shared__ float Wh[3][KT][17];
    __shared__ int vs[32];

    if (layer == 0 && tid < 32) vs[tid] = g_vecin[row0 + tid];
    __syncthreads();

    float rs[2] = {0,0}, zs[2] = {0,0}, nis[2] = {0,0}, nhs[2] = {0,0};

    for (int k0 = 0; k0 < Hq; k0 += KT) {
        {
            int r = tid >> 3, kk = (tid & 7) << 2;
            const float* xb = (layer == 0) ? (emb + (size_t)vs[r]*Hq)
                                           : (xin + (size_t)(row0 + r)*Hq);
            float4 x4 = *(const float4*)(xb + k0 + kk);
            Xs[kk][r]=x4.x; Xs[kk+1][r]=x4.y; Xs[kk+2][r]=x4.z; Xs[kk+3][r]=x4.w;
            float4 h4 = *(const float4*)(hprev + (size_t)(row0 + r)*Hq + k0 + kk);
            Hs[kk][r]=h4.x; Hs[kk+1][r]=h4.y; Hs[kk+2][r]=h4.z; Hs[kk+3][r]=h4.w;
        }
        #pragma unroll
        for (int j = 0; j < 6; j++) {
            int lin = tid + j*256;
            int rr = lin >> 5, k = lin & 31;
            int g = rr >> 4, c = rr & 15;
            Wi[g][k][c] = Wih[(size_t)(g*Hq + col0 + c)*Hq + k0 + k];
            Wh[g][k][c] = Whh[(size_t)(g*Hq + col0 + c)*Hq + k0 + k];
        }
        __syncthreads();
        #pragma unroll
        for (int k = 0; k < KT; k++) {
            float wir = Wi[0][k][tx], wiz = Wi[1][k][tx], win = Wi[2][k][tx];
            float whr = Wh[0][k][tx], whz = Wh[1][k][tx], whn = Wh[2][k][tx];
            #pragma unroll
            for (int i = 0; i < 2; i++) {
                float xv = Xs[k][ty + 16*i], hv = Hs[k][ty + 16*i];
                rs[i]  = fmaf(xv, wir, rs[i]);  rs[i]  = fmaf(hv, whr, rs[i]);
                zs[i]  = fmaf(xv, wiz, zs[i]);  zs[i]  = fmaf(hv, whz, zs[i]);
                nis[i] = fmaf(xv, win, nis[i]);
                nhs[i] = fmaf(hv, whn, nhs[i]);
            }
        }
        __syncthreads();
    }
    int c = col0 + tx;
    float bir = bih[c], biz = bih[Hq+c], bin = bih[2*Hq+c];
    float bhr = bhh[c], bhz = bhh[Hq+c], bhn = bhh[2*Hq+c];
    #pragma unroll
    for (int i = 0; i < 2; i++) {
        int b = row0 + ty + 16*i;
        float hp = hprev[(size_t)b*Hq + c];
        float r = 1.f/(1.f + expf(-(rs[i] + bir + bhr)));
        float z = 1.f/(1.f + expf(-(zs[i] + biz + bhz)));
        float n = tanhf(nis[i] + bin + r*(nhs[i] + bhn));
        hout[(size_t)b*Hq + c] = (1.f - z)*n + z*hp;
    }
}

// ---------------- v row norms ----------------
__global__ void k_vn() {
    int row = blockIdx.x;                 // LC*B rows
    int tid = threadIdx.x;                // 128
    const float* vr = g_v + (size_t)row*Hq;
    float s = 0.f;
    for (int k = tid; k < Hq; k += 128) { float x = vr[k]; s = fmaf(x, x, s); }
    __shared__ float red[128];
    red[tid] = s; __syncthreads();
    for (int o = 64; o > 0; o >>= 1) { if (tid < o) red[tid] += red[tid + o]; __syncthreads(); }
    if (tid == 0) g_vn[row] = fmaxf(sqrtf(red[0]), 1e-8f);
}

// ---------------- decoder init ----------------
__global__ void k_initdec() {
    int idx = blockIdx.x * blockDim.x + threadIdx.x;
    if (idx < Bq) g_vecin[idx] = 0;
    if (idx < Bq*Hq) {
        int b = idx / Hq, h = idx % Hq;
        g_hd[0][0][idx] = g_y0[((size_t)(LCq-1)*Bq + b)*2*Hq + h];        // hf0
        g_hd[0][1][idx] = g_y0[((size_t)b)*2*Hq + Hq + h];                // hb0
    }
}

// ---------------- attention: cosine sim + softmax + context ----------------
__global__ void k_attn(int t, int w, float* __restrict__ attn_out) {
    int b = blockIdx.x;
    int tid = threadIdx.x;                // 256 == LC
    __shared__ __align__(16) float qs[Hq];
    __shared__ float red[256];
    __shared__ float wsm[LCq];

    const float* q = g_hd[w][1] + (size_t)b*Hq;
    qs[tid] = q[tid]; qs[tid + 256] = q[tid + 256];
    __syncthreads();

    float ss = qs[tid]*qs[tid] + qs[tid+256]*qs[tid+256];
    red[tid] = ss; __syncthreads();
    for (int o = 128; o > 0; o >>= 1) { if (tid < o) red[tid] += red[tid + o]; __syncthreads(); }
    float qn = fmaxf(sqrtf(red[0]), 1e-8f);
    __syncthreads();

    const float4* v4 = (const float4*)(g_v + ((size_t)tid*Bq + b)*Hq);
    const float4* q4 = (const float4*)qs;
    float dot = 0.f;
    #pragma unroll 4
    for (int k = 0; k < Hq/4; k++) {
        float4 a = v4[k], c = q4[k];
        dot = fmaf(a.x, c.x, dot); dot = fmaf(a.y, c.y, dot);
        dot = fmaf(a.z, c.z, dot); dot = fmaf(a.w, c.w, dot);
    }
    float sim = dot / (g_vn[(size_t)tid*Bq + b] * qn);

    red[tid] = sim; __syncthreads();
    for (int o = 128; o > 0; o >>= 1) { if (tid < o) red[tid] = fmaxf(red[tid], red[tid+o]); __syncthreads(); }
    float mx = red[0]; __syncthreads();
    float e = expf(sim - mx);
    red[tid] = e; __syncthreads();
    for (int o = 128; o > 0; o >>= 1) { if (tid < o) red[tid] += red[tid + o]; __syncthreads(); }
    float wv = e / red[0];
    wsm[tid] = wv;
    attn_out[((size_t)b*LCq + tid)*LTq + t] = wv;
    __syncthreads();

    for (int h = tid; h < Hq; h += 256) {
        float acc = 0.f;
        for (int l = 0; l < LCq; l++)
            acc = fmaf(wsm[l], g_v[((size_t)l*Bq + b)*Hq + h], acc);
        g_a[(size_t)b*Hq + h] = acc;
    }
}

// ---------------- attention_fc: hid = [q, a] @ W_att^T + b_att ----------------
__global__ void k_attfc(const float* __restrict__ Watt, const float* __restrict__ batt, int w) {
    const float* X1 = g_hd[w][1];
    const float* X2 = g_a;
    int tid = threadIdx.x;
    int tx = tid & 15, ty = tid >> 4;
    int col0 = blockIdx.x * 16, row0 = blockIdx.y * 32;

    __shared__ float Xs[KT][33];
    __shared__ float As2[KT][33];
    __shared__ float Wq[KT][17];
    __shared__ float Wa[KT][17];

    float acc[2] = {0,0};
    for (int k0 = 0; k0 < Hq; k0 += KT) {
        {
            int r = tid >> 3, kk = (tid & 7) << 2;
            float4 x4 = *(const float4*)(X1 + (size_t)(row0 + r)*Hq + k0 + kk);
            Xs[kk][r]=x4.x; Xs[kk+1][r]=x4.y; Xs[kk+2][r]=x4.z; Xs[kk+3][r]=x4.w;
            float4 a4 = *(const float4*)(X2 + (size_t)(row0 + r)*Hq + k0 + kk);
            As2[kk][r]=a4.x; As2[kk+1][r]=a4.y; As2[kk+2][r]=a4.z; As2[kk+3][r]=a4.w;
        }
        #pragma unroll
        for (int j = 0; j < 2; j++) {
            int lin = tid + j*256;         // 0..511
            int c = lin >> 5, k = lin & 31;
            Wq[k][c] = Watt[(size_t)(col0 + c)*2*Hq + k0 + k];
            Wa[k][c] = Watt[(size_t)(col0 + c)*2*Hq + Hq + k0 + k];
        }
        __syncthreads();
        #pragma unroll
        for (int k = 0; k < KT; k++) {
            float wq = Wq[k][tx], wa = Wa[k][tx];
            #pragma unroll
            for (int i = 0; i < 2; i++) {
                acc[i] = fmaf(Xs[k][ty + 16*i], wq, acc[i]);
                acc[i] = fmaf(As2[k][ty + 16*i], wa, acc[i]);
            }
        }
        __syncthreads();
    }
    int c = col0 + tx;
    #pragma unroll
    for (int i = 0; i < 2; i++) {
        int b = row0 + ty + 16*i;
        g_hid[(size_t)b*Hq + c] = acc[i] + batt[c];
    }
}

// ---------------- output logits + argmax feedback ----------------
__global__ void k_out(const float* __restrict__ Wout, const float* __restrict__ bout,
                      int t, float* __restrict__ vecout) {
    int b = blockIdx.x;
    int tid = threadIdx.x;                // 256
    __shared__ float hs[Hq];
    __shared__ float lg[32];
    hs[tid] = g_hid[(size_t)b*Hq + tid];
    hs[tid + 256] = g_hid[(size_t)b*Hq + tid + 256];
    __syncthreads();

    int wid = tid >> 5, lane = tid & 31;
    for (int j = wid; j < Vq; j += 8) {
        float acc = 0.f;
        for (int k = lane; k < Hq; k += 32)
            acc = fmaf(hs[k], Wout[(size_t)j*Hq + k], acc);
        #pragma unroll
        for (int o = 16; o > 0; o >>= 1) acc += __shfl_down_sync(0xffffffffu, acc, o);
        if (lane == 0) lg[j] = acc + bout[j];
    }
    __syncthreads();
    if (tid < Vq) vecout[((size_t)b*LTq + t)*Vq + tid] = lg[tid];
    if (tid == 0) {
        int best = 0; float bv = lg[0];
        for (int j = 1; j < Vq; j++) { if (lg[j] > bv) { bv = lg[j]; best = j; } }
        g_vecin[b] = best;
    }
}

// ---------------- final hidden copy ----------------
__global__ void k_hfinal(float* __restrict__ out) {
    int idx = blockIdx.x * blockDim.x + threadIdx.x;
    if (idx < NLq*Bq*Hq) out[idx] = (&g_hd[0][0][0])[idx];
}

// ---------------- launch ----------------
extern "C" void kernel_launch(void* const* d_in, const int* in_sizes, int n_in,
                              void* d_out, int out_size) {
    const float* x        = (const float*)d_in[0];
    // d_in[1] = target (unused)
    const float* emb      = (const float*)d_in[2];
    const float* W_enc    = (const float*)d_in[3];
    const float* b_enc    = (const float*)d_in[4];
    const float* enc0_Wih = (const float*)d_in[5];
    const float* enc0_Whh = (const float*)d_in[6];
    const float* enc0_bih = (const float*)d_in[7];
    const float* enc0_bhh = (const float*)d_in[8];
    const float* enc1_Wih = (const float*)d_in[9];
    const float* enc1_Whh = (const float*)d_in[10];
    const float* enc1_bih = (const float*)d_in[11];
    const float* enc1_bhh = (const float*)d_in[12];
    const float* W_bi     = (const float*)d_in[13];
    const float* b_bi     = (const float*)d_in[14];
    const float* dec_Wih  = (const float*)d_in[15];
    const float* dec_Whh  = (const float*)d_in[16];
    const float* dec_bih  = (const float*)d_in[17];
    const float* dec_bhh  = (const float*)d_in[18];
    const float* W_att    = (const float*)d_in[19];
    const float* b_att    = (const float*)d_in[20];
    const float* W_out    = (const float*)d_in[21];
    const float* b_out    = (const float*)d_in[22];

    float* out_vec  = (float*)d_out;                       // [B, LT, V]
    float* out_h    = out_vec + (size_t)Bq*LTq*Vq;         // [NL, B, H]
    float* out_attn = out_h + (size_t)NLq*Bq*Hq;           // [B, LC, LT]

    // encoder input projection
    k_proj<<<(LCq*Bq*Hq + 255)/256, 256>>>(x, W_enc, b_enc);

    // layer 0: precompute gi, then 256 recurrent steps (both dirs per launch)
    k_gemm_gi0<<<dim3(H3q/64, (LCq*Bq)/128, 2), 256>>>(enc0_Wih, enc0_bih);
    for (int s = 0; s < LCq; s++)
        k_gru_enc<<<dim3(Hq/16, Bq/64, 2), 256>>>(enc0_Whh, enc0_bhh, 0, s);

    // layer 1
    k_gemm_gi1<<<dim3(H3q/64, (LCq*Bq)/128, 2), 256>>>(enc1_Wih, enc1_bih);
    for (int s = 0; s < LCq; s++)
        k_gru_enc<<<dim3(Hq/16, Bq/64, 2), 256>>>(enc1_Whh, enc1_bhh, 1, s);

    // bi_fc + norms
    k_gemm_bi<<<dim3(Hq/64, (LCq*Bq)/128, 1), 256>>>(W_bi, b_bi);
    k_vn<<<LCq*Bq, 128>>>();

    // decoder
    k_initdec<<<(Bq*Hq + 255)/256, 256>>>();
    for (int t = 0; t < LTq; t++) {
        int p = t & 1, w = 1 - p;
        k_gru_dec<<<dim3(Hq/16, Bq/32), 256>>>(dec_Wih, dec_Whh, dec_bih, dec_bhh,
                                               emb, 0, p);
        k_gru_dec<<<dim3(Hq/16, Bq/32), 256>>>(dec_Wih + (size_t)H3q*Hq,
                                               dec_Whh + (size_t)H3q*Hq,
                                               dec_bih + H3q, dec_bhh + H3q,
                                               emb, 1, p);
        k_attn<<<Bq, 256>>>(t, w, out_attn);
        k_attfc<<<dim3(Hq/16, Bq/32), 256>>>(W_att, b_att, w);
        k_out<<<Bq, 256>>>(W_out, b_out, t, out_vec);
    }
    k_hfinal<<<(NLq*Bq*Hq + 255)/256, 256>>>(out_h);
    (void)in_sizes; (void)n_in; (void)out_size;
}

// round 2
// speedup vs baseline: 1.3351x; 1.3351x over previous
#include <cuda_runtime.h>
#include <math.h>
#include <stdint.h>

#define Bq 128
#define Hq 512
#define LCq 256
#define LTq 64
#define Vq 27
#define NLq 2
#define H3q (3*Hq)
#define KT 32

// ---------------- scratch (device globals: allocation-free rule) ----------------
__device__ float g_xr[LCq*Bq*Hq];                    // [l][b][h] encoder input proj
__device__ float g_gi[(size_t)2*LCq*Bq*H3q];         // [dir][t][b][3H] precomputed input gates
__device__ float g_y0[(size_t)LCq*Bq*2*Hq];          // [t][b][2H] layer0 outputs (fwd|bwd)
__device__ float g_y1[(size_t)LCq*Bq*2*Hq];          // [t][b][2H] layer1 outputs
__device__ float g_v [(size_t)LCq*Bq*Hq];            // [l][b][h] bi_fc output
__device__ float g_vn[LCq*Bq];                       // [l][b] norms
__device__ float g_hd[2][NLq][Bq*Hq];                // decoder hidden, double buffered
__device__ float g_a [Bq*Hq];                        // attention context
__device__ float g_hid[Bq*Hq];                       // attention_fc output
__device__ int   g_vecin[Bq];                        // greedy feedback token
__device__ unsigned g_barc[2];                       // grid-barrier counters (per layer)

// ---------------- encoder input projection ----------------
__global__ void k_proj(const float* __restrict__ x, const float* __restrict__ W_enc,
                       const float* __restrict__ b_enc) {
    int idx = blockIdx.x * blockDim.x + threadIdx.x;
    if (idx >= LCq*Bq*Hq) return;
    int h = idx % Hq; int bl = idx / Hq; int b = bl % Bq; int l = bl / Bq;
    float v = x[(size_t)b*2*LCq + l] * W_enc[h*2]
            + x[(size_t)b*2*LCq + LCq + l] * W_enc[h*2+1] + b_enc[h];
    g_xr[idx] = v;
}

__global__ void k_zerobar() { g_barc[0] = 0; g_barc[1] = 0; }

// ---------------- batched SGEMM: C[M,N] = A[M,K] @ W[N,K]^T + bias ----------------
__device__ __forceinline__ void sgemm_body(const float* __restrict__ A,
                                           const float* __restrict__ W,
                                           const float* __restrict__ bias,
                                           float* __restrict__ C, int N, int K) {
    __shared__ float As[16][129];
    __shared__ float Ws[16][65];
    int tid = threadIdx.x;
    int tx = tid & 15, ty = tid >> 4;
    int row0 = blockIdx.y * 128, col0 = blockIdx.x * 64;
    float acc[8][4];
    #pragma unroll
    for (int i = 0; i < 8; i++)
        #pragma unroll
        for (int j = 0; j < 4; j++) acc[i][j] = 0.f;

    for (int k0 = 0; k0 < K; k0 += 16) {
        #pragma unroll
        for (int j = 0; j < 2; j++) {
            int lin = tid + j*256;
            int r = lin >> 2, kk = (lin & 3) << 2;
            float4 a4 = *(const float4*)(A + (size_t)(row0 + r)*K + k0 + kk);
            As[kk][r] = a4.x; As[kk+1][r] = a4.y; As[kk+2][r] = a4.z; As[kk+3][r] = a4.w;
        }
        {
            int n = tid >> 2, kk = (tid & 3) << 2;
            float4 w4 = *(const float4*)(W + (size_t)(col0 + n)*K + k0 + kk);
            Ws[kk][n] = w4.x; Ws[kk+1][n] = w4.y; Ws[kk+2][n] = w4.z; Ws[kk+3][n] = w4.w;
        }
        __syncthreads();
        #pragma unroll
        for (int k = 0; k < 16; k++) {
            float ar[8], wr[4];
            #pragma unroll
            for (int i = 0; i < 8; i++) ar[i] = As[k][ty*8 + i];
            #pragma unroll
            for (int j = 0; j < 4; j++) wr[j] = Ws[k][tx*4 + j];
            #pragma unroll
            for (int i = 0; i < 8; i++)
                #pragma unroll
                for (int j = 0; j < 4; j++)
                    acc[i][j] = fmaf(ar[i], wr[j], acc[i][j]);
        }
        __syncthreads();
    }
    #pragma unroll
    for (int i = 0; i < 8; i++) {
        int r = row0 + ty*8 + i;
        #pragma unroll
        for (int j = 0; j < 4; j++) {
            int c = col0 + tx*4 + j;
            C[(size_t)r*N + c] = acc[i][j] + bias[c];
        }
    }
}

__global__ void k_gemm_gi0(const float* __restrict__ Wih, const float* __restrict__ bih) {
    int dir = blockIdx.z;
    sgemm_body(g_xr, Wih + (size_t)dir*H3q*Hq, bih + dir*H3q,
               g_gi + (size_t)dir*LCq*Bq*H3q, H3q, Hq);
}
__global__ void k_gemm_gi1(const float* __restrict__ Wih, const float* __restrict__ bih) {
    int dir = blockIdx.z;
    sgemm_body(g_y0, Wih + (size_t)dir*H3q*2*Hq, bih + dir*H3q,
               g_gi + (size_t)dir*LCq*Bq*H3q, H3q, 2*Hq);
}
__global__ void k_gemm_bi(const float* __restrict__ Wb, const float* __restrict__ bb) {
    sgemm_body(g_y1, Wb, bb, g_v, Hq, 2*Hq);
}

// ---------------- persistent encoder GRU layer ----------------
// 128 blocks (single wave), 256 threads. Block = (dir, batchTile of 64, colTile of 16).
// Whh slice (3 gates x 16 cols x 512 k) cached in SMEM once. 256 steps internally
// separated by software grid barriers.
// SMEM: Wsm[48][516] (99072B) + Hs[2][64][36] (18432B) = 117504B dynamic.
#define WROW 516
#define HROW 36
__global__ void __launch_bounds__(256, 1) k_enc_pers(
        const float* __restrict__ Whh2, const float* __restrict__ bhh2,
        int layer) {
    extern __shared__ float sm[];
    float* Wsm = sm;                      // [48][WROW]
    float* Hs  = sm + 48*WROW;            // [2][64][HROW]

    float* Y = layer ? g_y1 : g_y0;
    int bid = blockIdx.x;
    int dirv = bid >> 6;
    int rem  = bid & 63;
    int col0 = (rem & 31) * 16;
    int row0 = (rem >> 5) * 64;

    int tid = threadIdx.x;
    int tx = tid & 15, ty = tid >> 4;

    const float* Whh = Whh2 + (size_t)dirv*H3q*Hq;
    const float* bhh = bhh2 + dirv*H3q;

    // cache Whh slice: Wsm[g*16+c][k] = Whh[(g*512 + col0 + c)*512 + k]
    for (int idx = tid; idx < 48*128; idx += 256) {
        int row = idx >> 7;          // 0..47
        int kq  = idx & 127;         // float4 index
        int g = row >> 4, c = row & 15;
        float4 w = __ldg((const float4*)(Whh + (size_t)(g*Hq + col0 + c)*Hq) + kq);
        *(float4*)(Wsm + row*WROW + kq*4) = w;
    }
    int c = col0 + tx;
    float br = __ldg(bhh + c), bz = __ldg(bhh + Hq + c), bn = __ldg(bhh + 2*Hq + c);
    __syncthreads();

    const float* gi_base = g_gi + (size_t)dirv*LCq*Bq*H3q;

    for (int s = 0; s < LCq; s++) {
        int t = dirv ? (LCq-1-s) : s;
        int tprev = dirv ? (t+1) : (t-1);

        float racc[4] = {0,0,0,0}, zacc[4] = {0,0,0,0}, nacc[4] = {0,0,0,0};
        float hp[4] = {0,0,0,0};

        if (s > 0) {
            const float* Hp = Y + ((size_t)tprev*Bq)*2*Hq + (size_t)dirv*Hq;
            // load tile 0
            #pragma unroll
            for (int j = 0; j < 2; j++) {
                int lin = tid + j*256;
                int r = lin >> 3, kq = lin & 7;
                float4 h4 = __ldcg((const float4*)(Hp + (size_t)(row0 + r)*2*Hq) + kq);
                *(float4*)(Hs + r*HROW + kq*4) = h4;
            }
            __syncthreads();

            int buf = 0;
            for (int i = 0; i < 16; i++) {
                int k0 = i*KT;
                float4 p0, p1;
                if (i < 15) {
                    int lin0 = tid, lin1 = tid + 256;
                    p0 = __ldcg((const float4*)(Hp + (size_t)(row0 + (lin0 >> 3))*2*Hq) + (k0/4 + 8) + (lin0 & 7));
                    p1 = __ldcg((const float4*)(Hp + (size_t)(row0 + (lin1 >> 3))*2*Hq) + (k0/4 + 8) + (lin1 & 7));
                }
                const float* HsB = Hs + buf*64*HROW;
                const float4* Wr = (const float4*)(Wsm + (0*16 + tx)*WROW) + (k0 >> 2);
                const float4* Wz = (const float4*)(Wsm + (1*16 + tx)*WROW) + (k0 >> 2);
                const float4* Wn = (const float4*)(Wsm + (2*16 + tx)*WROW) + (k0 >> 2);
                #pragma unroll
                for (int kk4 = 0; kk4 < 8; kk4++) {
                    float4 wr = Wr[kk4], wz = Wz[kk4], wn = Wn[kk4];
                    #pragma unroll
                    for (int b4 = 0; b4 < 4; b4++) {
                        float4 hv = *(const float4*)(HsB + (ty*4 + b4)*HROW + kk4*4);
                        racc[b4] = fmaf(hv.x, wr.x, racc[b4]);
                        racc[b4] = fmaf(hv.y, wr.y, racc[b4]);
                        racc[b4] = fmaf(hv.z, wr.z, racc[b4]);
                        racc[b4] = fmaf(hv.w, wr.w, racc[b4]);
                        zacc[b4] = fmaf(hv.x, wz.x, zacc[b4]);
                        zacc[b4] = fmaf(hv.y, wz.y, zacc[b4]);
                        zacc[b4] = fmaf(hv.z, wz.z, zacc[b4]);
                        zacc[b4] = fmaf(hv.w, wz.w, zacc[b4]);
                        nacc[b4] = fmaf(hv.x, wn.x, nacc[b4]);
                        nacc[b4] = fmaf(hv.y, wn.y, nacc[b4]);
                        nacc[b4] = fmaf(hv.z, wn.z, nacc[b4]);
                        nacc[b4] = fmaf(hv.w, wn.w, nacc[b4]);
                    }
                }
                if (i < 15) {
                    float* HsN = Hs + (buf^1)*64*HROW;
                    int lin0 = tid, lin1 = tid + 256;
                    *(float4*)(HsN + (lin0 >> 3)*HROW + (lin0 & 7)*4) = p0;
                    *(float4*)(HsN + (lin1 >> 3)*HROW + (lin1 & 7)*4) = p1;
                    __syncthreads();
                    buf ^= 1;
                }
            }
            // previous hidden for the output columns
            #pragma unroll
            for (int b4 = 0; b4 < 4; b4++) {
                int b = row0 + ty*4 + b4;
                hp[b4] = __ldcg(Y + ((size_t)tprev*Bq + b)*2*Hq + dirv*Hq + c);
            }
        }

        // pointwise tail
        const float* gi_t = gi_base + (size_t)t*Bq*H3q;
        #pragma unroll
        for (int b4 = 0; b4 < 4; b4++) {
            int b = row0 + ty*4 + b4;
            const float* gib = gi_t + (size_t)b*H3q;
            float gr = __ldg(gib + c), gz = __ldg(gib + Hq + c), gn = __ldg(gib + 2*Hq + c);
            float r = 1.f/(1.f + expf(-(gr + racc[b4] + br)));
            float z = 1.f/(1.f + expf(-(gz + zacc[b4] + bz)));
            float n = tanhf(gn + r*(nacc[b4] + bn));
            Y[((size_t)t*Bq + b)*2*Hq + dirv*Hq + c] = (1.f - z)*n + z*hp[b4];
        }

        // grid barrier
        __threadfence();
        __syncthreads();
        if (tid == 0) {
            atomicAdd(&g_barc[layer], 1u);
            unsigned target = 128u * (unsigned)(s + 1);
            while (*(volatile unsigned*)&g_barc[layer] < target) { }
        }
        __syncthreads();
    }
}

// ---------------- decoder GRU step (one layer per launch) ----------------
__global__ void k_gru_dec(const float* __restrict__ Wih, const float* __restrict__ Whh,
                          const float* __restrict__ bih, const float* __restrict__ bhh,
                          const float* __restrict__ emb, int layer, int p) {
    const float* hprev = g_hd[p][layer];
    const float* xin   = (layer == 0) ? (const float*)nullptr : g_hd[1-p][0];
    float* hout        = g_hd[1-p][layer];

    int tid = threadIdx.x;
    int tx = tid & 15, ty = tid >> 4;
    int col0 = blockIdx.x * 16, row0 = blockIdx.y * 32;

    __shared__ float Xs[KT][33];
    __shared__ float Hs[KT][33];
    __shared__ float Wi[3][KT][17];
    __shared__ float Wh[3][KT][17];
    __shared__ int vs[32];

    if (layer == 0 && tid < 32) vs[tid] = g_vecin[row0 + tid];
    __syncthreads();

    float rs[2] = {0,0}, zs[2] = {0,0}, nis[2] = {0,0}, nhs[2] = {0,0};

    for (int k0 = 0; k0 < Hq; k0 += KT) {
        {
            int r = tid >> 3, kk = (tid & 7) << 2;
            const float* xb = (layer == 0) ? (emb + (size_t)vs[r]*Hq)
                                           : (xin + (size_t)(row0 + r)*Hq);
            float4 x4 = *(const float4*)(xb + k0 + kk);
            Xs[kk][r]=x4.x; Xs[kk+1][r]=x4.y; Xs[kk+2][r]=x4.z; Xs[kk+3][r]=x4.w;
            float4 h4 = *(const float4*)(hprev + (size_t)(row0 + r)*Hq + k0 + kk);
            Hs[kk][r]=h4.x; Hs[kk+1][r]=h4.y; Hs[kk+2][r]=h4.z; Hs[kk+3][r]=h4.w;
        }
        #pragma unroll
        for (int j = 0; j < 6; j++) {
            int lin = tid + j*256;
            int rr = lin >> 5, k = lin & 31;
            int g = rr >> 4, c = rr & 15;
            Wi[g][k][c] = Wih[(size_t)(g*Hq + col0 + c)*Hq + k0 + k];
            Wh[g][k][c] = Whh[(size_t)(g*Hq + col0 + c)*Hq + k0 + k];
        }
        __syncthreads();
        #pragma unroll
        for (int k = 0; k < KT; k++) {
            float wir = Wi[0][k][tx], wiz = Wi[1][k][tx], win = Wi[2][k][tx];
            float whr = Wh[0][k][tx], whz = Wh[1][k][tx], whn = Wh[2][k][tx];
            #pragma unroll
            for (int i = 0; i < 2; i++) {
                float xv = Xs[k][ty + 16*i], hv = Hs[k][ty + 16*i];
                rs[i]  = fmaf(xv, wir, rs[i]);  rs[i]  = fmaf(hv, whr, rs[i]);
                zs[i]  = fmaf(xv, wiz, zs[i]);  zs[i]  = fmaf(hv, whz, zs[i]);
                nis[i] = fmaf(xv, win, nis[i]);
                nhs[i] = fmaf(hv, whn, nhs[i]);
            }
        }
        __syncthreads();
    }
    int c = col0 + tx;
    float bir = bih[c], biz = bih[Hq+c], bin = bih[2*Hq+c];
    float bhr = bhh[c], bhz = bhh[Hq+c], bhn = bhh[2*Hq+c];
    #pragma unroll
    for (int i = 0; i < 2; i++) {
        int b = row0 + ty + 16*i;
        float hp = hprev[(size_t)b*Hq + c];
        float r = 1.f/(1.f + expf(-(rs[i] + bir + bhr)));
        float z = 1.f/(1.f + expf(-(zs[i] + biz + bhz)));
        float n = tanhf(nis[i] + bin + r*(nhs[i] + bhn));
        hout[(size_t)b*Hq + c] = (1.f - z)*n + z*hp;
    }
}

// ---------------- v row norms ----------------
__global__ void k_vn() {
    int row = blockIdx.x;
    int tid = threadIdx.x;
    const float* vr = g_v + (size_t)row*Hq;
    float s = 0.f;
    for (int k = tid; k < Hq; k += 128) { float x = vr[k]; s = fmaf(x, x, s); }
    __shared__ float red[128];
    red[tid] = s; __syncthreads();
    for (int o = 64; o > 0; o >>= 1) { if (tid < o) red[tid] += red[tid + o]; __syncthreads(); }
    if (tid == 0) g_vn[row] = fmaxf(sqrtf(red[0]), 1e-8f);
}

// ---------------- decoder init ----------------
__global__ void k_initdec() {
    int idx = blockIdx.x * blockDim.x + threadIdx.x;
    if (idx < Bq) g_vecin[idx] = 0;
    if (idx < Bq*Hq) {
        int b = idx / Hq, h = idx % Hq;
        g_hd[0][0][idx] = g_y0[((size_t)(LCq-1)*Bq + b)*2*Hq + h];        // hf0
        g_hd[0][1][idx] = g_y0[((size_t)b)*2*Hq + Hq + h];                // hb0
    }
}

// ---------------- attention: cosine sim + softmax + context ----------------
__global__ void k_attn(int t, int w, float* __restrict__ attn_out) {
    int b = blockIdx.x;
    int tid = threadIdx.x;                // 256 == LC
    __shared__ __align__(16) float qs[Hq];
    __shared__ float red[256];
    __shared__ float wsm[LCq];

    const float* q = g_hd[w][1] + (size_t)b*Hq;
    qs[tid] = q[tid]; qs[tid + 256] = q[tid + 256];
    __syncthreads();

    float ss = qs[tid]*qs[tid] + qs[tid+256]*qs[tid+256];
    red[tid] = ss; __syncthreads();
    for (int o = 128; o > 0; o >>= 1) { if (tid < o) red[tid] += red[tid + o]; __syncthreads(); }
    float qn = fmaxf(sqrtf(red[0]), 1e-8f);
    __syncthreads();

    const float4* v4 = (const float4*)(g_v + ((size_t)tid*Bq + b)*Hq);
    const float4* q4 = (const float4*)qs;
    float dot = 0.f;
    #pragma unroll 4
    for (int k = 0; k < Hq/4; k++) {
        float4 a = v4[k], c = q4[k];
        dot = fmaf(a.x, c.x, dot); dot = fmaf(a.y, c.y, dot);
        dot = fmaf(a.z, c.z, dot); dot = fmaf(a.w, c.w, dot);
    }
    float sim = dot / (g_vn[(size_t)tid*Bq + b] * qn);

    red[tid] = sim; __syncthreads();
    for (int o = 128; o > 0; o >>= 1) { if (tid < o) red[tid] = fmaxf(red[tid], red[tid+o]); __syncthreads(); }
    float mx = red[0]; __syncthreads();
    float e = expf(sim - mx);
    red[tid] = e; __syncthreads();
    for (int o = 128; o > 0; o >>= 1) { if (tid < o) red[tid] += red[tid + o]; __syncthreads(); }
    float wv = e / red[0];
    wsm[tid] = wv;
    attn_out[((size_t)b*LCq + tid)*LTq + t] = wv;
    __syncthreads();

    for (int h = tid; h < Hq; h += 256) {
        float acc = 0.f;
        for (int l = 0; l < LCq; l++)
            acc = fmaf(wsm[l], g_v[((size_t)l*Bq + b)*Hq + h], acc);
        g_a[(size_t)b*Hq + h] = acc;
    }
}

// ---------------- attention_fc: hid = [q, a] @ W_att^T + b_att ----------------
__global__ void k_attfc(const float* __restrict__ Watt, const float* __restrict__ batt, int w) {
    const float* X1 = g_hd[w][1];
    const float* X2 = g_a;
    int tid = threadIdx.x;
    int tx = tid & 15, ty = tid >> 4;
    int col0 = blockIdx.x * 16, row0 = blockIdx.y * 32;

    __shared__ float Xs[KT][33];
    __shared__ float As2[KT][33];
    __shared__ float Wq[KT][17];
    __shared__ float Wa[KT][17];

    float acc[2] = {0,0};
    for (int k0 = 0; k0 < Hq; k0 += KT) {
        {
            int r = tid >> 3, kk = (tid & 7) << 2;
            float4 x4 = *(const float4*)(X1 + (size_t)(row0 + r)*Hq + k0 + kk);
            Xs[kk][r]=x4.x; Xs[kk+1][r]=x4.y; Xs[kk+2][r]=x4.z; Xs[kk+3][r]=x4.w;
            float4 a4 = *(const float4*)(X2 + (size_t)(row0 + r)*Hq + k0 + kk);
            As2[kk][r]=a4.x; As2[kk+1][r]=a4.y; As2[kk+2][r]=a4.z; As2[kk+3][r]=a4.w;
        }
        #pragma unroll
        for (int j = 0; j < 2; j++) {
            int lin = tid + j*256;
            int c = lin >> 5, k = lin & 31;
            Wq[k][c] = Watt[(size_t)(col0 + c)*2*Hq + k0 + k];
            Wa[k][c] = Watt[(size_t)(col0 + c)*2*Hq + Hq + k0 + k];
        }
        __syncthreads();
        #pragma unroll
        for (int k = 0; k < KT; k++) {
            float wq = Wq[k][tx], wa = Wa[k][tx];
            #pragma unroll
            for (int i = 0; i < 2; i++) {
                acc[i] = fmaf(Xs[k][ty + 16*i], wq, acc[i]);
                acc[i] = fmaf(As2[k][ty + 16*i], wa, acc[i]);
            }
        }
        __syncthreads();
    }
    int c = col0 + tx;
    #pragma unroll
    for (int i = 0; i < 2; i++) {
        int b = row0 + ty + 16*i;
        g_hid[(size_t)b*Hq + c] = acc[i] + batt[c];
    }
}

// ---------------- output logits + argmax feedback ----------------
__global__ void k_out(const float* __restrict__ Wout, const float* __restrict__ bout,
                      int t, float* __restrict__ vecout) {
    int b = blockIdx.x;
    int tid = threadIdx.x;
    __shared__ float hs[Hq];
    __shared__ float lg[32];
    hs[tid] = g_hid[(size_t)b*Hq + tid];
    hs[tid + 256] = g_hid[(size_t)b*Hq + tid + 256];
    __syncthreads();

    int wid = tid >> 5, lane = tid & 31;
    for (int j = wid; j < Vq; j += 8) {
        float acc = 0.f;
        for (int k = lane; k < Hq; k += 32)
            acc = fmaf(hs[k], Wout[(size_t)j*Hq + k], acc);
        #pragma unroll
        for (int o = 16; o > 0; o >>= 1) acc += __shfl_down_sync(0xffffffffu, acc, o);
        if (lane == 0) lg[j] = acc + bout[j];
    }
    __syncthreads();
    if (tid < Vq) vecout[((size_t)b*LTq + t)*Vq + tid] = lg[tid];
    if (tid == 0) {
        int best = 0; float bv = lg[0];
        for (int j = 1; j < Vq; j++) { if (lg[j] > bv) { bv = lg[j]; best = j; } }
        g_vecin[b] = best;
    }
}

// ---------------- final hidden copy ----------------
__global__ void k_hfinal(float* __restrict__ out) {
    int idx = blockIdx.x * blockDim.x + threadIdx.x;
    if (idx < NLq*Bq*Hq) out[idx] = (&g_hd[0][0][0])[idx];
}

// ---------------- launch ----------------
extern "C" void kernel_launch(void* const* d_in, const int* in_sizes, int n_in,
                              void* d_out, int out_size) {
    const float* x        = (const float*)d_in[0];
    const float* emb      = (const float*)d_in[2];
    const float* W_enc    = (const float*)d_in[3];
    const float* b_enc    = (const float*)d_in[4];
    const float* enc0_Wih = (const float*)d_in[5];
    const float* enc0_Whh = (const float*)d_in[6];
    const float* enc0_bih = (const float*)d_in[7];
    const float* enc0_bhh = (const float*)d_in[8];
    const float* enc1_Wih = (const float*)d_in[9];
    const float* enc1_Whh = (const float*)d_in[10];
    const float* enc1_bih = (const float*)d_in[11];
    const float* enc1_bhh = (const float*)d_in[12];
    const float* W_bi     = (const float*)d_in[13];
    const float* b_bi     = (const float*)d_in[14];
    const float* dec_Wih  = (const float*)d_in[15];
    const float* dec_Whh  = (const float*)d_in[16];
    const float* dec_bih  = (const float*)d_in[17];
    const float* dec_bhh  = (const float*)d_in[18];
    const float* W_att    = (const float*)d_in[19];
    const float* b_att    = (const float*)d_in[20];
    const float* W_out    = (const float*)d_in[21];
    const float* b_out    = (const float*)d_in[22];

    float* out_vec  = (float*)d_out;                       // [B, LT, V]
    float* out_h    = out_vec + (size_t)Bq*LTq*Vq;         // [NL, B, H]
    float* out_attn = out_h + (size_t)NLq*Bq*Hq;           // [B, LC, LT]

    const int PERS_SMEM = (48*WROW + 2*64*HROW) * 4;       // 117504 B
    cudaFuncSetAttribute(k_enc_pers, cudaFuncAttributeMaxDynamicSharedMemorySize, PERS_SMEM);

    // encoder input projection + barrier reset
    k_proj<<<(LCq*Bq*Hq + 255)/256, 256>>>(x, W_enc, b_enc);
    k_zerobar<<<1, 1>>>();

    // layer 0: precompute gi, then persistent recurrence (256 steps internal)
    k_gemm_gi0<<<dim3(H3q/64, (LCq*Bq)/128, 2), 256>>>(enc0_Wih, enc0_bih);
    k_enc_pers<<<128, 256, PERS_SMEM>>>(enc0_Whh, enc0_bhh, 0);

    // layer 1
    k_gemm_gi1<<<dim3(H3q/64, (LCq*Bq)/128, 2), 256>>>(enc1_Wih, enc1_bih);
    k_enc_pers<<<128, 256, PERS_SMEM>>>(enc1_Whh, enc1_bhh, 1);

    // bi_fc + norms
    k_gemm_bi<<<dim3(Hq/64, (LCq*Bq)/128, 1), 256>>>(W_bi, b_bi);
    k_vn<<<LCq*Bq, 128>>>();

    // decoder
    k_initdec<<<(Bq*Hq + 255)/256, 256>>>();
    for (int t = 0; t < LTq; t++) {
        int p = t & 1, w = 1 - p;
        k_gru_dec<<<dim3(Hq/16, Bq/32), 256>>>(dec_Wih, dec_Whh, dec_bih, dec_bhh,
                                               emb, 0, p);
        k_gru_dec<<<dim3(Hq/16, Bq/32), 256>>>(dec_Wih + (size_t)H3q*Hq,
                                               dec_Whh + (size_t)H3q*Hq,
                                               dec_bih + H3q, dec_bhh + H3q,
                                               emb, 1, p);
        k_attn<<<Bq, 256>>>(t, w, out_attn);
        k_attfc<<<dim3(Hq/16, Bq/32), 256>>>(W_att, b_att, w);
        k_out<<<Bq, 256>>>(W_out, b_out, t, out_vec);
    }
    k_hfinal<<<(NLq*Bq*Hq + 255)/256, 256>>>(out_h);
    (void)in_sizes; (void)n_in; (void)out_size;
}

// round 4
// speedup vs baseline: 1.6875x; 1.2640x over previous
#include <cuda_runtime.h>
#include <cuda_bf16.h>
#include <math.h>
#include <stdint.h>

#define Bq 128
#define Hq 512
#define LCq 256
#define LTq 64
#define Vq 27
#define NLq 2
#define H3q (3*Hq)
#define KT 32
#define Mq (LCq*Bq)

// ---------------- scratch (device globals: allocation-free rule) ----------------
__device__ float g_xr[(size_t)Mq*Hq];
__device__ float g_gi[(size_t)2*Mq*H3q];
__device__ float g_y0[(size_t)Mq*2*Hq];
__device__ float g_y1[(size_t)Mq*2*Hq];
__device__ float g_v [(size_t)Mq*Hq];
__device__ float g_vn[Mq];
__device__ float g_hd[2][NLq][Bq*Hq];
__device__ float g_a [Bq*Hq];
__device__ float g_hid[Bq*Hq];
__device__ int   g_vecin[Bq];
__device__ unsigned g_barc[2];

// bf16 hi/lo decompositions
__device__ __nv_bfloat16 g_xr_h[(size_t)Mq*Hq],   g_xr_l[(size_t)Mq*Hq];
__device__ __nv_bfloat16 g_y0_h[(size_t)Mq*2*Hq], g_y0_l[(size_t)Mq*2*Hq];
__device__ __nv_bfloat16 g_y1_h[(size_t)Mq*2*Hq], g_y1_l[(size_t)Mq*2*Hq];
__device__ __nv_bfloat16 g_w0_h[2*H3q*Hq],   g_w0_l[2*H3q*Hq];
__device__ __nv_bfloat16 g_w1_h[2*H3q*2*Hq], g_w1_l[2*H3q*2*Hq];
__device__ __nv_bfloat16 g_wb_h[Hq*2*Hq],    g_wb_l[Hq*2*Hq];

// ---------------- warp-mma primitives (sm_80+ PTX, works on compute_103) -------
__device__ __forceinline__ uint32_t smem_u32(const void* p) {
    uint32_t a;
    asm("{ .reg .u64 t; cvta.to.shared.u64 t, %1; cvt.u32.u64 %0, t; }" : "=r"(a) : "l"(p));
    return a;
}
__device__ __forceinline__ void ldsm4(uint32_t& r0, uint32_t& r1, uint32_t& r2, uint32_t& r3,
                                      uint32_t a) {
    asm volatile("ldmatrix.sync.aligned.m8n8.x4.shared.b16 {%0,%1,%2,%3}, [%4];"
        : "=r"(r0), "=r"(r1), "=r"(r2), "=r"(r3) : "r"(a));
}
__device__ __forceinline__ void mma_bf16(float* c, const uint32_t* a, const uint32_t* b) {
    asm volatile("mma.sync.aligned.m16n8k16.row.col.f32.bf16.bf16.f32 "
        "{%0,%1,%2,%3}, {%4,%5,%6,%7}, {%8,%9}, {%0,%1,%2,%3};"
        : "+f"(c[0]), "+f"(c[1]), "+f"(c[2]), "+f"(c[3])
        : "r"(a[0]), "r"(a[1]), "r"(a[2]), "r"(a[3]), "r"(b[0]), "r"(b[1]));
}

// ---------------- fp32 -> bf16 hi/lo split ----------------
__global__ void k_cvt(const float* __restrict__ s, __nv_bfloat16* __restrict__ hi,
                      __nv_bfloat16* __restrict__ lo, int n4) {
    int i = blockIdx.x * blockDim.x + threadIdx.x;
    if (i >= n4) return;
    float4 v = *(const float4*)(s + (size_t)i*4);
    __nv_bfloat16 h0 = __float2bfloat16(v.x), h1 = __float2bfloat16(v.y);
    __nv_bfloat16 h2 = __float2bfloat16(v.z), h3 = __float2bfloat16(v.w);
    __nv_bfloat162 hA, hB, lA, lB;
    hA.x = h0; hA.y = h1; hB.x = h2; hB.y = h3;
    lA.x = __float2bfloat16(v.x - __bfloat162float(h0));
    lA.y = __float2bfloat16(v.y - __bfloat162float(h1));
    lB.x = __float2bfloat16(v.z - __bfloat162float(h2));
    lB.y = __float2bfloat16(v.w - __bfloat162float(h3));
    *(__nv_bfloat162*)(hi + (size_t)i*4)     = hA;
    *(__nv_bfloat162*)(hi + (size_t)i*4 + 2) = hB;
    *(__nv_bfloat162*)(lo + (size_t)i*4)     = lA;
    *(__nv_bfloat162*)(lo + (size_t)i*4 + 2) = lB;
}

// ---------------- encoder input projection ----------------
__global__ void k_proj(const float* __restrict__ x, const float* __restrict__ W_enc,
                       const float* __restrict__ b_enc) {
    int idx = blockIdx.x * blockDim.x + threadIdx.x;
    if (idx >= Mq*Hq) return;
    int h = idx % Hq; int bl = idx / Hq; int b = bl % Bq; int l = bl / Bq;
    float v = x[(size_t)b*2*LCq + l] * W_enc[h*2]
            + x[(size_t)b*2*LCq + LCq + l] * W_enc[h*2+1] + b_enc[h];
    g_xr[idx] = v;
}

__global__ void k_zerobar() { g_barc[0] = 0; g_barc[1] = 0; }

// ---------------- tensor-core GEMM via warp mma: C = A @ W^T + bias ------------
// split-bf16: C = Ah*Wh + Ah*Wl + Al*Wh (fp32 register accumulate).
// CTA tile 128x64, K-tile 32, 8 warps in 4(M) x 2(N).
#define AROW 40   // padded row length in bf16 (80B) -> conflict-free ldmatrix
__global__ void __launch_bounds__(256) k_gemm_mma(
        const __nv_bfloat16* __restrict__ Ah, const __nv_bfloat16* __restrict__ Al,
        const __nv_bfloat16* __restrict__ Wh, const __nv_bfloat16* __restrict__ Wl,
        const float* __restrict__ bias, float* __restrict__ C,
        int K, int Nld, size_t wStrideZ, int bStrideZ, size_t cStrideZ) {
    __shared__ __nv_bfloat16 sAh[128*AROW], sAl[128*AROW];
    __shared__ __nv_bfloat16 sWh[64*AROW],  sWl[64*AROW];

    int tid = threadIdx.x, wid = tid >> 5, lane = tid & 31;
    int z = blockIdx.z;
    const __nv_bfloat16* Whz = Wh + (size_t)z*wStrideZ;
    const __nv_bfloat16* Wlz = Wl + (size_t)z*wStrideZ;
    const float* bias_z = bias + (size_t)z*bStrideZ;
    float* C_z = C + (size_t)z*cStrideZ;
    int col0 = blockIdx.x * 64, row0 = blockIdx.y * 128;
    int wm = (wid & 3) * 32, wn = (wid >> 2) * 32;

    float acc[2][4][4];
    #pragma unroll
    for (int i = 0; i < 2; i++)
        #pragma unroll
        for (int j = 0; j < 4; j++)
            #pragma unroll
            for (int k = 0; k < 4; k++) acc[i][j][k] = 0.f;

    // precompute ldmatrix lane addresses (byte offsets into padded tiles)
    uint32_t aBase = smem_u32(sAh), alBase = smem_u32(sAl);
    uint32_t wBase = smem_u32(sWh), wlBase = smem_u32(sWl);
    int aRow = wm + (lane & 15);             // + mi*16
    int aCol = (lane >> 4) * 8;              // + ks*16
    int g = lane >> 3;
    int bRow = wn + (lane & 7) + ((g >> 1) & 1) * 8;   // + ng*16
    int bCol = (g & 1) * 8;                             // + ks*16

    for (int k0 = 0; k0 < K; k0 += 32) {
        // stage A: 128 rows x 32 bf16 (hi & lo)
        #pragma unroll
        for (int i = 0; i < 2; i++) {
            int u = tid + (i << 8);
            int r = u >> 2, cu = u & 3;
            size_t go = (size_t)(row0 + r)*K + k0 + cu*8;
            *(uint4*)(sAh + r*AROW + cu*8) = *(const uint4*)(Ah + go);
            *(uint4*)(sAl + r*AROW + cu*8) = *(const uint4*)(Al + go);
        }
        // stage W: 64 rows x 32 bf16 (hi & lo)
        {
            int r = tid >> 2, cu = tid & 3;
            size_t go = (size_t)(col0 + r)*K + k0 + cu*8;
            *(uint4*)(sWh + r*AROW + cu*8) = *(const uint4*)(Whz + go);
            *(uint4*)(sWl + r*AROW + cu*8) = *(const uint4*)(Wlz + go);
        }
        __syncthreads();

        #pragma unroll
        for (int ks = 0; ks < 2; ks++) {
            uint32_t ah[2][4], al[2][4], bh[2][4], bl[2][4];
            #pragma unroll
            for (int mi = 0; mi < 2; mi++) {
                uint32_t off = (uint32_t)(((aRow + mi*16)*AROW + ks*16 + aCol) * 2);
                ldsm4(ah[mi][0], ah[mi][1], ah[mi][2], ah[mi][3], aBase + off);
                ldsm4(al[mi][0], al[mi][1], al[mi][2], al[mi][3], alBase + off);
            }
            #pragma unroll
            for (int ng = 0; ng < 2; ng++) {
                uint32_t off = (uint32_t)(((bRow + ng*16)*AROW + ks*16 + bCol) * 2);
                ldsm4(bh[ng][0], bh[ng][1], bh[ng][2], bh[ng][3], wBase + off);
                ldsm4(bl[ng][0], bl[ng][1], bl[ng][2], bl[ng][3], wlBase + off);
            }
            #pragma unroll
            for (int mi = 0; mi < 2; mi++)
                #pragma unroll
                for (int ng = 0; ng < 2; ng++) {
                    #pragma unroll
                    for (int half = 0; half < 2; half++) {
                        float* c = acc[mi][ng*2 + half];
                        mma_bf16(c, ah[mi], &bh[ng][half*2]);
                        mma_bf16(c, ah[mi], &bl[ng][half*2]);
                        mma_bf16(c, al[mi], &bh[ng][half*2]);
                    }
                }
        }
        __syncthreads();
    }

    // epilogue: c0,c1 -> (row, col..col+1), c2,c3 -> (row+8, col..col+1)
    #pragma unroll
    for (int mi = 0; mi < 2; mi++) {
        int r_ = row0 + wm + mi*16 + (lane >> 2);
        #pragma unroll
        for (int ni = 0; ni < 4; ni++) {
            int c_ = col0 + wn + ni*8 + (lane & 3)*2;
            float b0 = bias_z[c_], b1 = bias_z[c_ + 1];
            float2 o0 = { acc[mi][ni][0] + b0, acc[mi][ni][1] + b1 };
            float2 o1 = { acc[mi][ni][2] + b0, acc[mi][ni][3] + b1 };
            *(float2*)(C_z + (size_t)r_*Nld + c_)       = o0;
            *(float2*)(C_z + (size_t)(r_ + 8)*Nld + c_) = o1;
        }
    }
}

// ---------------- persistent encoder GRU layer (unchanged from R2) ----------------
#define WROW 516
#define HROW 36
__global__ void __launch_bounds__(256, 1) k_enc_pers(
        const float* __restrict__ Whh2, const float* __restrict__ bhh2,
        int layer) {
    extern __shared__ float smf[];
    float* Wsm = smf;
    float* Hs  = smf + 48*WROW;

    float* Y = layer ? g_y1 : g_y0;
    int bid = blockIdx.x;
    int dirv = bid >> 6;
    int rem  = bid & 63;
    int col0 = (rem & 31) * 16;
    int row0 = (rem >> 5) * 64;

    int tid = threadIdx.x;
    int tx = tid & 15, ty = tid >> 4;

    const float* Whh = Whh2 + (size_t)dirv*H3q*Hq;
    const float* bhh = bhh2 + dirv*H3q;

    for (int idx = tid; idx < 48*128; idx += 256) {
        int row = idx >> 7;
        int kq  = idx & 127;
        int g = row >> 4, c = row & 15;
        float4 w = __ldg((const float4*)(Whh + (size_t)(g*Hq + col0 + c)*Hq) + kq);
        *(float4*)(Wsm + row*WROW + kq*4) = w;
    }
    int c = col0 + tx;
    float br = __ldg(bhh + c), bz = __ldg(bhh + Hq + c), bn = __ldg(bhh + 2*Hq + c);
    __syncthreads();

    const float* gi_base = g_gi + (size_t)dirv*LCq*Bq*H3q;

    for (int s = 0; s < LCq; s++) {
        int t = dirv ? (LCq-1-s) : s;
        int tprev = dirv ? (t+1) : (t-1);

        float racc[4] = {0,0,0,0}, zacc[4] = {0,0,0,0}, nacc[4] = {0,0,0,0};
        float hp[4] = {0,0,0,0};

        if (s > 0) {
            const float* Hp = Y + ((size_t)tprev*Bq)*2*Hq + (size_t)dirv*Hq;
            #pragma unroll
            for (int j = 0; j < 2; j++) {
                int lin = tid + j*256;
                int r = lin >> 3, kq = lin & 7;
                float4 h4 = __ldcg((const float4*)(Hp + (size_t)(row0 + r)*2*Hq) + kq);
                *(float4*)(Hs + r*HROW + kq*4) = h4;
            }
            __syncthreads();

            int buf = 0;
            for (int i = 0; i < 16; i++) {
                int k0 = i*KT;
                float4 p0, p1;
                if (i < 15) {
                    int lin0 = tid, lin1 = tid + 256;
                    p0 = __ldcg((const float4*)(Hp + (size_t)(row0 + (lin0 >> 3))*2*Hq) + (k0/4 + 8) + (lin0 & 7));
                    p1 = __ldcg((const float4*)(Hp + (size_t)(row0 + (lin1 >> 3))*2*Hq) + (k0/4 + 8) + (lin1 & 7));
                }
                const float* HsB = Hs + buf*64*HROW;
                const float4* Wr = (const float4*)(Wsm + (0*16 + tx)*WROW) + (k0 >> 2);
                const float4* Wz = (const float4*)(Wsm + (1*16 + tx)*WROW) + (k0 >> 2);
                const float4* Wn = (const float4*)(Wsm + (2*16 + tx)*WROW) + (k0 >> 2);
                #pragma unroll
                for (int kk4 = 0; kk4 < 8; kk4++) {
                    float4 wr = Wr[kk4], wz = Wz[kk4], wn = Wn[kk4];
                    #pragma unroll
                    for (int b4 = 0; b4 < 4; b4++) {
                        float4 hv = *(const float4*)(HsB + (ty*4 + b4)*HROW + kk4*4);
                        racc[b4] = fmaf(hv.x, wr.x, racc[b4]);
                        racc[b4] = fmaf(hv.y, wr.y, racc[b4]);
                        racc[b4] = fmaf(hv.z, wr.z, racc[b4]);
                        racc[b4] = fmaf(hv.w, wr.w, racc[b4]);
                        zacc[b4] = fmaf(hv.x, wz.x, zacc[b4]);
                        zacc[b4] = fmaf(hv.y, wz.y, zacc[b4]);
                        zacc[b4] = fmaf(hv.z, wz.z, zacc[b4]);
                        zacc[b4] = fmaf(hv.w, wz.w, zacc[b4]);
                        nacc[b4] = fmaf(hv.x, wn.x, nacc[b4]);
                        nacc[b4] = fmaf(hv.y, wn.y, nacc[b4]);
                        nacc[b4] = fmaf(hv.z, wn.z, nacc[b4]);
                        nacc[b4] = fmaf(hv.w, wn.w, nacc[b4]);
                    }
                }
                if (i < 15) {
                    float* HsN = Hs + (buf^1)*64*HROW;
                    int lin0 = tid, lin1 = tid + 256;
                    *(float4*)(HsN + (lin0 >> 3)*HROW + (lin0 & 7)*4) = p0;
                    *(float4*)(HsN + (lin1 >> 3)*HROW + (lin1 & 7)*4) = p1;
                    __syncthreads();
                    buf ^= 1;
                }
            }
            #pragma unroll
            for (int b4 = 0; b4 < 4; b4++) {
                int b = row0 + ty*4 + b4;
                hp[b4] = __ldcg(Y + ((size_t)tprev*Bq + b)*2*Hq + dirv*Hq + c);
            }
        }

        const float* gi_t = gi_base + (size_t)t*Bq*H3q;
        #pragma unroll
        for (int b4 = 0; b4 < 4; b4++) {
            int b = row0 + ty*4 + b4;
            const float* gib = gi_t + (size_t)b*H3q;
            float gr = __ldg(gib + c), gz = __ldg(gib + Hq + c), gn = __ldg(gib + 2*Hq + c);
            float r = 1.f/(1.f + expf(-(gr + racc[b4] + br)));
            float z = 1.f/(1.f + expf(-(gz + zacc[b4] + bz)));
            float n = tanhf(gn + r*(nacc[b4] + bn));
            Y[((size_t)t*Bq + b)*2*Hq + dirv*Hq + c] = (1.f - z)*n + z*hp[b4];
        }

        __threadfence();
        __syncthreads();
        if (tid == 0) {
            atomicAdd(&g_barc[layer], 1u);
            unsigned target = 128u * (unsigned)(s + 1);
            while (*(volatile unsigned*)&g_barc[layer] < target) { }
        }
        __syncthreads();
    }
}

// ---------------- decoder GRU step ----------------
__global__ void k_gru_dec(const float* __restrict__ Wih, const float* __restrict__ Whh,
                          const float* __restrict__ bih, const float* __restrict__ bhh,
                          const float* __restrict__ emb, int layer, int p) {
    const float* hprev = g_hd[p][layer];
    const float* xin   = (layer == 0) ? (const float*)nullptr : g_hd[1-p][0];
    float* hout        = g_hd[1-p][layer];

    int tid = threadIdx.x;
    int tx = tid & 15, ty = tid >> 4;
    int col0 = blockIdx.x * 16, row0 = blockIdx.y * 32;

    __shared__ float Xs[KT][33];
    __shared__ float Hs[KT][33];
    __shared__ float Wi[3][KT][17];
    __shared__ float Wh[3][KT][17];
    __shared__ int vs[32];

    if (layer == 0 && tid < 32) vs[tid] = g_vecin[row0 + tid];
    __syncthreads();

    float rs[2] = {0,0}, zs[2] = {0,0}, nis[2] = {0,0}, nhs[2] = {0,0};

    for (int k0 = 0; k0 < Hq; k0 += KT) {
        {
            int r = tid >> 3, kk = (tid & 7) << 2;
            const float* xb = (layer == 0) ? (emb + (size_t)vs[r]*Hq)
                                           : (xin + (size_t)(row0 + r)*Hq);
            float4 x4 = *(const float4*)(xb + k0 + kk);
            Xs[kk][r]=x4.x; Xs[kk+1][r]=x4.y; Xs[kk+2][r]=x4.z; Xs[kk+3][r]=x4.w;
            float4 h4 = *(const float4*)(hprev + (size_t)(row0 + r)*Hq + k0 + kk);
            Hs[kk][r]=h4.x; Hs[kk+1][r]=h4.y; Hs[kk+2][r]=h4.z; Hs[kk+3][r]=h4.w;
        }
        #pragma unroll
        for (int j = 0; j < 6; j++) {
            int lin = tid + j*256;
            int rr = lin >> 5, k = lin & 31;
            int g = rr >> 4, c = rr & 15;
            Wi[g][k][c] = Wih[(size_t)(g*Hq + col0 + c)*Hq + k0 + k];
            Wh[g][k][c] = Whh[(size_t)(g*Hq + col0 + c)*Hq + k0 + k];
        }
        __syncthreads();
        #pragma unroll
        for (int k = 0; k < KT; k++) {
            float wir = Wi[0][k][tx], wiz = Wi[1][k][tx], win = Wi[2][k][tx];
            float whr = Wh[0][k][tx], whz = Wh[1][k][tx], whn = Wh[2][k][tx];
            #pragma unroll
            for (int i = 0; i < 2; i++) {
                float xv = Xs[k][ty + 16*i], hv = Hs[k][ty + 16*i];
                rs[i]  = fmaf(xv, wir, rs[i]);  rs[i]  = fmaf(hv, whr, rs[i]);
                zs[i]  = fmaf(xv, wiz, zs[i]);  zs[i]  = fmaf(hv, whz, zs[i]);
                nis[i] = fmaf(xv, win, nis[i]);
                nhs[i] = fmaf(hv, whn, nhs[i]);
            }
        }
        __syncthreads();
    }
    int c = col0 + tx;
    float bir = bih[c], biz = bih[Hq+c], bin = bih[2*Hq+c];
    float bhr = bhh[c], bhz = bhh[Hq+c], bhn = bhh[2*Hq+c];
    #pragma unroll
    for (int i = 0; i < 2; i++) {
        int b = row0 + ty + 16*i;
        float hp = hprev[(size_t)b*Hq + c];
        float r = 1.f/(1.f + expf(-(rs[i] + bir + bhr)));
        float z = 1.f/(1.f + expf(-(zs[i] + biz + bhz)));
        float n = tanhf(nis[i] + bin + r*(nhs[i] + bhn));
        hout[(size_t)b*Hq + c] = (1.f - z)*n + z*hp;
    }
}

// ---------------- v row norms ----------------
__global__ void k_vn() {
    int row = blockIdx.x;
    int tid = threadIdx.x;
    const float* vr = g_v + (size_t)row*Hq;
    float s = 0.f;
    for (int k = tid; k < Hq; k += 128) { float x = vr[k]; s = fmaf(x, x, s); }
    __shared__ float red[128];
    red[tid] = s; __syncthreads();
    for (int o = 64; o > 0; o >>= 1) { if (tid < o) red[tid] += red[tid + o]; __syncthreads(); }
    if (tid == 0) g_vn[row] = fmaxf(sqrtf(red[0]), 1e-8f);
}

// ---------------- decoder init ----------------
__global__ void k_initdec() {
    int idx = blockIdx.x * blockDim.x + threadIdx.x;
    if (idx < Bq) g_vecin[idx] = 0;
    if (idx < Bq*Hq) {
        int b = idx / Hq, h = idx % Hq;
        g_hd[0][0][idx] = g_y0[((size_t)(LCq-1)*Bq + b)*2*Hq + h];
        g_hd[0][1][idx] = g_y0[((size_t)b)*2*Hq + Hq + h];
    }
}

// ---------------- attention ----------------
__global__ void k_attn(int t, int w, float* __restrict__ attn_out) {
    int b = blockIdx.x;
    int tid = threadIdx.x;
    __shared__ __align__(16) float qs[Hq];
    __shared__ float red[256];
    __shared__ float wsm[LCq];

    const float* q = g_hd[w][1] + (size_t)b*Hq;
    qs[tid] = q[tid]; qs[tid + 256] = q[tid + 256];
    __syncthreads();

    float ss = qs[tid]*qs[tid] + qs[tid+256]*qs[tid+256];
    red[tid] = ss; __syncthreads();
    for (int o = 128; o > 0; o >>= 1) { if (tid < o) red[tid] += red[tid + o]; __syncthreads(); }
    float qn = fmaxf(sqrtf(red[0]), 1e-8f);
    __syncthreads();

    const float4* v4 = (const float4*)(g_v + ((size_t)tid*Bq + b)*Hq);
    const float4* q4 = (const float4*)qs;
    float dot = 0.f;
    #pragma unroll 4
    for (int k = 0; k < Hq/4; k++) {
        float4 a = v4[k], c = q4[k];
        dot = fmaf(a.x, c.x, dot); dot = fmaf(a.y, c.y, dot);
        dot = fmaf(a.z, c.z, dot); dot = fmaf(a.w, c.w, dot);
    }
    float sim = dot / (g_vn[(size_t)tid*Bq + b] * qn);

    red[tid] = sim; __syncthreads();
    for (int o = 128; o > 0; o >>= 1) { if (tid < o) red[tid] = fmaxf(red[tid], red[tid+o]); __syncthreads(); }
    float mx = red[0]; __syncthreads();
    float e = expf(sim - mx);
    red[tid] = e; __syncthreads();
    for (int o = 128; o > 0; o >>= 1) { if (tid < o) red[tid] += red[tid + o]; __syncthreads(); }
    float wv = e / red[0];
    wsm[tid] = wv;
    attn_out[((size_t)b*LCq + tid)*LTq + t] = wv;
    __syncthreads();

    for (int h = tid; h < Hq; h += 256) {
        float acc = 0.f;
        for (int l = 0; l < LCq; l++)
            acc = fmaf(wsm[l], g_v[((size_t)l*Bq + b)*Hq + h], acc);
        g_a[(size_t)b*Hq + h] = acc;
    }
}

// ---------------- attention_fc ----------------
__global__ void k_attfc(const float* __restrict__ Watt, const float* __restrict__ batt, int w) {
    const float* X1 = g_hd[w][1];
    const float* X2 = g_a;
    int tid = threadIdx.x;
    int tx = tid & 15, ty = tid >> 4;
    int col0 = blockIdx.x * 16, row0 = blockIdx.y * 32;

    __shared__ float Xs[KT][33];
    __shared__ float As2[KT][33];
    __shared__ float Wq[KT][17];
    __shared__ float Wa[KT][17];

    float acc[2] = {0,0};
    for (int k0 = 0; k0 < Hq; k0 += KT) {
        {
            int r = tid >> 3, kk = (tid & 7) << 2;
            float4 x4 = *(const float4*)(X1 + (size_t)(row0 + r)*Hq + k0 + kk);
            Xs[kk][r]=x4.x; Xs[kk+1][r]=x4.y; Xs[kk+2][r]=x4.z; Xs[kk+3][r]=x4.w;
            float4 a4 = *(const float4*)(X2 + (size_t)(row0 + r)*Hq + k0 + kk);
            As2[kk][r]=a4.x; As2[kk+1][r]=a4.y; As2[kk+2][r]=a4.z; As2[kk+3][r]=a4.w;
        }
        #pragma unroll
        for (int j = 0; j < 2; j++) {
            int lin = tid + j*256;
            int c = lin >> 5, k = lin & 31;
            Wq[k][c] = Watt[(size_t)(col0 + c)*2*Hq + k0 + k];
            Wa[k][c] = Watt[(size_t)(col0 + c)*2*Hq + Hq + k0 + k];
        }
        __syncthreads();
        #pragma unroll
        for (int k = 0; k < KT; k++) {
            float wq = Wq[k][tx], wa = Wa[k][tx];
            #pragma unroll
            for (int i = 0; i < 2; i++) {
                acc[i] = fmaf(Xs[k][ty + 16*i], wq, acc[i]);
                acc[i] = fmaf(As2[k][ty + 16*i], wa, acc[i]);
            }
        }
        __syncthreads();
    }
    int c = col0 + tx;
    #pragma unroll
    for (int i = 0; i < 2; i++) {
        int b = row0 + ty + 16*i;
        g_hid[(size_t)b*Hq + c] = acc[i] + batt[c];
    }
}

// ---------------- output logits + argmax ----------------
__global__ void k_out(const float* __restrict__ Wout, const float* __restrict__ bout,
                      int t, float* __restrict__ vecout) {
    int b = blockIdx.x;
    int tid = threadIdx.x;
    __shared__ float hs[Hq];
    __shared__ float lg[32];
    hs[tid] = g_hid[(size_t)b*Hq + tid];
    hs[tid + 256] = g_hid[(size_t)b*Hq + tid + 256];
    __syncthreads();

    int wid = tid >> 5, lane = tid & 31;
    for (int j = wid; j < Vq; j += 8) {
        float acc = 0.f;
        for (int k = lane; k < Hq; k += 32)
            acc = fmaf(hs[k], Wout[(size_t)j*Hq + k], acc);
        #pragma unroll
        for (int o = 16; o > 0; o >>= 1) acc += __shfl_down_sync(0xffffffffu, acc, o);
        if (lane == 0) lg[j] = acc + bout[j];
    }
    __syncthreads();
    if (tid < Vq) vecout[((size_t)b*LTq + t)*Vq + tid] = lg[tid];
    if (tid == 0) {
        int best = 0; float bv = lg[0];
        for (int j = 1; j < Vq; j++) { if (lg[j] > bv) { bv = lg[j]; best = j; } }
        g_vecin[b] = best;
    }
}

__global__ void k_hfinal(float* __restrict__ out) {
    int idx = blockIdx.x * blockDim.x + threadIdx.x;
    if (idx < NLq*Bq*Hq) out[idx] = (&g_hd[0][0][0])[idx];
}

// ---------------- launch ----------------
extern "C" void kernel_launch(void* const* d_in, const int* in_sizes, int n_in,
                              void* d_out, int out_size) {
    const float* x        = (const float*)d_in[0];
    const float* emb      = (const float*)d_in[2];
    const float* W_enc    = (const float*)d_in[3];
    const float* b_enc    = (const float*)d_in[4];
    const float* enc0_Wih = (const float*)d_in[5];
    const float* enc0_Whh = (const float*)d_in[6];
    const float* enc0_bih = (const float*)d_in[7];
    const float* enc0_bhh = (const float*)d_in[8];
    const float* enc1_Wih = (const float*)d_in[9];
    const float* enc1_Whh = (const float*)d_in[10];
    const float* enc1_bih = (const float*)d_in[11];
    const float* enc1_bhh = (const float*)d_in[12];
    const float* W_bi     = (const float*)d_in[13];
    const float* b_bi     = (const float*)d_in[14];
    const float* dec_Wih  = (const float*)d_in[15];
    const float* dec_Whh  = (const float*)d_in[16];
    const float* dec_bih  = (const float*)d_in[17];
    const float* dec_bhh  = (const float*)d_in[18];
    const float* W_att    = (const float*)d_in[19];
    const float* b_att    = (const float*)d_in[20];
    const float* W_out    = (const float*)d_in[21];
    const float* b_out    = (const float*)d_in[22];

    float* out_vec  = (float*)d_out;
    float* out_h    = out_vec + (size_t)Bq*LTq*Vq;
    float* out_attn = out_h + (size_t)NLq*Bq*Hq;

    const int PERS_SMEM = (48*WROW + 2*64*HROW) * 4;
    cudaFuncSetAttribute(k_enc_pers, cudaFuncAttributeMaxDynamicSharedMemorySize, PERS_SMEM);

    // resolve bf16 scratch symbol addresses (device globals; query only, no alloc)
    __nv_bfloat16 *xr_h, *xr_l, *y0_h, *y0_l, *y1_h, *y1_l, *w0_h, *w0_l, *w1_h, *w1_l, *wb_h, *wb_l;
    cudaGetSymbolAddress((void**)&xr_h, g_xr_h); cudaGetSymbolAddress((void**)&xr_l, g_xr_l);
    cudaGetSymbolAddress((void**)&y0_h, g_y0_h); cudaGetSymbolAddress((void**)&y0_l, g_y0_l);
    cudaGetSymbolAddress((void**)&y1_h, g_y1_h); cudaGetSymbolAddress((void**)&y1_l, g_y1_l);
    cudaGetSymbolAddress((void**)&w0_h, g_w0_h); cudaGetSymbolAddress((void**)&w0_l, g_w0_l);
    cudaGetSymbolAddress((void**)&w1_h, g_w1_h); cudaGetSymbolAddress((void**)&w1_l, g_w1_l);
    cudaGetSymbolAddress((void**)&wb_h, g_wb_h); cudaGetSymbolAddress((void**)&wb_l, g_wb_l);
    float* xr_f; cudaGetSymbolAddress((void**)&xr_f, g_xr);
    float* y0_f; cudaGetSymbolAddress((void**)&y0_f, g_y0);
    float* y1_f; cudaGetSymbolAddress((void**)&y1_f, g_y1);
    float* gi_f; cudaGetSymbolAddress((void**)&gi_f, g_gi);
    float* v_f;  cudaGetSymbolAddress((void**)&v_f,  g_v);

    // encoder input projection + weight conversions
    k_proj<<<(Mq*Hq + 255)/256, 256>>>(x, W_enc, b_enc);
    k_zerobar<<<1, 1>>>();
    k_cvt<<<(2*H3q*Hq/4 + 255)/256, 256>>>(enc0_Wih, w0_h, w0_l, 2*H3q*Hq/4);
    k_cvt<<<(2*H3q*2*Hq/4 + 255)/256, 256>>>(enc1_Wih, w1_h, w1_l, 2*H3q*2*Hq/4);
    k_cvt<<<(Hq*2*Hq/4 + 255)/256, 256>>>(W_bi, wb_h, wb_l, Hq*2*Hq/4);
    k_cvt<<<(Mq*Hq/4 + 255)/256, 256>>>(xr_f, xr_h, xr_l, Mq*Hq/4);

    // layer 0: gi GEMM (tensor) + persistent recurrence
    k_gemm_mma<<<dim3(H3q/64, Mq/128, 2), 256>>>(
        xr_h, xr_l, w0_h, w0_l, enc0_bih, gi_f,
        Hq, H3q, (size_t)H3q*Hq, H3q, (size_t)Mq*H3q);
    k_enc_pers<<<128, 256, PERS_SMEM>>>(enc0_Whh, enc0_bhh, 0);

    // layer 1
    k_cvt<<<(Mq*2*Hq/4 + 255)/256, 256>>>(y0_f, y0_h, y0_l, Mq*2*Hq/4);
    k_gemm_mma<<<dim3(H3q/64, Mq/128, 2), 256>>>(
        y0_h, y0_l, w1_h, w1_l, enc1_bih, gi_f,
        2*Hq, H3q, (size_t)H3q*2*Hq, H3q, (size_t)Mq*H3q);
    k_enc_pers<<<128, 256, PERS_SMEM>>>(enc1_Whh, enc1_bhh, 1);

    // bi_fc + norms
    k_cvt<<<(Mq*2*Hq/4 + 255)/256, 256>>>(y1_f, y1_h, y1_l, Mq*2*Hq/4);
    k_gemm_mma<<<dim3(Hq/64, Mq/128, 1), 256>>>(
        y1_h, y1_l, wb_h, wb_l, b_bi, v_f,
        2*Hq, Hq, 0, 0, 0);
    k_vn<<<Mq, 128>>>();

    // decoder
    k_initdec<<<(Bq*Hq + 255)/256, 256>>>();
    for (int t = 0; t < LTq; t++) {
        int p = t & 1, w = 1 - p;
        k_gru_dec<<<dim3(Hq/16, Bq/32), 256>>>(dec_Wih, dec_Whh, dec_bih, dec_bhh,
                                               emb, 0, p);
        k_gru_dec<<<dim3(Hq/16, Bq/32), 256>>>(dec_Wih + (size_t)H3q*Hq,
                                               dec_Whh + (size_t)H3q*Hq,
                                               dec_bih + H3q, dec_bhh + H3q,
                                               emb, 1, p);
        k_attn<<<Bq, 256>>>(t, w, out_attn);
        k_attfc<<<dim3(Hq/16, Bq/32), 256>>>(W_att, b_att, w);
        k_out<<<Bq, 256>>>(W_out, b_out, t, out_vec);
    }
    k_hfinal<<<(NLq*Bq*Hq + 255)/256, 256>>>(out_h);
    (void)in_sizes; (void)n_in; (void)out_size;
}

// round 5
// speedup vs baseline: 2.1270x; 1.2605x over previous
#include <cuda_runtime.h>
#include <cuda_bf16.h>
#include <math.h>
#include <stdint.h>

#define Bq 128
#define Hq 512
#define LCq 256
#define LTq 64
#define Vq 27
#define NLq 2
#define H3q (3*Hq)
#define KT 32
#define Mq (LCq*Bq)

// ---------------- scratch (device globals: allocation-free rule) ----------------
__device__ float g_xr[(size_t)Mq*Hq];
__device__ float g_gi[(size_t)2*Mq*H3q];
__device__ float g_y0[(size_t)Mq*2*Hq];
__device__ float g_y1[(size_t)Mq*2*Hq];
__device__ float g_v [(size_t)Mq*Hq];
__device__ float g_vn[Mq];
__device__ float g_hd[2][NLq][Bq*Hq];
__device__ float g_a [Bq*Hq];
__device__ float g_hid[Bq*Hq];
__device__ int   g_vecin[Bq];
__device__ unsigned g_barc[2];

// bf16 hi/lo decompositions
__device__ __nv_bfloat16 g_xr_h[(size_t)Mq*Hq],   g_xr_l[(size_t)Mq*Hq];
__device__ __nv_bfloat16 g_y0_h[(size_t)Mq*2*Hq], g_y0_l[(size_t)Mq*2*Hq];
__device__ __nv_bfloat16 g_y1_h[(size_t)Mq*2*Hq], g_y1_l[(size_t)Mq*2*Hq];
__device__ __nv_bfloat16 g_w0_h[2*H3q*Hq],   g_w0_l[2*H3q*Hq];
__device__ __nv_bfloat16 g_w1_h[2*H3q*2*Hq], g_w1_l[2*H3q*2*Hq];
__device__ __nv_bfloat16 g_wb_h[Hq*2*Hq],    g_wb_l[Hq*2*Hq];

// ---------------- warp-mma primitives (sm_80+ PTX, works on compute_103) -------
__device__ __forceinline__ uint32_t smem_u32(const void* p) {
    uint32_t a;
    asm("{ .reg .u64 t; cvta.to.shared.u64 t, %1; cvt.u32.u64 %0, t; }" : "=r"(a) : "l"(p));
    return a;
}
__device__ __forceinline__ void ldsm4(uint32_t& r0, uint32_t& r1, uint32_t& r2, uint32_t& r3,
                                      uint32_t a) {
    asm volatile("ldmatrix.sync.aligned.m8n8.x4.shared.b16 {%0,%1,%2,%3}, [%4];"
        : "=r"(r0), "=r"(r1), "=r"(r2), "=r"(r3) : "r"(a));
}
__device__ __forceinline__ void ldsm2(uint32_t& r0, uint32_t& r1, uint32_t a) {
    asm volatile("ldmatrix.sync.aligned.m8n8.x2.shared.b16 {%0,%1}, [%2];"
        : "=r"(r0), "=r"(r1) : "r"(a));
}
__device__ __forceinline__ void mma_bf16(float* c, const uint32_t* a, const uint32_t* b) {
    asm volatile("mma.sync.aligned.m16n8k16.row.col.f32.bf16.bf16.f32 "
        "{%0,%1,%2,%3}, {%4,%5,%6,%7}, {%8,%9}, {%0,%1,%2,%3};"
        : "+f"(c[0]), "+f"(c[1]), "+f"(c[2]), "+f"(c[3])
        : "r"(a[0]), "r"(a[1]), "r"(a[2]), "r"(a[3]), "r"(b[0]), "r"(b[1]));
}

// ---------------- fp32 -> bf16 hi/lo split ----------------
__global__ void k_cvt(const float* __restrict__ s, __nv_bfloat16* __restrict__ hi,
                      __nv_bfloat16* __restrict__ lo, int n4) {
    int i = blockIdx.x * blockDim.x + threadIdx.x;
    if (i >= n4) return;
    float4 v = *(const float4*)(s + (size_t)i*4);
    __nv_bfloat16 h0 = __float2bfloat16(v.x), h1 = __float2bfloat16(v.y);
    __nv_bfloat16 h2 = __float2bfloat16(v.z), h3 = __float2bfloat16(v.w);
    __nv_bfloat162 hA, hB, lA, lB;
    hA.x = h0; hA.y = h1; hB.x = h2; hB.y = h3;
    lA.x = __float2bfloat16(v.x - __bfloat162float(h0));
    lA.y = __float2bfloat16(v.y - __bfloat162float(h1));
    lB.x = __float2bfloat16(v.z - __bfloat162float(h2));
    lB.y = __float2bfloat16(v.w - __bfloat162float(h3));
    *(__nv_bfloat162*)(hi + (size_t)i*4)     = hA;
    *(__nv_bfloat162*)(hi + (size_t)i*4 + 2) = hB;
    *(__nv_bfloat162*)(lo + (size_t)i*4)     = lA;
    *(__nv_bfloat162*)(lo + (size_t)i*4 + 2) = lB;
}

// ---------------- encoder input projection ----------------
__global__ void k_proj(const float* __restrict__ x, const float* __restrict__ W_enc,
                       const float* __restrict__ b_enc) {
    int idx = blockIdx.x * blockDim.x + threadIdx.x;
    if (idx >= Mq*Hq) return;
    int h = idx % Hq; int bl = idx / Hq; int b = bl % Bq; int l = bl / Bq;
    float v = x[(size_t)b*2*LCq + l] * W_enc[h*2]
            + x[(size_t)b*2*LCq + LCq + l] * W_enc[h*2+1] + b_enc[h];
    g_xr[idx] = v;
}

__global__ void k_zerobar() { g_barc[0] = 0; g_barc[1] = 0; }

// ---------------- tensor-core GEMM via warp mma: C = A @ W^T + bias ------------
#define AROW 40
__global__ void __launch_bounds__(256) k_gemm_mma(
        const __nv_bfloat16* __restrict__ Ah, const __nv_bfloat16* __restrict__ Al,
        const __nv_bfloat16* __restrict__ Wh, const __nv_bfloat16* __restrict__ Wl,
        const float* __restrict__ bias, float* __restrict__ C,
        int K, int Nld, size_t wStrideZ, int bStrideZ, size_t cStrideZ) {
    __shared__ __nv_bfloat16 sAh[128*AROW], sAl[128*AROW];
    __shared__ __nv_bfloat16 sWh[64*AROW],  sWl[64*AROW];

    int tid = threadIdx.x, wid = tid >> 5, lane = tid & 31;
    int z = blockIdx.z;
    const __nv_bfloat16* Whz = Wh + (size_t)z*wStrideZ;
    const __nv_bfloat16* Wlz = Wl + (size_t)z*wStrideZ;
    const float* bias_z = bias + (size_t)z*bStrideZ;
    float* C_z = C + (size_t)z*cStrideZ;
    int col0 = blockIdx.x * 64, row0 = blockIdx.y * 128;
    int wm = (wid & 3) * 32, wn = (wid >> 2) * 32;

    float acc[2][4][4];
    #pragma unroll
    for (int i = 0; i < 2; i++)
        #pragma unroll
        for (int j = 0; j < 4; j++)
            #pragma unroll
            for (int k = 0; k < 4; k++) acc[i][j][k] = 0.f;

    uint32_t aBase = smem_u32(sAh), alBase = smem_u32(sAl);
    uint32_t wBase = smem_u32(sWh), wlBase = smem_u32(sWl);
    int aRow = wm + (lane & 15);
    int aCol = (lane >> 4) * 8;
    int g = lane >> 3;
    int bRow = wn + (lane & 7) + ((g >> 1) & 1) * 8;
    int bCol = (g & 1) * 8;

    for (int k0 = 0; k0 < K; k0 += 32) {
        #pragma unroll
        for (int i = 0; i < 2; i++) {
            int u = tid + (i << 8);
            int r = u >> 2, cu = u & 3;
            size_t go = (size_t)(row0 + r)*K + k0 + cu*8;
            *(uint4*)(sAh + r*AROW + cu*8) = *(const uint4*)(Ah + go);
            *(uint4*)(sAl + r*AROW + cu*8) = *(const uint4*)(Al + go);
        }
        {
            int r = tid >> 2, cu = tid & 3;
            size_t go = (size_t)(col0 + r)*K + k0 + cu*8;
            *(uint4*)(sWh + r*AROW + cu*8) = *(const uint4*)(Whz + go);
            *(uint4*)(sWl + r*AROW + cu*8) = *(const uint4*)(Wlz + go);
        }
        __syncthreads();

        #pragma unroll
        for (int ks = 0; ks < 2; ks++) {
            uint32_t ah[2][4], al[2][4], bh[2][4], bl[2][4];
            #pragma unroll
            for (int mi = 0; mi < 2; mi++) {
                uint32_t off = (uint32_t)(((aRow + mi*16)*AROW + ks*16 + aCol) * 2);
                ldsm4(ah[mi][0], ah[mi][1], ah[mi][2], ah[mi][3], aBase + off);
                ldsm4(al[mi][0], al[mi][1], al[mi][2], al[mi][3], alBase + off);
            }
            #pragma unroll
            for (int ng = 0; ng < 2; ng++) {
                uint32_t off = (uint32_t)(((bRow + ng*16)*AROW + ks*16 + bCol) * 2);
                ldsm4(bh[ng][0], bh[ng][1], bh[ng][2], bh[ng][3], wBase + off);
                ldsm4(bl[ng][0], bl[ng][1], bl[ng][2], bl[ng][3], wlBase + off);
            }
            #pragma unroll
            for (int mi = 0; mi < 2; mi++)
                #pragma unroll
                for (int ng = 0; ng < 2; ng++) {
                    #pragma unroll
                    for (int half = 0; half < 2; half++) {
                        float* c = acc[mi][ng*2 + half];
                        mma_bf16(c, ah[mi], &bh[ng][half*2]);
                        mma_bf16(c, ah[mi], &bl[ng][half*2]);
                        mma_bf16(c, al[mi], &bh[ng][half*2]);
                    }
                }
        }
        __syncthreads();
    }

    #pragma unroll
    for (int mi = 0; mi < 2; mi++) {
        int r_ = row0 + wm + mi*16 + (lane >> 2);
        #pragma unroll
        for (int ni = 0; ni < 4; ni++) {
            int c_ = col0 + wn + ni*8 + (lane & 3)*2;
            float b0 = bias_z[c_], b1 = bias_z[c_ + 1];
            float2 o0 = { acc[mi][ni][0] + b0, acc[mi][ni][1] + b1 };
            float2 o1 = { acc[mi][ni][2] + b0, acc[mi][ni][3] + b1 };
            *(float2*)(C_z + (size_t)r_*Nld + c_)       = o0;
            *(float2*)(C_z + (size_t)(r_ + 8)*Nld + c_) = o1;
        }
    }
}

// ---------------- persistent MMA encoder GRU layer ----------------
// 128 blocks = dir(2) x colgroup(32: 16 cols/gate) x batchhalf(2).
// W slice (48 gate-rows x 512) cached bf16 hi/lo in SMEM; h streamed bf16 hi/lo
// from Yh/Yl written by the previous step's tail. 256 steps with grid barriers.
#define WP 520
#define AP 72
#define ENC_SMEM ((96*WP + 128*AP) * 2)   // bytes: 118272
__global__ void __launch_bounds__(256, 1) k_enc_mma(
        const float* __restrict__ Whh2, const float* __restrict__ bhh2, int layer) {
    extern __shared__ __nv_bfloat16 smb[];
    __nv_bfloat16* sWh = smb;
    __nv_bfloat16* sWl = smb + 48*WP;
    __nv_bfloat16* sAh = smb + 96*WP;
    __nv_bfloat16* sAl = smb + 96*WP + 64*AP;

    float* Y = layer ? g_y1 : g_y0;
    __nv_bfloat16* Yh = layer ? g_y1_h : g_y0_h;
    __nv_bfloat16* Yl = layer ? g_y1_l : g_y0_l;

    int bid = blockIdx.x;
    int dirv = bid >> 6;
    int rem = bid & 63;
    int cg = rem & 31;
    int bg = rem >> 5;
    int gc0 = cg * 16;
    int row0 = bg * 64;

    int tid = threadIdx.x, wid = tid >> 5, lane = tid & 31;
    int wm = (wid & 3) * 16;       // M offset within 64-row tile
    int ws = wid >> 2;             // N split: 8 cols/gate per warp

    const float* Whh = Whh2 + (size_t)dirv*H3q*Hq;
    const float* bhh = bhh2 + dirv*H3q;

    // convert W slice fp32 -> bf16 hi/lo into SMEM (once)
    for (int u = tid; u < 48*128; u += 256) {
        int rrow = u >> 7, kq = u & 127;
        int g = rrow >> 4, c = rrow & 15;
        float4 w = __ldg((const float4*)(Whh + (size_t)(g*Hq + gc0 + c)*Hq) + kq);
        __nv_bfloat16 h0 = __float2bfloat16(w.x), h1 = __float2bfloat16(w.y);
        __nv_bfloat16 h2 = __float2bfloat16(w.z), h3 = __float2bfloat16(w.w);
        __nv_bfloat162 hh0; hh0.x = h0; hh0.y = h1;
        __nv_bfloat162 hh1; hh1.x = h2; hh1.y = h3;
        __nv_bfloat162 ll0, ll1;
        ll0.x = __float2bfloat16(w.x - __bfloat162float(h0));
        ll0.y = __float2bfloat16(w.y - __bfloat162float(h1));
        ll1.x = __float2bfloat16(w.z - __bfloat162float(h2));
        ll1.y = __float2bfloat16(w.w - __bfloat162float(h3));
        *(__nv_bfloat162*)(sWh + rrow*WP + kq*4)     = hh0;
        *(__nv_bfloat162*)(sWh + rrow*WP + kq*4 + 2) = hh1;
        *(__nv_bfloat162*)(sWl + rrow*WP + kq*4)     = ll0;
        *(__nv_bfloat162*)(sWl + rrow*WP + kq*4 + 2) = ll1;
    }
    int cA = gc0 + ws*8 + 2*(lane & 3);
    float br0 = __ldg(bhh + cA),        br1 = __ldg(bhh + cA + 1);
    float bz0 = __ldg(bhh + 512 + cA),  bz1 = __ldg(bhh + 512 + cA + 1);
    float bn0 = __ldg(bhh + 1024 + cA), bn1 = __ldg(bhh + 1024 + cA + 1);
    __syncthreads();

    uint32_t aBaseH = smem_u32(sAh), aBaseL = smem_u32(sAl);
    uint32_t wBaseH = smem_u32(sWh), wBaseL = smem_u32(sWl);
    uint32_t aOff = (uint32_t)(((wm + (lane & 15))*AP + (lane >> 4)*8) * 2);
    int bRow = ws*8 + (lane & 7);
    uint32_t bColOff = (uint32_t)((((lane >> 3) & 1) * 8) * 2);

    int ur0 = tid >> 3, uc0 = tid & 7;
    int ur1 = (tid + 256) >> 3, uc1 = (tid + 256) & 7;

    for (int s = 0; s < LCq; s++) {
        int t = dirv ? (LCq-1-s) : s;
        int tprev = dirv ? (t+1) : (t-1);

        float acc[3][4];
        #pragma unroll
        for (int g = 0; g < 3; g++) {
            acc[g][0] = acc[g][1] = acc[g][2] = acc[g][3] = 0.f;
        }

        if (s > 0) {
            const __nv_bfloat16* Ah = Yh + ((size_t)tprev*Bq)*2*Hq + (size_t)dirv*Hq;
            const __nv_bfloat16* Al = Yl + ((size_t)tprev*Bq)*2*Hq + (size_t)dirv*Hq;
            uint4 ph0, ph1, pl0, pl1;
            ph0 = __ldcg((const uint4*)(Ah + (size_t)(row0 + ur0)*2*Hq + uc0*8));
            ph1 = __ldcg((const uint4*)(Ah + (size_t)(row0 + ur1)*2*Hq + uc1*8));
            pl0 = __ldcg((const uint4*)(Al + (size_t)(row0 + ur0)*2*Hq + uc0*8));
            pl1 = __ldcg((const uint4*)(Al + (size_t)(row0 + ur1)*2*Hq + uc1*8));
            for (int kc = 0; kc < 8; kc++) {
                *(uint4*)(sAh + ur0*AP + uc0*8) = ph0;
                *(uint4*)(sAh + ur1*AP + uc1*8) = ph1;
                *(uint4*)(sAl + ur0*AP + uc0*8) = pl0;
                *(uint4*)(sAl + ur1*AP + uc1*8) = pl1;
                __syncthreads();
                if (kc < 7) {
                    int k1 = (kc + 1)*64;
                    ph0 = __ldcg((const uint4*)(Ah + (size_t)(row0 + ur0)*2*Hq + k1 + uc0*8));
                    ph1 = __ldcg((const uint4*)(Ah + (size_t)(row0 + ur1)*2*Hq + k1 + uc1*8));
                    pl0 = __ldcg((const uint4*)(Al + (size_t)(row0 + ur0)*2*Hq + k1 + uc0*8));
                    pl1 = __ldcg((const uint4*)(Al + (size_t)(row0 + ur1)*2*Hq + k1 + uc1*8));
                }
                int k0 = kc*64;
                #pragma unroll
                for (int ks = 0; ks < 4; ks++) {
                    uint32_t ah[4], al[4];
                    uint32_t ao = aOff + (uint32_t)(ks*32);
                    ldsm4(ah[0], ah[1], ah[2], ah[3], aBaseH + ao);
                    ldsm4(al[0], al[1], al[2], al[3], aBaseL + ao);
                    #pragma unroll
                    for (int g = 0; g < 3; g++) {
                        uint32_t bh[2], bl[2];
                        uint32_t wo = (uint32_t)((((g*16 + bRow)*WP) + k0 + ks*16)*2) + bColOff;
                        ldsm2(bh[0], bh[1], wBaseH + wo);
                        ldsm2(bl[0], bl[1], wBaseL + wo);
                        mma_bf16(acc[g], ah, bh);
                        mma_bf16(acc[g], ah, bl);
                        mma_bf16(acc[g], al, bh);
                    }
                }
                __syncthreads();
            }
        }

        // pointwise tail: 2 rows x 2 cols per thread
        const float* gi_t = g_gi + ((size_t)dirv*LCq + t)*Bq*H3q;
        #pragma unroll
        for (int rr = 0; rr < 2; rr++) {
            int b = row0 + wm + (lane >> 2) + rr*8;
            const float* gib = gi_t + (size_t)b*H3q;
            float2 gr = *(const float2*)(gib + cA);
            float2 gz = *(const float2*)(gib + 512 + cA);
            float2 gn = *(const float2*)(gib + 1024 + cA);
            float2 hp = make_float2(0.f, 0.f);
            if (s > 0)
                hp = __ldcg((const float2*)(Y + ((size_t)tprev*Bq + b)*2*Hq + (size_t)dirv*Hq + cA));
            float r0v = 1.f/(1.f + expf(-(gr.x + acc[0][rr*2]   + br0)));
            float r1v = 1.f/(1.f + expf(-(gr.y + acc[0][rr*2+1] + br1)));
            float z0v = 1.f/(1.f + expf(-(gz.x + acc[1][rr*2]   + bz0)));
            float z1v = 1.f/(1.f + expf(-(gz.y + acc[1][rr*2+1] + bz1)));
            float n0v = tanhf(gn.x + r0v*(acc[2][rr*2]   + bn0));
            float n1v = tanhf(gn.y + r1v*(acc[2][rr*2+1] + bn1));
            float h0v = (1.f - z0v)*n0v + z0v*hp.x;
            float h1v = (1.f - z1v)*n1v + z1v*hp.y;
            size_t o = ((size_t)t*Bq + b)*2*Hq + (size_t)dirv*Hq + cA;
            *(float2*)(Y + o) = make_float2(h0v, h1v);
            __nv_bfloat16 bh0 = __float2bfloat16(h0v), bh1 = __float2bfloat16(h1v);
            __nv_bfloat162 hv; hv.x = bh0; hv.y = bh1;
            __nv_bfloat162 lv;
            lv.x = __float2bfloat16(h0v - __bfloat162float(bh0));
            lv.y = __float2bfloat16(h1v - __bfloat162float(bh1));
            *(__nv_bfloat162*)(Yh + o) = hv;
            *(__nv_bfloat162*)(Yl + o) = lv;
        }

        __threadfence();
        __syncthreads();
        if (tid == 0) {
            atomicAdd(&g_barc[layer], 1u);
            unsigned target = 128u * (unsigned)(s + 1);
            while (*(volatile unsigned*)&g_barc[layer] < target) { }
        }
        __syncthreads();
    }
}

// ---------------- decoder GRU step ----------------
__global__ void k_gru_dec(const float* __restrict__ Wih, const float* __restrict__ Whh,
                          const float* __restrict__ bih, const float* __restrict__ bhh,
                          const float* __restrict__ emb, int layer, int p) {
    const float* hprev = g_hd[p][layer];
    const float* xin   = (layer == 0) ? (const float*)nullptr : g_hd[1-p][0];
    float* hout        = g_hd[1-p][layer];

    int tid = threadIdx.x;
    int tx = tid & 15, ty = tid >> 4;
    int col0 = blockIdx.x * 16, row0 = blockIdx.y * 32;

    __shared__ float Xs[KT][33];
    __shared__ float Hs[KT][33];
    __shared__ float Wi[3][KT][17];
    __shared__ float Wh[3][KT][17];
    __shared__ int vs[32];

    if (layer == 0 && tid < 32) vs[tid] = g_vecin[row0 + tid];
    __syncthreads();

    float rs[2] = {0,0}, zs[2] = {0,0}, nis[2] = {0,0}, nhs[2] = {0,0};

    for (int k0 = 0; k0 < Hq; k0 += KT) {
        {
            int r = tid >> 3, kk = (tid & 7) << 2;
            const float* xb = (layer == 0) ? (emb + (size_t)vs[r]*Hq)
                                           : (xin + (size_t)(row0 + r)*Hq);
            float4 x4 = *(const float4*)(xb + k0 + kk);
            Xs[kk][r]=x4.x; Xs[kk+1][r]=x4.y; Xs[kk+2][r]=x4.z; Xs[kk+3][r]=x4.w;
            float4 h4 = *(const float4*)(hprev + (size_t)(row0 + r)*Hq + k0 + kk);
            Hs[kk][r]=h4.x; Hs[kk+1][r]=h4.y; Hs[kk+2][r]=h4.z; Hs[kk+3][r]=h4.w;
        }
        #pragma unroll
        for (int j = 0; j < 6; j++) {
            int lin = tid + j*256;
            int rr = lin >> 5, k = lin & 31;
            int g = rr >> 4, c = rr & 15;
            Wi[g][k][c] = Wih[(size_t)(g*Hq + col0 + c)*Hq + k0 + k];
            Wh[g][k][c] = Whh[(size_t)(g*Hq + col0 + c)*Hq + k0 + k];
        }
        __syncthreads();
        #pragma unroll
        for (int k = 0; k < KT; k++) {
            float wir = Wi[0][k][tx], wiz = Wi[1][k][tx], win = Wi[2][k][tx];
            float whr = Wh[0][k][tx], whz = Wh[1][k][tx], whn = Wh[2][k][tx];
            #pragma unroll
            for (int i = 0; i < 2; i++) {
                float xv = Xs[k][ty + 16*i], hv = Hs[k][ty + 16*i];
                rs[i]  = fmaf(xv, wir, rs[i]);  rs[i]  = fmaf(hv, whr, rs[i]);
                zs[i]  = fmaf(xv, wiz, zs[i]);  zs[i]  = fmaf(hv, whz, zs[i]);
                nis[i] = fmaf(xv, win, nis[i]);
                nhs[i] = fmaf(hv, whn, nhs[i]);
            }
        }
        __syncthreads();
    }
    int c = col0 + tx;
    float bir = bih[c], biz = bih[Hq+c], bin = bih[2*Hq+c];
    float bhr = bhh[c], bhz = bhh[Hq+c], bhn = bhh[2*Hq+c];
    #pragma unroll
    for (int i = 0; i < 2; i++) {
        int b = row0 + ty + 16*i;
        float hp = hprev[(size_t)b*Hq + c];
        float r = 1.f/(1.f + expf(-(rs[i] + bir + bhr)));
        float z = 1.f/(1.f + expf(-(zs[i] + biz + bhz)));
        float n = tanhf(nis[i] + bin + r*(nhs[i] + bhn));
        hout[(size_t)b*Hq + c] = (1.f - z)*n + z*hp;
    }
}

// ---------------- v row norms ----------------
__global__ void k_vn() {
    int row = blockIdx.x;
    int tid = threadIdx.x;
    const float* vr = g_v + (size_t)row*Hq;
    float s = 0.f;
    for (int k = tid; k < Hq; k += 128) { float x = vr[k]; s = fmaf(x, x, s); }
    __shared__ float red[128];
    red[tid] = s; __syncthreads();
    for (int o = 64; o > 0; o >>= 1) { if (tid < o) red[tid] += red[tid + o]; __syncthreads(); }
    if (tid == 0) g_vn[row] = fmaxf(sqrtf(red[0]), 1e-8f);
}

// ---------------- decoder init ----------------
__global__ void k_initdec() {
    int idx = blockIdx.x * blockDim.x + threadIdx.x;
    if (idx < Bq) g_vecin[idx] = 0;
    if (idx < Bq*Hq) {
        int b = idx / Hq, h = idx % Hq;
        g_hd[0][0][idx] = g_y0[((size_t)(LCq-1)*Bq + b)*2*Hq + h];
        g_hd[0][1][idx] = g_y0[((size_t)b)*2*Hq + Hq + h];
    }
}

// ---------------- attention ----------------
__global__ void k_attn(int t, int w, float* __restrict__ attn_out) {
    int b = blockIdx.x;
    int tid = threadIdx.x;
    __shared__ __align__(16) float qs[Hq];
    __shared__ float red[256];
    __shared__ float wsm[LCq];

    const float* q = g_hd[w][1] + (size_t)b*Hq;
    qs[tid] = q[tid]; qs[tid + 256] = q[tid + 256];
    __syncthreads();

    float ss = qs[tid]*qs[tid] + qs[tid+256]*qs[tid+256];
    red[tid] = ss; __syncthreads();
    for (int o = 128; o > 0; o >>= 1) { if (tid < o) red[tid] += red[tid + o]; __syncthreads(); }
    float qn = fmaxf(sqrtf(red[0]), 1e-8f);
    __syncthreads();

    const float4* v4 = (const float4*)(g_v + ((size_t)tid*Bq + b)*Hq);
    const float4* q4 = (const float4*)qs;
    float dot = 0.f;
    #pragma unroll 4
    for (int k = 0; k < Hq/4; k++) {
        float4 a = v4[k], c = q4[k];
        dot = fmaf(a.x, c.x, dot); dot = fmaf(a.y, c.y, dot);
        dot = fmaf(a.z, c.z, dot); dot = fmaf(a.w, c.w, dot);
    }
    float sim = dot / (g_vn[(size_t)tid*Bq + b] * qn);

    red[tid] = sim; __syncthreads();
    for (int o = 128; o > 0; o >>= 1) { if (tid < o) red[tid] = fmaxf(red[tid], red[tid+o]); __syncthreads(); }
    float mx = red[0]; __syncthreads();
    float e = expf(sim - mx);
    red[tid] = e; __syncthreads();
    for (int o = 128; o > 0; o >>= 1) { if (tid < o) red[tid] += red[tid + o]; __syncthreads(); }
    float wv = e / red[0];
    wsm[tid] = wv;
    attn_out[((size_t)b*LCq + tid)*LTq + t] = wv;
    __syncthreads();

    for (int h = tid; h < Hq; h += 256) {
        float acc = 0.f;
        for (int l = 0; l < LCq; l++)
            acc = fmaf(wsm[l], g_v[((size_t)l*Bq + b)*Hq + h], acc);
        g_a[(size_t)b*Hq + h] = acc;
    }
}

// ---------------- attention_fc ----------------
__global__ void k_attfc(const float* __restrict__ Watt, const float* __restrict__ batt, int w) {
    const float* X1 = g_hd[w][1];
    const float* X2 = g_a;
    int tid = threadIdx.x;
    int tx = tid & 15, ty = tid >> 4;
    int col0 = blockIdx.x * 16, row0 = blockIdx.y * 32;

    __shared__ float Xs[KT][33];
    __shared__ float As2[KT][33];
    __shared__ float Wq[KT][17];
    __shared__ float Wa[KT][17];

    float acc[2] = {0,0};
    for (int k0 = 0; k0 < Hq; k0 += KT) {
        {
            int r = tid >> 3, kk = (tid & 7) << 2;
            float4 x4 = *(const float4*)(X1 + (size_t)(row0 + r)*Hq + k0 + kk);
            Xs[kk][r]=x4.x; Xs[kk+1][r]=x4.y; Xs[kk+2][r]=x4.z; Xs[kk+3][r]=x4.w;
            float4 a4 = *(const float4*)(X2 + (size_t)(row0 + r)*Hq + k0 + kk);
            As2[kk][r]=a4.x; As2[kk+1][r]=a4.y; As2[kk+2][r]=a4.z; As2[kk+3][r]=a4.w;
        }
        #pragma unroll
        for (int j = 0; j < 2; j++) {
            int lin = tid + j*256;
            int c = lin >> 5, k = lin & 31;
            Wq[k][c] = Watt[(size_t)(col0 + c)*2*Hq + k0 + k];
            Wa[k][c] = Watt[(size_t)(col0 + c)*2*Hq + Hq + k0 + k];
        }
        __syncthreads();
        #pragma unroll
        for (int k = 0; k < KT; k++) {
            float wq = Wq[k][tx], wa = Wa[k][tx];
            #pragma unroll
            for (int i = 0; i < 2; i++) {
                acc[i] = fmaf(Xs[k][ty + 16*i], wq, acc[i]);
                acc[i] = fmaf(As2[k][ty + 16*i], wa, acc[i]);
            }
        }
        __syncthreads();
    }
    int c = col0 + tx;
    #pragma unroll
    for (int i = 0; i < 2; i++) {
        int b = row0 + ty + 16*i;
        g_hid[(size_t)b*Hq + c] = acc[i] + batt[c];
    }
}

// ---------------- output logits + argmax ----------------
__global__ void k_out(const float* __restrict__ Wout, const float* __restrict__ bout,
                      int t, float* __restrict__ vecout) {
    int b = blockIdx.x;
    int tid = threadIdx.x;
    __shared__ float hs[Hq];
    __shared__ float lg[32];
    hs[tid] = g_hid[(size_t)b*Hq + tid];
    hs[tid + 256] = g_hid[(size_t)b*Hq + tid + 256];
    __syncthreads();

    int wid = tid >> 5, lane = tid & 31;
    for (int j = wid; j < Vq; j += 8) {
        float acc = 0.f;
        for (int k = lane; k < Hq; k += 32)
            acc = fmaf(hs[k], Wout[(size_t)j*Hq + k], acc);
        #pragma unroll
        for (int o = 16; o > 0; o >>= 1) acc += __shfl_down_sync(0xffffffffu, acc, o);
        if (lane == 0) lg[j] = acc + bout[j];
    }
    __syncthreads();
    if (tid < Vq) vecout[((size_t)b*LTq + t)*Vq + tid] = lg[tid];
    if (tid == 0) {
        int best = 0; float bv = lg[0];
        for (int j = 1; j < Vq; j++) { if (lg[j] > bv) { bv = lg[j]; best = j; } }
        g_vecin[b] = best;
    }
}

__global__ void k_hfinal(float* __restrict__ out) {
    int idx = blockIdx.x * blockDim.x + threadIdx.x;
    if (idx < NLq*Bq*Hq) out[idx] = (&g_hd[0][0][0])[idx];
}

// ---------------- launch ----------------
extern "C" void kernel_launch(void* const* d_in, const int* in_sizes, int n_in,
                              void* d_out, int out_size) {
    const float* x        = (const float*)d_in[0];
    const float* emb      = (const float*)d_in[2];
    const float* W_enc    = (const float*)d_in[3];
    const float* b_enc    = (const float*)d_in[4];
    const float* enc0_Wih = (const float*)d_in[5];
    const float* enc0_Whh = (const float*)d_in[6];
    const float* enc0_bih = (const float*)d_in[7];
    const float* enc0_bhh = (const float*)d_in[8];
    const float* enc1_Wih = (const float*)d_in[9];
    const float* enc1_Whh = (const float*)d_in[10];
    const float* enc1_bih = (const float*)d_in[11];
    const float* enc1_bhh = (const float*)d_in[12];
    const float* W_bi     = (const float*)d_in[13];
    const float* b_bi     = (const float*)d_in[14];
    const float* dec_Wih  = (const float*)d_in[15];
    const float* dec_Whh  = (const float*)d_in[16];
    const float* dec_bih  = (const float*)d_in[17];
    const float* dec_bhh  = (const float*)d_in[18];
    const float* W_att    = (const float*)d_in[19];
    const float* b_att    = (const float*)d_in[20];
    const float* W_out    = (const float*)d_in[21];
    const float* b_out    = (const float*)d_in[22];

    float* out_vec  = (float*)d_out;
    float* out_h    = out_vec + (size_t)Bq*LTq*Vq;
    float* out_attn = out_h + (size_t)NLq*Bq*Hq;

    cudaFuncSetAttribute(k_enc_mma, cudaFuncAttributeMaxDynamicSharedMemorySize, ENC_SMEM);

    __nv_bfloat16 *xr_h, *xr_l, *y0_h, *y0_l, *y1_h, *y1_l, *w0_h, *w0_l, *w1_h, *w1_l, *wb_h, *wb_l;
    cudaGetSymbolAddress((void**)&xr_h, g_xr_h); cudaGetSymbolAddress((void**)&xr_l, g_xr_l);
    cudaGetSymbolAddress((void**)&y0_h, g_y0_h); cudaGetSymbolAddress((void**)&y0_l, g_y0_l);
    cudaGetSymbolAddress((void**)&y1_h, g_y1_h); cudaGetSymbolAddress((void**)&y1_l, g_y1_l);
    cudaGetSymbolAddress((void**)&w0_h, g_w0_h); cudaGetSymbolAddress((void**)&w0_l, g_w0_l);
    cudaGetSymbolAddress((void**)&w1_h, g_w1_h); cudaGetSymbolAddress((void**)&w1_l, g_w1_l);
    cudaGetSymbolAddress((void**)&wb_h, g_wb_h); cudaGetSymbolAddress((void**)&wb_l, g_wb_l);
    float* xr_f; cudaGetSymbolAddress((void**)&xr_f, g_xr);
    float* gi_f; cudaGetSymbolAddress((void**)&gi_f, g_gi);
    float* v_f;  cudaGetSymbolAddress((void**)&v_f,  g_v);

    // encoder input projection + weight conversions
    k_proj<<<(Mq*Hq + 255)/256, 256>>>(x, W_enc, b_enc);
    k_zerobar<<<1, 1>>>();
    k_cvt<<<(2*H3q*Hq/4 + 255)/256, 256>>>(enc0_Wih, w0_h, w0_l, 2*H3q*Hq/4);
    k_cvt<<<(2*H3q*2*Hq/4 + 255)/256, 256>>>(enc1_Wih, w1_h, w1_l, 2*H3q*2*Hq/4);
    k_cvt<<<(Hq*2*Hq/4 + 255)/256, 256>>>(W_bi, wb_h, wb_l, Hq*2*Hq/4);
    k_cvt<<<(Mq*Hq/4 + 255)/256, 256>>>(xr_f, xr_h, xr_l, Mq*Hq/4);

    // layer 0: gi GEMM (tensor) + persistent MMA recurrence
    k_gemm_mma<<<dim3(H3q/64, Mq/128, 2), 256>>>(
        xr_h, xr_l, w0_h, w0_l, enc0_bih, gi_f,
        Hq, H3q, (size_t)H3q*Hq, H3q, (size_t)Mq*H3q);
    k_enc_mma<<<128, 256, ENC_SMEM>>>(enc0_Whh, enc0_bhh, 0);

    // layer 1 (y0 hi/lo produced by layer-0 encoder tail)
    k_gemm_mma<<<dim3(H3q/64, Mq/128, 2), 256>>>(
        y0_h, y0_l, w1_h, w1_l, enc1_bih, gi_f,
        2*Hq, H3q, (size_t)H3q*2*Hq, H3q, (size_t)Mq*H3q);
    k_enc_mma<<<128, 256, ENC_SMEM>>>(enc1_Whh, enc1_bhh, 1);

    // bi_fc + norms (y1 hi/lo produced by layer-1 encoder tail)
    k_gemm_mma<<<dim3(Hq/64, Mq/128, 1), 256>>>(
        y1_h, y1_l, wb_h, wb_l, b_bi, v_f,
        2*Hq, Hq, 0, 0, 0);
    k_vn<<<Mq, 128>>>();

    // decoder
    k_initdec<<<(Bq*Hq + 255)/256, 256>>>();
    for (int t = 0; t < LTq; t++) {
        int p = t & 1, w = 1 - p;
        k_gru_dec<<<dim3(Hq/16, Bq/32), 256>>>(dec_Wih, dec_Whh, dec_bih, dec_bhh,
                                               emb, 0, p);
        k_gru_dec<<<dim3(Hq/16, Bq/32), 256>>>(dec_Wih + (size_t)H3q*Hq,
                                               dec_Whh + (size_t)H3q*Hq,
                                               dec_bih + H3q, dec_bhh + H3q,
                                               emb, 1, p);
        k_attn<<<Bq, 256>>>(t, w, out_attn);
        k_attfc<<<dim3(Hq/16, Bq/32), 256>>>(W_att, b_att, w);
        k_out<<<Bq, 256>>>(W_out, b_out, t, out_vec);
    }
    k_hfinal<<<(NLq*Bq*Hq + 255)/256, 256>>>(out_h);
    (void)in_sizes; (void)n_in; (void)out_size;
}

// round 6
// speedup vs baseline: 2.6750x; 1.2576x over previous
#include <cuda_runtime.h>
#include <cuda_bf16.h>
#include <math.h>
#include <stdint.h>

#define Bq 128
#define Hq 512
#define LCq 256
#define LTq 64
#define Vq 27
#define NLq 2
#define H3q (3*Hq)
#define KT 32
#define Mq (LCq*Bq)

// ---------------- scratch ----------------
__device__ float g_gi[(size_t)2*Mq*H3q];
__device__ float g_y0[(size_t)Mq*2*Hq];
__device__ float g_y1[(size_t)Mq*2*Hq];
__device__ float g_v [(size_t)Mq*Hq];
__device__ float g_vn[Mq];
__device__ float g_hd[2][NLq][Bq*Hq];
__device__ float g_a [Bq*Hq];
__device__ float g_hid[Bq*Hq];
__device__ int   g_vecin[Bq];
__device__ unsigned g_barc[2];
__device__ unsigned g_dbar;

// bf16 hi/lo decompositions
__device__ __nv_bfloat16 g_xr_h[(size_t)Mq*Hq],   g_xr_l[(size_t)Mq*Hq];
__device__ __nv_bfloat16 g_y0_h[(size_t)Mq*2*Hq], g_y0_l[(size_t)Mq*2*Hq];
__device__ __nv_bfloat16 g_y1_h[(size_t)Mq*2*Hq], g_y1_l[(size_t)Mq*2*Hq];
__device__ __nv_bfloat16 g_w0_h[2*H3q*Hq],   g_w0_l[2*H3q*Hq];
__device__ __nv_bfloat16 g_w1_h[2*H3q*2*Hq], g_w1_l[2*H3q*2*Hq];
__device__ __nv_bfloat16 g_wb_h[Hq*2*Hq],    g_wb_l[Hq*2*Hq];
// decoder bf16
__device__ __nv_bfloat16 g_dwih_h[NLq*H3q*Hq], g_dwih_l[NLq*H3q*Hq];
__device__ __nv_bfloat16 g_dwhh_h[NLq*H3q*Hq], g_dwhh_l[NLq*H3q*Hq];
__device__ __nv_bfloat16 g_emb_h[Vq*Hq], g_emb_l[Vq*Hq];
__device__ __nv_bfloat16 g_hdh[2][NLq][Bq*Hq], g_hdl[2][NLq][Bq*Hq];

// ---------------- warp-mma primitives ----------------
__device__ __forceinline__ uint32_t smem_u32(const void* p) {
    uint32_t a;
    asm("{ .reg .u64 t; cvta.to.shared.u64 t, %1; cvt.u32.u64 %0, t; }" : "=r"(a) : "l"(p));
    return a;
}
__device__ __forceinline__ void ldsm4(uint32_t& r0, uint32_t& r1, uint32_t& r2, uint32_t& r3,
                                      uint32_t a) {
    asm volatile("ldmatrix.sync.aligned.m8n8.x4.shared.b16 {%0,%1,%2,%3}, [%4];"
        : "=r"(r0), "=r"(r1), "=r"(r2), "=r"(r3) : "r"(a));
}
__device__ __forceinline__ void ldsm2(uint32_t& r0, uint32_t& r1, uint32_t a) {
    asm volatile("ldmatrix.sync.aligned.m8n8.x2.shared.b16 {%0,%1}, [%2];"
        : "=r"(r0), "=r"(r1) : "r"(a));
}
__device__ __forceinline__ void mma_bf16(float* c, const uint32_t* a, const uint32_t* b) {
    asm volatile("mma.sync.aligned.m16n8k16.row.col.f32.bf16.bf16.f32 "
        "{%0,%1,%2,%3}, {%4,%5,%6,%7}, {%8,%9}, {%0,%1,%2,%3};"
        : "+f"(c[0]), "+f"(c[1]), "+f"(c[2]), "+f"(c[3])
        : "r"(a[0]), "r"(a[1]), "r"(a[2]), "r"(a[3]), "r"(b[0]), "r"(b[1]));
}

// ---------------- fp32 -> bf16 hi/lo split ----------------
__global__ void k_cvt(const float* __restrict__ s, __nv_bfloat16* __restrict__ hi,
                      __nv_bfloat16* __restrict__ lo, int n4) {
    int i = blockIdx.x * blockDim.x + threadIdx.x;
    if (i >= n4) return;
    float4 v = *(const float4*)(s + (size_t)i*4);
    __nv_bfloat16 h0 = __float2bfloat16(v.x), h1 = __float2bfloat16(v.y);
    __nv_bfloat16 h2 = __float2bfloat16(v.z), h3 = __float2bfloat16(v.w);
    __nv_bfloat162 hA, hB, lA, lB;
    hA.x = h0; hA.y = h1; hB.x = h2; hB.y = h3;
    lA.x = __float2bfloat16(v.x - __bfloat162float(h0));
    lA.y = __float2bfloat16(v.y - __bfloat162float(h1));
    lB.x = __float2bfloat16(v.z - __bfloat162float(h2));
    lB.y = __float2bfloat16(v.w - __bfloat162float(h3));
    *(__nv_bfloat162*)(hi + (size_t)i*4)     = hA;
    *(__nv_bfloat162*)(hi + (size_t)i*4 + 2) = hB;
    *(__nv_bfloat162*)(lo + (size_t)i*4)     = lA;
    *(__nv_bfloat162*)(lo + (size_t)i*4 + 2) = lB;
}

// ---------------- encoder input projection (fused hi/lo) ----------------
__global__ void k_proj(const float* __restrict__ x, const float* __restrict__ W_enc,
                       const float* __restrict__ b_enc) {
    int idx = blockIdx.x * blockDim.x + threadIdx.x;
    if (idx >= Mq*Hq) return;
    int h = idx % Hq; int bl = idx / Hq; int b = bl % Bq; int l = bl / Bq;
    float v = x[(size_t)b*2*LCq + l] * W_enc[h*2]
            + x[(size_t)b*2*LCq + LCq + l] * W_enc[h*2+1] + b_enc[h];
    __nv_bfloat16 hv = __float2bfloat16(v);
    g_xr_h[idx] = hv;
    g_xr_l[idx] = __float2bfloat16(v - __bfloat162float(hv));
}

__global__ void k_zerobar() { g_barc[0] = 0; g_barc[1] = 0; g_dbar = 0; }

// ---------------- tensor-core GEMM via warp mma ----------------
#define AROW 40
__global__ void __launch_bounds__(256) k_gemm_mma(
        const __nv_bfloat16* __restrict__ Ah, const __nv_bfloat16* __restrict__ Al,
        const __nv_bfloat16* __restrict__ Wh, const __nv_bfloat16* __restrict__ Wl,
        const float* __restrict__ bias, float* __restrict__ C,
        int K, int Nld, size_t wStrideZ, int bStrideZ, size_t cStrideZ) {
    __shared__ __nv_bfloat16 sAh[128*AROW], sAl[128*AROW];
    __shared__ __nv_bfloat16 sWh[64*AROW],  sWl[64*AROW];

    int tid = threadIdx.x, wid = tid >> 5, lane = tid & 31;
    int z = blockIdx.z;
    const __nv_bfloat16* Whz = Wh + (size_t)z*wStrideZ;
    const __nv_bfloat16* Wlz = Wl + (size_t)z*wStrideZ;
    const float* bias_z = bias + (size_t)z*bStrideZ;
    float* C_z = C + (size_t)z*cStrideZ;
    int col0 = blockIdx.x * 64, row0 = blockIdx.y * 128;
    int wm = (wid & 3) * 32, wn = (wid >> 2) * 32;

    float acc[2][4][4];
    #pragma unroll
    for (int i = 0; i < 2; i++)
        #pragma unroll
        for (int j = 0; j < 4; j++)
            #pragma unroll
            for (int k = 0; k < 4; k++) acc[i][j][k] = 0.f;

    uint32_t aBase = smem_u32(sAh), alBase = smem_u32(sAl);
    uint32_t wBase = smem_u32(sWh), wlBase = smem_u32(sWl);
    int aRow = wm + (lane & 15);
    int aCol = (lane >> 4) * 8;
    int g = lane >> 3;
    int bRow = wn + (lane & 7) + ((g >> 1) & 1) * 8;
    int bCol = (g & 1) * 8;

    for (int k0 = 0; k0 < K; k0 += 32) {
        #pragma unroll
        for (int i = 0; i < 2; i++) {
            int u = tid + (i << 8);
            int r = u >> 2, cu = u & 3;
            size_t go = (size_t)(row0 + r)*K + k0 + cu*8;
            *(uint4*)(sAh + r*AROW + cu*8) = *(const uint4*)(Ah + go);
            *(uint4*)(sAl + r*AROW + cu*8) = *(const uint4*)(Al + go);
        }
        {
            int r = tid >> 2, cu = tid & 3;
            size_t go = (size_t)(col0 + r)*K + k0 + cu*8;
            *(uint4*)(sWh + r*AROW + cu*8) = *(const uint4*)(Whz + go);
            *(uint4*)(sWl + r*AROW + cu*8) = *(const uint4*)(Wlz + go);
        }
        __syncthreads();

        #pragma unroll
        for (int ks = 0; ks < 2; ks++) {
            uint32_t ah[2][4], al[2][4], bh[2][4], bl[2][4];
            #pragma unroll
            for (int mi = 0; mi < 2; mi++) {
                uint32_t off = (uint32_t)(((aRow + mi*16)*AROW + ks*16 + aCol) * 2);
                ldsm4(ah[mi][0], ah[mi][1], ah[mi][2], ah[mi][3], aBase + off);
                ldsm4(al[mi][0], al[mi][1], al[mi][2], al[mi][3], alBase + off);
            }
            #pragma unroll
            for (int ng = 0; ng < 2; ng++) {
                uint32_t off = (uint32_t)(((bRow + ng*16)*AROW + ks*16 + bCol) * 2);
                ldsm4(bh[ng][0], bh[ng][1], bh[ng][2], bh[ng][3], wBase + off);
                ldsm4(bl[ng][0], bl[ng][1], bl[ng][2], bl[ng][3], wlBase + off);
            }
            #pragma unroll
            for (int mi = 0; mi < 2; mi++)
                #pragma unroll
                for (int ng = 0; ng < 2; ng++) {
                    #pragma unroll
                    for (int half = 0; half < 2; half++) {
                        float* c = acc[mi][ng*2 + half];
                        mma_bf16(c, ah[mi], &bh[ng][half*2]);
                        mma_bf16(c, ah[mi], &bl[ng][half*2]);
                        mma_bf16(c, al[mi], &bh[ng][half*2]);
                    }
                }
        }
        __syncthreads();
    }

    #pragma unroll
    for (int mi = 0; mi < 2; mi++) {
        int r_ = row0 + wm + mi*16 + (lane >> 2);
        #pragma unroll
        for (int ni = 0; ni < 4; ni++) {
            int c_ = col0 + wn + ni*8 + (lane & 3)*2;
            float b0 = bias_z[c_], b1 = bias_z[c_ + 1];
            float2 o0 = { acc[mi][ni][0] + b0, acc[mi][ni][1] + b1 };
            float2 o1 = { acc[mi][ni][2] + b0, acc[mi][ni][3] + b1 };
            *(float2*)(C_z + (size_t)r_*Nld + c_)       = o0;
            *(float2*)(C_z + (size_t)(r_ + 8)*Nld + c_) = o1;
        }
    }
}

// ---------------- persistent MMA encoder GRU layer (unchanged from R5) --------
#define WP 520
#define AP 72
#define ENC_SMEM ((96*WP + 128*AP) * 2)
__global__ void __launch_bounds__(256, 1) k_enc_mma(
        const float* __restrict__ Whh2, const float* __restrict__ bhh2, int layer) {
    extern __shared__ __nv_bfloat16 smb[];
    __nv_bfloat16* sWh = smb;
    __nv_bfloat16* sWl = smb + 48*WP;
    __nv_bfloat16* sAh = smb + 96*WP;
    __nv_bfloat16* sAl = smb + 96*WP + 64*AP;

    float* Y = layer ? g_y1 : g_y0;
    __nv_bfloat16* Yh = layer ? g_y1_h : g_y0_h;
    __nv_bfloat16* Yl = layer ? g_y1_l : g_y0_l;

    int bid = blockIdx.x;
    int dirv = bid >> 6;
    int rem = bid & 63;
    int cg = rem & 31;
    int bg = rem >> 5;
    int gc0 = cg * 16;
    int row0 = bg * 64;

    int tid = threadIdx.x, wid = tid >> 5, lane = tid & 31;
    int wm = (wid & 3) * 16;
    int ws = wid >> 2;

    const float* Whh = Whh2 + (size_t)dirv*H3q*Hq;
    const float* bhh = bhh2 + dirv*H3q;

    for (int u = tid; u < 48*128; u += 256) {
        int rrow = u >> 7, kq = u & 127;
        int g = rrow >> 4, c = rrow & 15;
        float4 w = __ldg((const float4*)(Whh + (size_t)(g*Hq + gc0 + c)*Hq) + kq);
        __nv_bfloat16 h0 = __float2bfloat16(w.x), h1 = __float2bfloat16(w.y);
        __nv_bfloat16 h2 = __float2bfloat16(w.z), h3 = __float2bfloat16(w.w);
        __nv_bfloat162 hh0; hh0.x = h0; hh0.y = h1;
        __nv_bfloat162 hh1; hh1.x = h2; hh1.y = h3;
        __nv_bfloat162 ll0, ll1;
        ll0.x = __float2bfloat16(w.x - __bfloat162float(h0));
        ll0.y = __float2bfloat16(w.y - __bfloat162float(h1));
        ll1.x = __float2bfloat16(w.z - __bfloat162float(h2));
        ll1.y = __float2bfloat16(w.w - __bfloat162float(h3));
        *(__nv_bfloat162*)(sWh + rrow*WP + kq*4)     = hh0;
        *(__nv_bfloat162*)(sWh + rrow*WP + kq*4 + 2) = hh1;
        *(__nv_bfloat162*)(sWl + rrow*WP + kq*4)     = ll0;
        *(__nv_bfloat162*)(sWl + rrow*WP + kq*4 + 2) = ll1;
    }
    int cA = gc0 + ws*8 + 2*(lane & 3);
    float br0 = __ldg(bhh + cA),        br1 = __ldg(bhh + cA + 1);
    float bz0 = __ldg(bhh + 512 + cA),  bz1 = __ldg(bhh + 512 + cA + 1);
    float bn0 = __ldg(bhh + 1024 + cA), bn1 = __ldg(bhh + 1024 + cA + 1);
    __syncthreads();

    uint32_t aBaseH = smem_u32(sAh), aBaseL = smem_u32(sAl);
    uint32_t wBaseH = smem_u32(sWh), wBaseL = smem_u32(sWl);
    uint32_t aOff = (uint32_t)(((wm + (lane & 15))*AP + (lane >> 4)*8) * 2);
    int bRow = ws*8 + (lane & 7);
    uint32_t bColOff = (uint32_t)((((lane >> 3) & 1) * 8) * 2);

    int ur0 = tid >> 3, uc0 = tid & 7;
    int ur1 = (tid + 256) >> 3, uc1 = (tid + 256) & 7;

    for (int s = 0; s < LCq; s++) {
        int t = dirv ? (LCq-1-s) : s;
        int tprev = dirv ? (t+1) : (t-1);

        float acc[3][4];
        #pragma unroll
        for (int g = 0; g < 3; g++) {
            acc[g][0] = acc[g][1] = acc[g][2] = acc[g][3] = 0.f;
        }

        if (s > 0) {
            const __nv_bfloat16* Ah = Yh + ((size_t)tprev*Bq)*2*Hq + (size_t)dirv*Hq;
            const __nv_bfloat16* Al = Yl + ((size_t)tprev*Bq)*2*Hq + (size_t)dirv*Hq;
            uint4 ph0, ph1, pl0, pl1;
            ph0 = __ldcg((const uint4*)(Ah + (size_t)(row0 + ur0)*2*Hq + uc0*8));
            ph1 = __ldcg((const uint4*)(Ah + (size_t)(row0 + ur1)*2*Hq + uc1*8));
            pl0 = __ldcg((const uint4*)(Al + (size_t)(row0 + ur0)*2*Hq + uc0*8));
            pl1 = __ldcg((const uint4*)(Al + (size_t)(row0 + ur1)*2*Hq + uc1*8));
            for (int kc = 0; kc < 8; kc++) {
                *(uint4*)(sAh + ur0*AP + uc0*8) = ph0;
                *(uint4*)(sAh + ur1*AP + uc1*8) = ph1;
                *(uint4*)(sAl + ur0*AP + uc0*8) = pl0;
                *(uint4*)(sAl + ur1*AP + uc1*8) = pl1;
                __syncthreads();
                if (kc < 7) {
                    int k1 = (kc + 1)*64;
                    ph0 = __ldcg((const uint4*)(Ah + (size_t)(row0 + ur0)*2*Hq + k1 + uc0*8));
                    ph1 = __ldcg((const uint4*)(Ah + (size_t)(row0 + ur1)*2*Hq + k1 + uc1*8));
                    pl0 = __ldcg((const uint4*)(Al + (size_t)(row0 + ur0)*2*Hq + k1 + uc0*8));
                    pl1 = __ldcg((const uint4*)(Al + (size_t)(row0 + ur1)*2*Hq + k1 + uc1*8));
                }
                int k0 = kc*64;
                #pragma unroll
                for (int ks = 0; ks < 4; ks++) {
                    uint32_t ah[4], al[4];
                    uint32_t ao = aOff + (uint32_t)(ks*32);
                    ldsm4(ah[0], ah[1], ah[2], ah[3], aBaseH + ao);
                    ldsm4(al[0], al[1], al[2], al[3], aBaseL + ao);
                    #pragma unroll
                    for (int g = 0; g < 3; g++) {
                        uint32_t bh[2], bl[2];
                        uint32_t wo = (uint32_t)((((g*16 + bRow)*WP) + k0 + ks*16)*2) + bColOff;
                        ldsm2(bh[0], bh[1], wBaseH + wo);
                        ldsm2(bl[0], bl[1], wBaseL + wo);
                        mma_bf16(acc[g], ah, bh);
                        mma_bf16(acc[g], ah, bl);
                        mma_bf16(acc[g], al, bh);
                    }
                }
                __syncthreads();
            }
        }

        const float* gi_t = g_gi + ((size_t)dirv*LCq + t)*Bq*H3q;
        #pragma unroll
        for (int rr = 0; rr < 2; rr++) {
            int b = row0 + wm + (lane >> 2) + rr*8;
            const float* gib = gi_t + (size_t)b*H3q;
            float2 gr = *(const float2*)(gib + cA);
            float2 gz = *(const float2*)(gib + 512 + cA);
            float2 gn = *(const float2*)(gib + 1024 + cA);
            float2 hp = make_float2(0.f, 0.f);
            if (s > 0)
                hp = __ldcg((const float2*)(Y + ((size_t)tprev*Bq + b)*2*Hq + (size_t)dirv*Hq + cA));
            float r0v = 1.f/(1.f + expf(-(gr.x + acc[0][rr*2]   + br0)));
            float r1v = 1.f/(1.f + expf(-(gr.y + acc[0][rr*2+1] + br1)));
            float z0v = 1.f/(1.f + expf(-(gz.x + acc[1][rr*2]   + bz0)));
            float z1v = 1.f/(1.f + expf(-(gz.y + acc[1][rr*2+1] + bz1)));
            float n0v = tanhf(gn.x + r0v*(acc[2][rr*2]   + bn0));
            float n1v = tanhf(gn.y + r1v*(acc[2][rr*2+1] + bn1));
            float h0v = (1.f - z0v)*n0v + z0v*hp.x;
            float h1v = (1.f - z1v)*n1v + z1v*hp.y;
            size_t o = ((size_t)t*Bq + b)*2*Hq + (size_t)dirv*Hq + cA;
            *(float2*)(Y + o) = make_float2(h0v, h1v);
            __nv_bfloat16 bh0 = __float2bfloat16(h0v), bh1 = __float2bfloat16(h1v);
            __nv_bfloat162 hv; hv.x = bh0; hv.y = bh1;
            __nv_bfloat162 lv;
            lv.x = __float2bfloat16(h0v - __bfloat162float(bh0));
            lv.y = __float2bfloat16(h1v - __bfloat162float(bh1));
            *(__nv_bfloat162*)(Yh + o) = hv;
            *(__nv_bfloat162*)(Yl + o) = lv;
        }

        __threadfence();
        __syncthreads();
        if (tid == 0) {
            atomicAdd(&g_barc[layer], 1u);
            unsigned target = 128u * (unsigned)(s + 1);
            while (*(volatile unsigned*)&g_barc[layer] < target) { }
        }
        __syncthreads();
    }
}

// ---------------- v row norms ----------------
__global__ void k_vn() {
    int row = blockIdx.x;
    int tid = threadIdx.x;
    const float* vr = g_v + (size_t)row*Hq;
    float s = 0.f;
    for (int k = tid; k < Hq; k += 128) { float x = vr[k]; s = fmaf(x, x, s); }
    __shared__ float red[128];
    red[tid] = s; __syncthreads();
    for (int o = 64; o > 0; o >>= 1) { if (tid < o) red[tid] += red[tid + o]; __syncthreads(); }
    if (tid == 0) g_vn[row] = fmaxf(sqrtf(red[0]), 1e-8f);
}

// ---------------- decoder init (fp32 + hi/lo) ----------------
__global__ void k_initdec() {
    int idx = blockIdx.x * blockDim.x + threadIdx.x;
    if (idx < Bq) g_vecin[idx] = 0;
    if (idx < Bq*Hq) {
        int b = idx / Hq, h = idx % Hq;
        float h0 = g_y0[((size_t)(LCq-1)*Bq + b)*2*Hq + h];
        float h1 = g_y0[((size_t)b)*2*Hq + Hq + h];
        g_hd[0][0][idx] = h0;
        g_hd[0][1][idx] = h1;
        __nv_bfloat16 a = __float2bfloat16(h0);
        __nv_bfloat16 c = __float2bfloat16(h1);
        g_hdh[0][0][idx] = a;
        g_hdl[0][0][idx] = __float2bfloat16(h0 - __bfloat162float(a));
        g_hdh[0][1][idx] = c;
        g_hdl[0][1][idx] = __float2bfloat16(h1 - __bfloat162float(c));
    }
}

// ================= persistent decoder =================
// smem layout (bytes):
// [0, 13824)          sWh  (96 x 72 bf16)
// [13824, 27648)      sWl
// [27648, 32256)      sXh  (32 x 72 bf16)
// [32256, 36864)      sXl
// [36864, 41472)      sHh
// [41472, 46080)      sHl
// [46080, 54784)      sAcc (4 x 32 x 17 f32)
// [54784, 54912)      vs (32 int)
#define DEC_SMEM 55296

__device__ __forceinline__ void dec_gridbar(unsigned seq) {
    __threadfence();
    __syncthreads();
    if (threadIdx.x == 0) {
        atomicAdd(&g_dbar, 1u);
        unsigned target = 128u * seq;
        while (*(volatile unsigned*)&g_dbar < target) { }
    }
    __syncthreads();
}

__device__ void dec_gru_stage(char* sm, int l, int p,
        const __nv_bfloat16* __restrict__ Wih_h, const __nv_bfloat16* __restrict__ Wih_l,
        const __nv_bfloat16* __restrict__ Whh_h, const __nv_bfloat16* __restrict__ Whh_l,
        const float* __restrict__ bih, const float* __restrict__ bhh) {
    __nv_bfloat16* sWh = (__nv_bfloat16*)sm;
    __nv_bfloat16* sWl = sWh + 96*72;
    __nv_bfloat16* sXh = sWl + 96*72;
    __nv_bfloat16* sXl = sXh + 32*72;
    __nv_bfloat16* sHh = sXl + 32*72;
    __nv_bfloat16* sHl = sHh + 32*72;
    float* sAcc = (float*)(sHl + 32*72);          // [4][32][17]
    int* vs = (int*)(sAcc + 4*32*17);

    int tid = threadIdx.x, lane = tid & 31, wid = tid >> 5;
    int cg = blockIdx.x & 31, bg = blockIdx.x >> 5;
    int gc0 = cg * 16, row0 = bg * 32;
    int wm16 = (wid & 1) * 16;
    int wq = wid >> 1;

    if (l == 0 && tid < 32) vs[tid] = __ldcg(&g_vecin[row0 + tid]);

    const __nv_bfloat16* Hh = g_hdh[p][l];
    const __nv_bfloat16* Hl = g_hdl[p][l];
    const __nv_bfloat16* Xh_g = (l == 0) ? g_emb_h : g_hdh[1-p][0];
    const __nv_bfloat16* Xl_g = (l == 0) ? g_emb_l : g_hdl[1-p][0];

    float acc[2][4] = {{0,0,0,0},{0,0,0,0}};

    uint32_t aXh = smem_u32(sXh), aXl = smem_u32(sXl);
    uint32_t aHh = smem_u32(sHh), aHl = smem_u32(sHl);
    uint32_t wBh = smem_u32(sWh), wBl = smem_u32(sWl);
    uint32_t aOffBase = (uint32_t)(((wm16 + (lane & 15))*72 + (lane >> 4)*8) * 2);
    int bRowIn = (lane & 7) + ((lane >> 4) & 1)*8;
    uint32_t bColOff = (uint32_t)((((lane >> 3) & 1) * 8) * 2);

    __syncthreads();

    for (int kc = 0; kc < 8; kc++) {
        int k0 = kc * 64;
        // stage weights: 96 rows x 64k, hi+lo
        #pragma unroll
        for (int i = 0; i < 3; i++) {
            int u = tid + i*256;
            int rr = u >> 3, ku = u & 7;
            int grow = rr < 48 ? rr : rr - 48;
            int g = grow >> 4, c = grow & 15;
            size_t src = (size_t)(g*Hq + gc0 + c)*Hq + k0 + ku*8;
            const __nv_bfloat16* MH = rr < 48 ? Wih_h : Whh_h;
            const __nv_bfloat16* ML = rr < 48 ? Wih_l : Whh_l;
            *(uint4*)(sWh + rr*72 + ku*8) = *(const uint4*)(MH + src);
            *(uint4*)(sWl + rr*72 + ku*8) = *(const uint4*)(ML + src);
        }
        // stage x and h: 32 rows x 64k, hi+lo each
        {
            int rr = tid >> 3, ku = tid & 7;
            size_t xoff;
            if (l == 0) xoff = (size_t)vs[rr]*Hq + k0 + ku*8;
            else        xoff = (size_t)(row0 + rr)*Hq + k0 + ku*8;
            if (l == 0) {
                *(uint4*)(sXh + rr*72 + ku*8) = *(const uint4*)(Xh_g + xoff);
                *(uint4*)(sXl + rr*72 + ku*8) = *(const uint4*)(Xl_g + xoff);
            } else {
                *(uint4*)(sXh + rr*72 + ku*8) = __ldcg((const uint4*)(Xh_g + xoff));
                *(uint4*)(sXl + rr*72 + ku*8) = __ldcg((const uint4*)(Xl_g + xoff));
            }
            size_t hoff = (size_t)(row0 + rr)*Hq + k0 + ku*8;
            *(uint4*)(sHh + rr*72 + ku*8) = __ldcg((const uint4*)(Hh + hoff));
            *(uint4*)(sHl + rr*72 + ku*8) = __ldcg((const uint4*)(Hl + hoff));
        }
        __syncthreads();

        #pragma unroll
        for (int ks = 0; ks < 4; ks++) {
            uint32_t ao = aOffBase + (uint32_t)(ks*32);
            uint32_t coff = bColOff + (uint32_t)(ks*32);
            if (wq < 2) {
                uint32_t axh[4], axl[4], ahh[4], ahl[4];
                ldsm4(axh[0], axh[1], axh[2], axh[3], aXh + ao);
                ldsm4(axl[0], axl[1], axl[2], axl[3], aXl + ao);
                ldsm4(ahh[0], ahh[1], ahh[2], ahh[3], aHh + ao);
                ldsm4(ahl[0], ahl[1], ahl[2], ahl[3], aHl + ao);
                int gih = wq*16, ghh = 48 + wq*16;
                uint32_t bih_h[4], bih_l[4], bhh_h[4], bhh_l[4];
                uint32_t oi = (uint32_t)(((gih + bRowIn)*72)*2) + coff;
                uint32_t oh = (uint32_t)(((ghh + bRowIn)*72)*2) + coff;
                ldsm4(bih_h[0], bih_h[1], bih_h[2], bih_h[3], wBh + oi);
                ldsm4(bih_l[0], bih_l[1], bih_l[2], bih_l[3], wBl + oi);
                ldsm4(bhh_h[0], bhh_h[1], bhh_h[2], bhh_h[3], wBh + oh);
                ldsm4(bhh_l[0], bhh_l[1], bhh_l[2], bhh_l[3], wBl + oh);
                #pragma unroll
                for (int ni = 0; ni < 2; ni++) {
                    mma_bf16(acc[ni], axh, &bih_h[ni*2]);
                    mma_bf16(acc[ni], axh, &bih_l[ni*2]);
                    mma_bf16(acc[ni], axl, &bih_h[ni*2]);
                    mma_bf16(acc[ni], ahh, &bhh_h[ni*2]);
                    mma_bf16(acc[ni], ahh, &bhh_l[ni*2]);
                    mma_bf16(acc[ni], ahl, &bhh_h[ni*2]);
                }
            } else if (wq == 2) {
                uint32_t axh[4], axl[4], bh[4], bl[4];
                ldsm4(axh[0], axh[1], axh[2], axh[3], aXh + ao);
                ldsm4(axl[0], axl[1], axl[2], axl[3], aXl + ao);
                uint32_t oi = (uint32_t)(((32 + bRowIn)*72)*2) + coff;
                ldsm4(bh[0], bh[1], bh[2], bh[3], wBh + oi);
                ldsm4(bl[0], bl[1], bl[2], bl[3], wBl + oi);
                #pragma unroll
                for (int ni = 0; ni < 2; ni++) {
                    mma_bf16(acc[ni], axh, &bh[ni*2]);
                    mma_bf16(acc[ni], axh, &bl[ni*2]);
                    mma_bf16(acc[ni], axl, &bh[ni*2]);
                }
            } else {
                uint32_t ahh[4], ahl[4], bh[4], bl[4];
                ldsm4(ahh[0], ahh[1], ahh[2], ahh[3], aHh + ao);
                ldsm4(ahl[0], ahl[1], ahl[2], ahl[3], aHl + ao);
                uint32_t oh = (uint32_t)(((80 + bRowIn)*72)*2) + coff;
                ldsm4(bh[0], bh[1], bh[2], bh[3], wBh + oh);
                ldsm4(bl[0], bl[1], bl[2], bl[3], wBl + oh);
                #pragma unroll
                for (int ni = 0; ni < 2; ni++) {
                    mma_bf16(acc[ni], ahh, &bh[ni*2]);
                    mma_bf16(acc[ni], ahh, &bl[ni*2]);
                    mma_bf16(acc[ni], ahl, &bh[ni*2]);
                }
            }
        }
        __syncthreads();
    }

    // exchange accumulators through smem
    {
        int r0 = wm16 + (lane >> 2);
        #pragma unroll
        for (int ni = 0; ni < 2; ni++) {
            int cb = ni*8 + (lane & 3)*2;
            sAcc[(wq*32 + r0)*17 + cb]       = acc[ni][0];
            sAcc[(wq*32 + r0)*17 + cb + 1]   = acc[ni][1];
            sAcc[(wq*32 + r0+8)*17 + cb]     = acc[ni][2];
            sAcc[(wq*32 + r0+8)*17 + cb + 1] = acc[ni][3];
        }
    }
    __syncthreads();

    // pointwise tail
    #pragma unroll
    for (int j = 0; j < 2; j++) {
        int e = tid + j*256;
        int row = e >> 4, col = e & 15;
        float rv  = sAcc[(0*32 + row)*17 + col];
        float zv  = sAcc[(1*32 + row)*17 + col];
        float nxv = sAcc[(2*32 + row)*17 + col];
        float nhv = sAcc[(3*32 + row)*17 + col];
        int c = gc0 + col, b = row0 + row;
        float rr = 1.f/(1.f + expf(-(rv + __ldg(bih + c) + __ldg(bhh + c))));
        float zz = 1.f/(1.f + expf(-(zv + __ldg(bih + 512 + c) + __ldg(bhh + 512 + c))));
        float nn = tanhf(nxv + __ldg(bih + 1024 + c) + rr*(nhv + __ldg(bhh + 1024 + c)));
        float hp = __ldcg(&g_hd[p][l][(size_t)b*Hq + c]);
        float h = (1.f - zz)*nn + zz*hp;
        g_hd[1-p][l][(size_t)b*Hq + c] = h;
        __nv_bfloat16 bh = __float2bfloat16(h);
        g_hdh[1-p][l][(size_t)b*Hq + c] = bh;
        g_hdl[1-p][l][(size_t)b*Hq + c] = __float2bfloat16(h - __bfloat162float(bh));
    }
}

__device__ void dec_attn_stage(char* sm, int t, int p, float* __restrict__ attn_out) {
    float* qs  = (float*)sm;            // 512
    float* red = qs + 512;              // 256
    float* wsm = red + 256;             // 256
    int b = blockIdx.x;
    int tid = threadIdx.x;

    const float* q = g_hd[1-p][1] + (size_t)b*Hq;
    qs[tid]       = __ldcg(q + tid);
    qs[tid + 256] = __ldcg(q + tid + 256);
    __syncthreads();

    float ss = qs[tid]*qs[tid] + qs[tid+256]*qs[tid+256];
    red[tid] = ss; __syncthreads();
    for (int o = 128; o > 0; o >>= 1) { if (tid < o) red[tid] += red[tid + o]; __syncthreads(); }
    float qn = fmaxf(sqrtf(red[0]), 1e-8f);
    __syncthreads();

    const float4* v4 = (const float4*)(g_v + ((size_t)tid*Bq + b)*Hq);
    const float4* q4 = (const float4*)qs;
    float dot = 0.f;
    #pragma unroll 4
    for (int k = 0; k < Hq/4; k++) {
        float4 a = v4[k], c = q4[k];
        dot = fmaf(a.x, c.x, dot); dot = fmaf(a.y, c.y, dot);
        dot = fmaf(a.z, c.z, dot); dot = fmaf(a.w, c.w, dot);
    }
    float sim = dot / (g_vn[(size_t)tid*Bq + b] * qn);

    red[tid] = sim; __syncthreads();
    for (int o = 128; o > 0; o >>= 1) { if (tid < o) red[tid] = fmaxf(red[tid], red[tid+o]); __syncthreads(); }
    float mx = red[0]; __syncthreads();
    float e = expf(sim - mx);
    red[tid] = e; __syncthreads();
    for (int o = 128; o > 0; o >>= 1) { if (tid < o) red[tid] += red[tid + o]; __syncthreads(); }
    float wv = e / red[0];
    wsm[tid] = wv;
    attn_out[((size_t)b*LCq + tid)*LTq + t] = wv;
    __syncthreads();

    for (int h = tid; h < Hq; h += 256) {
        float acc = 0.f;
        for (int l = 0; l < LCq; l++)
            acc = fmaf(wsm[l], g_v[((size_t)l*Bq + b)*Hq + h], acc);
        g_a[(size_t)b*Hq + h] = acc;
    }
}

__device__ void dec_attfc_stage(char* sm, int p,
        const float* __restrict__ Watt, const float* __restrict__ batt) {
    float* Xs  = (float*)sm;            // [32][33]
    float* As2 = Xs + 32*33;            // [32][33]
    float* Wqs = As2 + 32*33;           // [32][17]
    float* Was = Wqs + 32*17;           // [32][17]

    const float* X1 = g_hd[1-p][1];
    const float* X2 = g_a;
    int tid = threadIdx.x;
    int tx = tid & 15, ty = tid >> 4;
    int col0 = (blockIdx.x & 31) * 16, row0 = (blockIdx.x >> 5) * 32;

    float acc[2] = {0,0};
    for (int k0 = 0; k0 < Hq; k0 += KT) {
        {
            int r = tid >> 3, kk = (tid & 7) << 2;
            float4 x4 = __ldcg((const float4*)(X1 + (size_t)(row0 + r)*Hq + k0 + kk));
            Xs[kk*33 + r]=x4.x; Xs[(kk+1)*33 + r]=x4.y; Xs[(kk+2)*33 + r]=x4.z; Xs[(kk+3)*33 + r]=x4.w;
            float4 a4 = __ldcg((const float4*)(X2 + (size_t)(row0 + r)*Hq + k0 + kk));
            As2[kk*33 + r]=a4.x; As2[(kk+1)*33 + r]=a4.y; As2[(kk+2)*33 + r]=a4.z; As2[(kk+3)*33 + r]=a4.w;
        }
        #pragma unroll
        for (int j = 0; j < 2; j++) {
            int lin = tid + j*256;
            int c = lin >> 5, k = lin & 31;
            Wqs[k*17 + c] = __ldg(Watt + (size_t)(col0 + c)*2*Hq + k0 + k);
            Was[k*17 + c] = __ldg(Watt + (size_t)(col0 + c)*2*Hq + Hq + k0 + k);
        }
        __syncthreads();
        #pragma unroll
        for (int k = 0; k < KT; k++) {
            float wq = Wqs[k*17 + tx], wa = Was[k*17 + tx];
            #pragma unroll
            for (int i = 0; i < 2; i++) {
                acc[i] = fmaf(Xs[k*33 + ty + 16*i], wq, acc[i]);
                acc[i] = fmaf(As2[k*33 + ty + 16*i], wa, acc[i]);
            }
        }
        __syncthreads();
    }
    int c = col0 + tx;
    #pragma unroll
    for (int i = 0; i < 2; i++) {
        int b = row0 + ty + 16*i;
        g_hid[(size_t)b*Hq + c] = acc[i] + __ldg(batt + c);
    }
}

__device__ void dec_out_stage(char* sm, int t,
        const float* __restrict__ Wout, const float* __restrict__ bout,
        float* __restrict__ vecout) {
    float* hs = (float*)sm;             // 512
    float* lg = hs + 512;               // 32
    int b = blockIdx.x;
    int tid = threadIdx.x;
    hs[tid]       = __ldcg(&g_hid[(size_t)b*Hq + tid]);
    hs[tid + 256] = __ldcg(&g_hid[(size_t)b*Hq + tid + 256]);
    __syncthreads();

    int wid = tid >> 5, lane = tid & 31;
    for (int j = wid; j < Vq; j += 8) {
        float acc = 0.f;
        for (int k = lane; k < Hq; k += 32)
            acc = fmaf(hs[k], __ldg(Wout + (size_t)j*Hq + k), acc);
        #pragma unroll
        for (int o = 16; o > 0; o >>= 1) acc += __shfl_down_sync(0xffffffffu, acc, o);
        if (lane == 0) lg[j] = acc + __ldg(bout + j);
    }
    __syncthreads();
    if (tid < Vq) vecout[((size_t)b*LTq + t)*Vq + tid] = lg[tid];
    if (tid == 0) {
        int best = 0; float bv = lg[0];
        for (int j = 1; j < Vq; j++) { if (lg[j] > bv) { bv = lg[j]; best = j; } }
        g_vecin[b] = best;
    }
}

__global__ void __launch_bounds__(256, 1) k_dec_pers(
        const float* __restrict__ dec_bih, const float* __restrict__ dec_bhh,
        const float* __restrict__ Watt, const float* __restrict__ batt,
        const float* __restrict__ Wout, const float* __restrict__ bout,
        float* __restrict__ vecout, float* __restrict__ attn_out) {
    extern __shared__ char dsm[];
    unsigned seq = 0;
    for (int t = 0; t < LTq; t++) {
        int p = t & 1;
        dec_gru_stage(dsm, 0, p, g_dwih_h, g_dwih_l, g_dwhh_h, g_dwhh_l,
                      dec_bih, dec_bhh);
        dec_gridbar(++seq);
        dec_gru_stage(dsm, 1, p,
                      g_dwih_h + (size_t)H3q*Hq, g_dwih_l + (size_t)H3q*Hq,
                      g_dwhh_h + (size_t)H3q*Hq, g_dwhh_l + (size_t)H3q*Hq,
                      dec_bih + H3q, dec_bhh + H3q);
        dec_gridbar(++seq);
        dec_attn_stage(dsm, t, p, attn_out);
        dec_gridbar(++seq);
        dec_attfc_stage(dsm, p, Watt, batt);
        dec_gridbar(++seq);
        dec_out_stage(dsm, t, Wout, bout, vecout);
        dec_gridbar(++seq);
    }
}

// ---------------- final hidden copy ----------------
__global__ void k_hfinal(float* __restrict__ out) {
    int idx = blockIdx.x * blockDim.x + threadIdx.x;
    if (idx < NLq*Bq*Hq) out[idx] = (&g_hd[0][0][0])[idx];
}

// ---------------- launch ----------------
extern "C" void kernel_launch(void* const* d_in, const int* in_sizes, int n_in,
                              void* d_out, int out_size) {
    const float* x        = (const float*)d_in[0];
    const float* emb      = (const float*)d_in[2];
    const float* W_enc    = (const float*)d_in[3];
    const float* b_enc    = (const float*)d_in[4];
    const float* enc0_Wih = (const float*)d_in[5];
    const float* enc0_Whh = (const float*)d_in[6];
    const float* enc0_bih = (const float*)d_in[7];
    const float* enc0_bhh = (const float*)d_in[8];
    const float* enc1_Wih = (const float*)d_in[9];
    const float* enc1_Whh = (const float*)d_in[10];
    const float* enc1_bih = (const float*)d_in[11];
    const float* enc1_bhh = (const float*)d_in[12];
    const float* W_bi     = (const float*)d_in[13];
    const float* b_bi     = (const float*)d_in[14];
    const float* dec_Wih  = (const float*)d_in[15];
    const float* dec_Whh  = (const float*)d_in[16];
    const float* dec_bih  = (const float*)d_in[17];
    const float* dec_bhh  = (const float*)d_in[18];
    const float* W_att    = (const float*)d_in[19];
    const float* b_att    = (const float*)d_in[20];
    const float* W_out    = (const float*)d_in[21];
    const float* b_out    = (const float*)d_in[22];

    float* out_vec  = (float*)d_out;
    float* out_h    = out_vec + (size_t)Bq*LTq*Vq;
    float* out_attn = out_h + (size_t)NLq*Bq*Hq;

    cudaFuncSetAttribute(k_enc_mma, cudaFuncAttributeMaxDynamicSharedMemorySize, ENC_SMEM);
    cudaFuncSetAttribute(k_dec_pers, cudaFuncAttributeMaxDynamicSharedMemorySize, DEC_SMEM);

    __nv_bfloat16 *xr_h, *xr_l, *y0_h, *y0_l, *y1_h, *y1_l, *w0_h, *w0_l, *w1_h, *w1_l, *wb_h, *wb_l;
    __nv_bfloat16 *dwih_h, *dwih_l, *dwhh_h, *dwhh_l, *emb_h, *emb_l;
    cudaGetSymbolAddress((void**)&xr_h, g_xr_h); cudaGetSymbolAddress((void**)&xr_l, g_xr_l);
    cudaGetSymbolAddress((void**)&y0_h, g_y0_h); cudaGetSymbolAddress((void**)&y0_l, g_y0_l);
    cudaGetSymbolAddress((void**)&y1_h, g_y1_h); cudaGetSymbolAddress((void**)&y1_l, g_y1_l);
    cudaGetSymbolAddress((void**)&w0_h, g_w0_h); cudaGetSymbolAddress((void**)&w0_l, g_w0_l);
    cudaGetSymbolAddress((void**)&w1_h, g_w1_h); cudaGetSymbolAddress((void**)&w1_l, g_w1_l);
    cudaGetSymbolAddress((void**)&wb_h, g_wb_h); cudaGetSymbolAddress((void**)&wb_l, g_wb_l);
    cudaGetSymbolAddress((void**)&dwih_h, g_dwih_h); cudaGetSymbolAddress((void**)&dwih_l, g_dwih_l);
    cudaGetSymbolAddress((void**)&dwhh_h, g_dwhh_h); cudaGetSymbolAddress((void**)&dwhh_l, g_dwhh_l);
    cudaGetSymbolAddress((void**)&emb_h, g_emb_h); cudaGetSymbolAddress((void**)&emb_l, g_emb_l);
    float* gi_f; cudaGetSymbolAddress((void**)&gi_f, g_gi);
    float* v_f;  cudaGetSymbolAddress((void**)&v_f,  g_v);

    // projections + weight conversions
    k_proj<<<(Mq*Hq + 255)/256, 256>>>(x, W_enc, b_enc);
    k_zerobar<<<1, 1>>>();
    k_cvt<<<(2*H3q*Hq/4 + 255)/256, 256>>>(enc0_Wih, w0_h, w0_l, 2*H3q*Hq/4);
    k_cvt<<<(2*H3q*2*Hq/4 + 255)/256, 256>>>(enc1_Wih, w1_h, w1_l, 2*H3q*2*Hq/4);
    k_cvt<<<(Hq*2*Hq/4 + 255)/256, 256>>>(W_bi, wb_h, wb_l, Hq*2*Hq/4);
    k_cvt<<<(NLq*H3q*Hq/4 + 255)/256, 256>>>(dec_Wih, dwih_h, dwih_l, NLq*H3q*Hq/4);
    k_cvt<<<(NLq*H3q*Hq/4 + 255)/256, 256>>>(dec_Whh, dwhh_h, dwhh_l, NLq*H3q*Hq/4);
    k_cvt<<<(Vq*Hq/4 + 255)/256, 256>>>(emb, emb_h, emb_l, Vq*Hq/4);

    // layer 0: gi GEMM + persistent MMA recurrence
    k_gemm_mma<<<dim3(H3q/64, Mq/128, 2), 256>>>(
        xr_h, xr_l, w0_h, w0_l, enc0_bih, gi_f,
        Hq, H3q, (size_t)H3q*Hq, H3q, (size_t)Mq*H3q);
    k_enc_mma<<<128, 256, ENC_SMEM>>>(enc0_Whh, enc0_bhh, 0);

    // layer 1
    k_gemm_mma<<<dim3(H3q/64, Mq/128, 2), 256>>>(
        y0_h, y0_l, w1_h, w1_l, enc1_bih, gi_f,
        2*Hq, H3q, (size_t)H3q*2*Hq, H3q, (size_t)Mq*H3q);
    k_enc_mma<<<128, 256, ENC_SMEM>>>(enc1_Whh, enc1_bhh, 1);

    // bi_fc + norms
    k_gemm_mma<<<dim3(Hq/64, Mq/128, 1), 256>>>(
        y1_h, y1_l, wb_h, wb_l, b_bi, v_f,
        2*Hq, Hq, 0, 0, 0);
    k_vn<<<Mq, 128>>>();

    // persistent decoder
    k_initdec<<<(Bq*Hq + 255)/256, 256>>>();
    k_dec_pers<<<128, 256, DEC_SMEM>>>(dec_bih, dec_bhh, W_att, b_att,
                                       W_out, b_out, out_vec, out_attn);
    k_hfinal<<<(NLq*Bq*Hq + 255)/256, 256>>>(out_h);
    (void)in_sizes; (void)n_in; (void)out_size;
}

// round 7
// speedup vs baseline: 2.7009x; 1.0097x over previous
#include <cuda_runtime.h>
#include <cuda_bf16.h>
#include <math.h>
#include <stdint.h>

#define Bq 128
#define Hq 512
#define LCq 256
#define LTq 64
#define Vq 27
#define NLq 2
#define H3q (3*Hq)
#define KT 32
#define Mq (LCq*Bq)

// ---------------- scratch ----------------
__device__ float g_gi[(size_t)2*Mq*H3q];
__device__ float g_y0[(size_t)Mq*2*Hq];
__device__ float g_y1[(size_t)Mq*2*Hq];
__device__ float g_v [(size_t)Mq*Hq];
__device__ float g_vn[Mq];
__device__ float g_hd[2][NLq][Bq*Hq];
__device__ float g_a [Bq*Hq];
__device__ float g_hid[Bq*Hq];
__device__ int   g_vecin[Bq];
__device__ unsigned g_barc[2][4*32];   // per-layer, per-group (padded 128B)
__device__ unsigned g_dbar[4*32];      // decoder groups (padded)

// bf16 hi/lo decompositions
__device__ __nv_bfloat16 g_xr_h[(size_t)Mq*Hq],   g_xr_l[(size_t)Mq*Hq];
__device__ __nv_bfloat16 g_y0_h[(size_t)Mq*2*Hq], g_y0_l[(size_t)Mq*2*Hq];
__device__ __nv_bfloat16 g_y1_h[(size_t)Mq*2*Hq], g_y1_l[(size_t)Mq*2*Hq];
__device__ __nv_bfloat16 g_w0_h[2*H3q*Hq],   g_w0_l[2*H3q*Hq];
__device__ __nv_bfloat16 g_w1_h[2*H3q*2*Hq], g_w1_l[2*H3q*2*Hq];
__device__ __nv_bfloat16 g_wb_h[Hq*2*Hq],    g_wb_l[Hq*2*Hq];
// decoder bf16
__device__ __nv_bfloat16 g_dwih_h[NLq*H3q*Hq], g_dwih_l[NLq*H3q*Hq];
__device__ __nv_bfloat16 g_dwhh_h[NLq*H3q*Hq], g_dwhh_l[NLq*H3q*Hq];
__device__ __nv_bfloat16 g_emb_h[Vq*Hq], g_emb_l[Vq*Hq];
__device__ __nv_bfloat16 g_hdh[2][NLq][Bq*Hq], g_hdl[2][NLq][Bq*Hq];

// ---------------- warp-mma primitives ----------------
__device__ __forceinline__ uint32_t smem_u32(const void* p) {
    uint32_t a;
    asm("{ .reg .u64 t; cvta.to.shared.u64 t, %1; cvt.u32.u64 %0, t; }" : "=r"(a) : "l"(p));
    return a;
}
__device__ __forceinline__ void ldsm4(uint32_t& r0, uint32_t& r1, uint32_t& r2, uint32_t& r3,
                                      uint32_t a) {
    asm volatile("ldmatrix.sync.aligned.m8n8.x4.shared.b16 {%0,%1,%2,%3}, [%4];"
        : "=r"(r0), "=r"(r1), "=r"(r2), "=r"(r3) : "r"(a));
}
__device__ __forceinline__ void ldsm2(uint32_t& r0, uint32_t& r1, uint32_t a) {
    asm volatile("ldmatrix.sync.aligned.m8n8.x2.shared.b16 {%0,%1}, [%2];"
        : "=r"(r0), "=r"(r1) : "r"(a));
}
__device__ __forceinline__ void mma_bf16(float* c, const uint32_t* a, const uint32_t* b) {
    asm volatile("mma.sync.aligned.m16n8k16.row.col.f32.bf16.bf16.f32 "
        "{%0,%1,%2,%3}, {%4,%5,%6,%7}, {%8,%9}, {%0,%1,%2,%3};"
        : "+f"(c[0]), "+f"(c[1]), "+f"(c[2]), "+f"(c[3])
        : "r"(a[0]), "r"(a[1]), "r"(a[2]), "r"(a[3]), "r"(b[0]), "r"(b[1]));
}

// ---------------- fp32 -> bf16 hi/lo split ----------------
__global__ void k_cvt(const float* __restrict__ s, __nv_bfloat16* __restrict__ hi,
                      __nv_bfloat16* __restrict__ lo, int n4) {
    int i = blockIdx.x * blockDim.x + threadIdx.x;
    if (i >= n4) return;
    float4 v = *(const float4*)(s + (size_t)i*4);
    __nv_bfloat16 h0 = __float2bfloat16(v.x), h1 = __float2bfloat16(v.y);
    __nv_bfloat16 h2 = __float2bfloat16(v.z), h3 = __float2bfloat16(v.w);
    __nv_bfloat162 hA, hB, lA, lB;
    hA.x = h0; hA.y = h1; hB.x = h2; hB.y = h3;
    lA.x = __float2bfloat16(v.x - __bfloat162float(h0));
    lA.y = __float2bfloat16(v.y - __bfloat162float(h1));
    lB.x = __float2bfloat16(v.z - __bfloat162float(h2));
    lB.y = __float2bfloat16(v.w - __bfloat162float(h3));
    *(__nv_bfloat162*)(hi + (size_t)i*4)     = hA;
    *(__nv_bfloat162*)(hi + (size_t)i*4 + 2) = hB;
    *(__nv_bfloat162*)(lo + (size_t)i*4)     = lA;
    *(__nv_bfloat162*)(lo + (size_t)i*4 + 2) = lB;
}

// ---------------- encoder input projection (fused hi/lo) ----------------
__global__ void k_proj(const float* __restrict__ x, const float* __restrict__ W_enc,
                       const float* __restrict__ b_enc) {
    int idx = blockIdx.x * blockDim.x + threadIdx.x;
    if (idx >= Mq*Hq) return;
    int h = idx % Hq; int bl = idx / Hq; int b = bl % Bq; int l = bl / Bq;
    float v = x[(size_t)b*2*LCq + l] * W_enc[h*2]
            + x[(size_t)b*2*LCq + LCq + l] * W_enc[h*2+1] + b_enc[h];
    __nv_bfloat16 hv = __float2bfloat16(v);
    g_xr_h[idx] = hv;
    g_xr_l[idx] = __float2bfloat16(v - __bfloat162float(hv));
}

__global__ void k_zerobar() {
    for (int i = 0; i < 2; i++)
        for (int j = 0; j < 4; j++) g_barc[i][j*32] = 0;
    for (int j = 0; j < 4; j++) g_dbar[j*32] = 0;
}

// ---------------- tensor-core GEMM via warp mma (double-buffered) --------------
#define AROW 40
#define GA (128*AROW)
#define GW (64*AROW)
#define GEMM_SMEM ((4*GA + 4*GW) * 2)
__global__ void __launch_bounds__(256) k_gemm_mma(
        const __nv_bfloat16* __restrict__ Ah, const __nv_bfloat16* __restrict__ Al,
        const __nv_bfloat16* __restrict__ Wh, const __nv_bfloat16* __restrict__ Wl,
        const float* __restrict__ bias, float* __restrict__ C,
        int K, int Nld, size_t wStrideZ, int bStrideZ, size_t cStrideZ) {
    extern __shared__ __nv_bfloat16 gsm[];
    __nv_bfloat16* sAh = gsm;             // [2][GA]
    __nv_bfloat16* sAl = gsm + 2*GA;      // [2][GA]
    __nv_bfloat16* sWh = gsm + 4*GA;      // [2][GW]
    __nv_bfloat16* sWl = gsm + 4*GA + 2*GW;

    int tid = threadIdx.x, wid = tid >> 5, lane = tid & 31;
    int z = blockIdx.z;
    const __nv_bfloat16* Whz = Wh + (size_t)z*wStrideZ;
    const __nv_bfloat16* Wlz = Wl + (size_t)z*wStrideZ;
    const float* bias_z = bias + (size_t)z*bStrideZ;
    float* C_z = C + (size_t)z*cStrideZ;
    int col0 = blockIdx.x * 64, row0 = blockIdx.y * 128;
    int wm = (wid & 3) * 32, wn = (wid >> 2) * 32;

    float acc[2][4][4];
    #pragma unroll
    for (int i = 0; i < 2; i++)
        #pragma unroll
        for (int j = 0; j < 4; j++)
            #pragma unroll
            for (int k = 0; k < 4; k++) acc[i][j][k] = 0.f;

    uint32_t aBase = smem_u32(sAh), alBase = smem_u32(sAl);
    uint32_t wBase = smem_u32(sWh), wlBase = smem_u32(sWl);
    int aRow = wm + (lane & 15);
    int aCol = (lane >> 4) * 8;
    int g = lane >> 3;
    int bRow = wn + (lane & 7) + ((g >> 1) & 1) * 8;
    int bCol = (g & 1) * 8;

    // per-thread staged-load coordinates
    int r0 = tid >> 2, c0 = tid & 3;            // A rows r0 and r0+64
    int rw = tid >> 2, cw = tid & 3;            // W row rw
    size_t goA0 = (size_t)(row0 + r0)*K + c0*8;
    size_t goA1 = (size_t)(row0 + r0 + 64)*K + c0*8;
    size_t goW  = (size_t)(col0 + rw)*K + cw*8;

    uint4 rAh0 = *(const uint4*)(Ah + goA0);
    uint4 rAh1 = *(const uint4*)(Ah + goA1);
    uint4 rAl0 = *(const uint4*)(Al + goA0);
    uint4 rAl1 = *(const uint4*)(Al + goA1);
    uint4 rWh  = *(const uint4*)(Whz + goW);
    uint4 rWl  = *(const uint4*)(Wlz + goW);

    int nk = K >> 5;
    int buf = 0;
    for (int kc = 0; kc < nk; kc++) {
        __nv_bfloat16* dAh = sAh + buf*GA;
        __nv_bfloat16* dAl = sAl + buf*GA;
        __nv_bfloat16* dWh = sWh + buf*GW;
        __nv_bfloat16* dWl = sWl + buf*GW;
        *(uint4*)(dAh + r0*AROW + c0*8)        = rAh0;
        *(uint4*)(dAh + (r0 + 64)*AROW + c0*8) = rAh1;
        *(uint4*)(dAl + r0*AROW + c0*8)        = rAl0;
        *(uint4*)(dAl + (r0 + 64)*AROW + c0*8) = rAl1;
        *(uint4*)(dWh + rw*AROW + cw*8)        = rWh;
        *(uint4*)(dWl + rw*AROW + cw*8)        = rWl;
        __syncthreads();
        if (kc + 1 < nk) {
            int kn = (kc + 1) * 32;
            rAh0 = *(const uint4*)(Ah + goA0 + kn);
            rAh1 = *(const uint4*)(Ah + goA1 + kn);
            rAl0 = *(const uint4*)(Al + goA0 + kn);
            rAl1 = *(const uint4*)(Al + goA1 + kn);
            rWh  = *(const uint4*)(Whz + goW + kn);
            rWl  = *(const uint4*)(Wlz + goW + kn);
        }
        uint32_t abH = aBase + (uint32_t)(buf*GA*2);
        uint32_t abL = alBase + (uint32_t)(buf*GA*2);
        uint32_t wbH = wBase + (uint32_t)(buf*GW*2);
        uint32_t wbL = wlBase + (uint32_t)(buf*GW*2);

        #pragma unroll
        for (int ks = 0; ks < 2; ks++) {
            uint32_t ah[2][4], al[2][4], bh[2][4], bl[2][4];
            #pragma unroll
            for (int mi = 0; mi < 2; mi++) {
                uint32_t off = (uint32_t)(((aRow + mi*16)*AROW + ks*16 + aCol) * 2);
                ldsm4(ah[mi][0], ah[mi][1], ah[mi][2], ah[mi][3], abH + off);
                ldsm4(al[mi][0], al[mi][1], al[mi][2], al[mi][3], abL + off);
            }
            #pragma unroll
            for (int ng = 0; ng < 2; ng++) {
                uint32_t off = (uint32_t)(((bRow + ng*16)*AROW + ks*16 + bCol) * 2);
                ldsm4(bh[ng][0], bh[ng][1], bh[ng][2], bh[ng][3], wbH + off);
                ldsm4(bl[ng][0], bl[ng][1], bl[ng][2], bl[ng][3], wbL + off);
            }
            #pragma unroll
            for (int mi = 0; mi < 2; mi++)
                #pragma unroll
                for (int ng = 0; ng < 2; ng++) {
                    #pragma unroll
                    for (int half = 0; half < 2; half++) {
                        float* c = acc[mi][ng*2 + half];
                        mma_bf16(c, ah[mi], &bh[ng][half*2]);
                        mma_bf16(c, ah[mi], &bl[ng][half*2]);
                        mma_bf16(c, al[mi], &bh[ng][half*2]);
                    }
                }
        }
        buf ^= 1;
    }

    #pragma unroll
    for (int mi = 0; mi < 2; mi++) {
        int r_ = row0 + wm + mi*16 + (lane >> 2);
        #pragma unroll
        for (int ni = 0; ni < 4; ni++) {
            int c_ = col0 + wn + ni*8 + (lane & 3)*2;
            float b0 = bias_z[c_], b1 = bias_z[c_ + 1];
            float2 o0 = { acc[mi][ni][0] + b0, acc[mi][ni][1] + b1 };
            float2 o1 = { acc[mi][ni][2] + b0, acc[mi][ni][3] + b1 };
            *(float2*)(C_z + (size_t)r_*Nld + c_)       = o0;
            *(float2*)(C_z + (size_t)(r_ + 8)*Nld + c_) = o1;
        }
    }
}

// ---------------- persistent MMA encoder GRU layer ----------------
#define WP 520
#define AP 72
#define ENC_SMEM ((96*WP + 256*AP) * 2)
__global__ void __launch_bounds__(256, 1) k_enc_mma(
        const float* __restrict__ Whh2, const float* __restrict__ bhh2, int layer) {
    extern __shared__ __nv_bfloat16 smb[];
    __nv_bfloat16* sWh = smb;
    __nv_bfloat16* sWl = smb + 48*WP;
    __nv_bfloat16* sAh = smb + 96*WP;               // [2][64*AP]
    __nv_bfloat16* sAl = smb + 96*WP + 128*AP;      // [2][64*AP]

    float* Y = layer ? g_y1 : g_y0;
    __nv_bfloat16* Yh = layer ? g_y1_h : g_y0_h;
    __nv_bfloat16* Yl = layer ? g_y1_l : g_y0_l;

    int bid = blockIdx.x;
    int dirv = bid >> 6;
    int rem = bid & 63;
    int cg = rem & 31;
    int bg = rem >> 5;
    int gc0 = cg * 16;
    int row0 = bg * 64;
    unsigned grp = ((unsigned)dirv << 1) | (unsigned)bg;

    int tid = threadIdx.x, wid = tid >> 5, lane = tid & 31;
    int wm = (wid & 3) * 16;
    int ws = wid >> 2;

    const float* Whh = Whh2 + (size_t)dirv*H3q*Hq;
    const float* bhh = bhh2 + dirv*H3q;

    for (int u = tid; u < 48*128; u += 256) {
        int rrow = u >> 7, kq = u & 127;
        int g = rrow >> 4, c = rrow & 15;
        float4 w = __ldg((const float4*)(Whh + (size_t)(g*Hq + gc0 + c)*Hq) + kq);
        __nv_bfloat16 h0 = __float2bfloat16(w.x), h1 = __float2bfloat16(w.y);
        __nv_bfloat16 h2 = __float2bfloat16(w.z), h3 = __float2bfloat16(w.w);
        __nv_bfloat162 hh0; hh0.x = h0; hh0.y = h1;
        __nv_bfloat162 hh1; hh1.x = h2; hh1.y = h3;
        __nv_bfloat162 ll0, ll1;
        ll0.x = __float2bfloat16(w.x - __bfloat162float(h0));
        ll0.y = __float2bfloat16(w.y - __bfloat162float(h1));
        ll1.x = __float2bfloat16(w.z - __bfloat162float(h2));
        ll1.y = __float2bfloat16(w.w - __bfloat162float(h3));
        *(__nv_bfloat162*)(sWh + rrow*WP + kq*4)     = hh0;
        *(__nv_bfloat162*)(sWh + rrow*WP + kq*4 + 2) = hh1;
        *(__nv_bfloat162*)(sWl + rrow*WP + kq*4)     = ll0;
        *(__nv_bfloat162*)(sWl + rrow*WP + kq*4 + 2) = ll1;
    }
    int cA = gc0 + ws*8 + 2*(lane & 3);
    float br0 = __ldg(bhh + cA),        br1 = __ldg(bhh + cA + 1);
    float bz0 = __ldg(bhh + 512 + cA),  bz1 = __ldg(bhh + 512 + cA + 1);
    float bn0 = __ldg(bhh + 1024 + cA), bn1 = __ldg(bhh + 1024 + cA + 1);
    __syncthreads();

    uint32_t aBaseH = smem_u32(sAh), aBaseL = smem_u32(sAl);
    uint32_t wBaseH = smem_u32(sWh), wBaseL = smem_u32(sWl);
    uint32_t aOff = (uint32_t)(((wm + (lane & 15))*AP + (lane >> 4)*8) * 2);
    int bRow = ws*8 + (lane & 7);
    uint32_t bColOff = (uint32_t)((((lane >> 3) & 1) * 8) * 2);

    int ur0 = tid >> 3, uc0 = tid & 7;
    int ur1 = (tid + 256) >> 3, uc1 = (tid + 256) & 7;

    for (int s = 0; s < LCq; s++) {
        int t = dirv ? (LCq-1-s) : s;
        int tprev = dirv ? (t+1) : (t-1);

        float acc[3][4];
        #pragma unroll
        for (int g = 0; g < 3; g++) {
            acc[g][0] = acc[g][1] = acc[g][2] = acc[g][3] = 0.f;
        }

        if (s > 0) {
            const __nv_bfloat16* Ahp = Yh + ((size_t)tprev*Bq)*2*Hq + (size_t)dirv*Hq;
            const __nv_bfloat16* Alp = Yl + ((size_t)tprev*Bq)*2*Hq + (size_t)dirv*Hq;
            uint4 ph0, ph1, pl0, pl1;
            ph0 = __ldcg((const uint4*)(Ahp + (size_t)(row0 + ur0)*2*Hq + uc0*8));
            ph1 = __ldcg((const uint4*)(Ahp + (size_t)(row0 + ur1)*2*Hq + uc1*8));
            pl0 = __ldcg((const uint4*)(Alp + (size_t)(row0 + ur0)*2*Hq + uc0*8));
            pl1 = __ldcg((const uint4*)(Alp + (size_t)(row0 + ur1)*2*Hq + uc1*8));
            int buf = 0;
            for (int kc = 0; kc < 8; kc++) {
                __nv_bfloat16* dAh = sAh + buf*64*AP;
                __nv_bfloat16* dAl = sAl + buf*64*AP;
                *(uint4*)(dAh + ur0*AP + uc0*8) = ph0;
                *(uint4*)(dAh + ur1*AP + uc1*8) = ph1;
                *(uint4*)(dAl + ur0*AP + uc0*8) = pl0;
                *(uint4*)(dAl + ur1*AP + uc1*8) = pl1;
                __syncthreads();
                if (kc < 7) {
                    int k1 = (kc + 1)*64;
                    ph0 = __ldcg((const uint4*)(Ahp + (size_t)(row0 + ur0)*2*Hq + k1 + uc0*8));
                    ph1 = __ldcg((const uint4*)(Ahp + (size_t)(row0 + ur1)*2*Hq + k1 + uc1*8));
                    pl0 = __ldcg((const uint4*)(Alp + (size_t)(row0 + ur0)*2*Hq + k1 + uc0*8));
                    pl1 = __ldcg((const uint4*)(Alp + (size_t)(row0 + ur1)*2*Hq + k1 + uc1*8));
                }
                int k0 = kc*64;
                uint32_t abH = aBaseH + (uint32_t)(buf*64*AP*2);
                uint32_t abL = aBaseL + (uint32_t)(buf*64*AP*2);
                #pragma unroll
                for (int ks = 0; ks < 4; ks++) {
                    uint32_t ah[4], al[4];
                    uint32_t ao = aOff + (uint32_t)(ks*32);
                    ldsm4(ah[0], ah[1], ah[2], ah[3], abH + ao);
                    ldsm4(al[0], al[1], al[2], al[3], abL + ao);
                    #pragma unroll
                    for (int g = 0; g < 3; g++) {
                        uint32_t bh[2], bl[2];
                        uint32_t wo = (uint32_t)((((g*16 + bRow)*WP) + k0 + ks*16)*2) + bColOff;
                        ldsm2(bh[0], bh[1], wBaseH + wo);
                        ldsm2(bl[0], bl[1], wBaseL + wo);
                        mma_bf16(acc[g], ah, bh);
                        mma_bf16(acc[g], ah, bl);
                        mma_bf16(acc[g], al, bh);
                    }
                }
                buf ^= 1;
            }
        }

        const float* gi_t = g_gi + ((size_t)dirv*LCq + t)*Bq*H3q;
        #pragma unroll
        for (int rr = 0; rr < 2; rr++) {
            int b = row0 + wm + (lane >> 2) + rr*8;
            const float* gib = gi_t + (size_t)b*H3q;
            float2 gr = *(const float2*)(gib + cA);
            float2 gz = *(const float2*)(gib + 512 + cA);
            float2 gn = *(const float2*)(gib + 1024 + cA);
            float2 hp = make_float2(0.f, 0.f);
            if (s > 0)
                hp = __ldcg((const float2*)(Y + ((size_t)tprev*Bq + b)*2*Hq + (size_t)dirv*Hq + cA));
            float r0v = 1.f/(1.f + expf(-(gr.x + acc[0][rr*2]   + br0)));
            float r1v = 1.f/(1.f + expf(-(gr.y + acc[0][rr*2+1] + br1)));
            float z0v = 1.f/(1.f + expf(-(gz.x + acc[1][rr*2]   + bz0)));
            float z1v = 1.f/(1.f + expf(-(gz.y + acc[1][rr*2+1] + bz1)));
            float n0v = tanhf(gn.x + r0v*(acc[2][rr*2]   + bn0));
            float n1v = tanhf(gn.y + r1v*(acc[2][rr*2+1] + bn1));
            float h0v = (1.f - z0v)*n0v + z0v*hp.x;
            float h1v = (1.f - z1v)*n1v + z1v*hp.y;
            size_t o = ((size_t)t*Bq + b)*2*Hq + (size_t)dirv*Hq + cA;
            *(float2*)(Y + o) = make_float2(h0v, h1v);
            __nv_bfloat16 bh0 = __float2bfloat16(h0v), bh1 = __float2bfloat16(h1v);
            __nv_bfloat162 hv; hv.x = bh0; hv.y = bh1;
            __nv_bfloat162 lv;
            lv.x = __float2bfloat16(h0v - __bfloat162float(bh0));
            lv.y = __float2bfloat16(h1v - __bfloat162float(bh1));
            *(__nv_bfloat162*)(Yh + o) = hv;
            *(__nv_bfloat162*)(Yl + o) = lv;
        }

        // group-local barrier (32 blocks sharing dir+batchgroup)
        __threadfence();
        __syncthreads();
        if (tid == 0) {
            atomicAdd(&g_barc[layer][grp*32], 1u);
            unsigned target = 32u * (unsigned)(s + 1);
            while (*(volatile unsigned*)&g_barc[layer][grp*32] < target) { }
        }
        __syncthreads();
    }
}

// ---------------- v row norms ----------------
__global__ void k_vn() {
    int row = blockIdx.x;
    int tid = threadIdx.x;
    const float* vr = g_v + (size_t)row*Hq;
    float s = 0.f;
    for (int k = tid; k < Hq; k += 128) { float x = vr[k]; s = fmaf(x, x, s); }
    __shared__ float red[128];
    red[tid] = s; __syncthreads();
    for (int o = 64; o > 0; o >>= 1) { if (tid < o) red[tid] += red[tid + o]; __syncthreads(); }
    if (tid == 0) g_vn[row] = fmaxf(sqrtf(red[0]), 1e-8f);
}

// ---------------- decoder init (fp32 + hi/lo) ----------------
__global__ void k_initdec() {
    int idx = blockIdx.x * blockDim.x + threadIdx.x;
    if (idx < Bq) g_vecin[idx] = 0;
    if (idx < Bq*Hq) {
        int b = idx / Hq, h = idx % Hq;
        float h0 = g_y0[((size_t)(LCq-1)*Bq + b)*2*Hq + h];
        float h1 = g_y0[((size_t)b)*2*Hq + Hq + h];
        g_hd[0][0][idx] = h0;
        g_hd[0][1][idx] = h1;
        __nv_bfloat16 a = __float2bfloat16(h0);
        __nv_bfloat16 c = __float2bfloat16(h1);
        g_hdh[0][0][idx] = a;
        g_hdl[0][0][idx] = __float2bfloat16(h0 - __bfloat162float(a));
        g_hdh[0][1][idx] = c;
        g_hdl[0][1][idx] = __float2bfloat16(h1 - __bfloat162float(c));
    }
}

// ================= persistent decoder =================
#define DEC_SMEM 55296

__device__ __forceinline__ void dec_gridbar(unsigned seq) {
    __threadfence();
    __syncthreads();
    if (threadIdx.x == 0) {
        unsigned grp = blockIdx.x >> 5;
        atomicAdd(&g_dbar[grp*32], 1u);
        unsigned t = 32u * seq;
        while (*(volatile unsigned*)&g_dbar[0]  < t ||
               *(volatile unsigned*)&g_dbar[32] < t ||
               *(volatile unsigned*)&g_dbar[64] < t ||
               *(volatile unsigned*)&g_dbar[96] < t) { }
    }
    __syncthreads();
}

__device__ void dec_gru_stage(char* sm, int l, int p,
        const __nv_bfloat16* __restrict__ Wih_h, const __nv_bfloat16* __restrict__ Wih_l,
        const __nv_bfloat16* __restrict__ Whh_h, const __nv_bfloat16* __restrict__ Whh_l,
        const float* __restrict__ bih, const float* __restrict__ bhh) {
    __nv_bfloat16* sWh = (__nv_bfloat16*)sm;
    __nv_bfloat16* sWl = sWh + 96*72;
    __nv_bfloat16* sXh = sWl + 96*72;
    __nv_bfloat16* sXl = sXh + 32*72;
    __nv_bfloat16* sHh = sXl + 32*72;
    __nv_bfloat16* sHl = sHh + 32*72;
    float* sAcc = (float*)(sHl + 32*72);          // [4][32][17]
    int* vs = (int*)(sAcc + 4*32*17);

    int tid = threadIdx.x, lane = tid & 31, wid = tid >> 5;
    int cg = blockIdx.x & 31, bg = blockIdx.x >> 5;
    int gc0 = cg * 16, row0 = bg * 32;
    int wm16 = (wid & 1) * 16;
    int wq = wid >> 1;

    if (l == 0 && tid < 32) vs[tid] = __ldcg(&g_vecin[row0 + tid]);

    const __nv_bfloat16* Hh = g_hdh[p][l];
    const __nv_bfloat16* Hl = g_hdl[p][l];
    const __nv_bfloat16* Xh_g = (l == 0) ? g_emb_h : g_hdh[1-p][0];
    const __nv_bfloat16* Xl_g = (l == 0) ? g_emb_l : g_hdl[1-p][0];

    float acc[2][4] = {{0,0,0,0},{0,0,0,0}};

    uint32_t aXh = smem_u32(sXh), aXl = smem_u32(sXl);
    uint32_t aHh = smem_u32(sHh), aHl = smem_u32(sHl);
    uint32_t wBh = smem_u32(sWh), wBl = smem_u32(sWl);
    uint32_t aOffBase = (uint32_t)(((wm16 + (lane & 15))*72 + (lane >> 4)*8) * 2);
    int bRowIn = (lane & 7) + ((lane >> 4) & 1)*8;
    uint32_t bColOff = (uint32_t)((((lane >> 3) & 1) * 8) * 2);

    __syncthreads();

    for (int kc = 0; kc < 8; kc++) {
        int k0 = kc * 64;
        #pragma unroll
        for (int i = 0; i < 3; i++) {
            int u = tid + i*256;
            int rr = u >> 3, ku = u & 7;
            int grow = rr < 48 ? rr : rr - 48;
            int g = grow >> 4, c = grow & 15;
            size_t src = (size_t)(g*Hq + gc0 + c)*Hq + k0 + ku*8;
            const __nv_bfloat16* MH = rr < 48 ? Wih_h : Whh_h;
            const __nv_bfloat16* ML = rr < 48 ? Wih_l : Whh_l;
            *(uint4*)(sWh + rr*72 + ku*8) = *(const uint4*)(MH + src);
            *(uint4*)(sWl + rr*72 + ku*8) = *(const uint4*)(ML + src);
        }
        {
            int rr = tid >> 3, ku = tid & 7;
            size_t xoff;
            if (l == 0) xoff = (size_t)vs[rr]*Hq + k0 + ku*8;
            else        xoff = (size_t)(row0 + rr)*Hq + k0 + ku*8;
            if (l == 0) {
                *(uint4*)(sXh + rr*72 + ku*8) = *(const uint4*)(Xh_g + xoff);
                *(uint4*)(sXl + rr*72 + ku*8) = *(const uint4*)(Xl_g + xoff);
            } else {
                *(uint4*)(sXh + rr*72 + ku*8) = __ldcg((const uint4*)(Xh_g + xoff));
                *(uint4*)(sXl + rr*72 + ku*8) = __ldcg((const uint4*)(Xl_g + xoff));
            }
            size_t hoff = (size_t)(row0 + rr)*Hq + k0 + ku*8;
            *(uint4*)(sHh + rr*72 + ku*8) = __ldcg((const uint4*)(Hh + hoff));
            *(uint4*)(sHl + rr*72 + ku*8) = __ldcg((const uint4*)(Hl + hoff));
        }
        __syncthreads();

        #pragma unroll
        for (int ks = 0; ks < 4; ks++) {
            uint32_t ao = aOffBase + (uint32_t)(ks*32);
            uint32_t coff = bColOff + (uint32_t)(ks*32);
            if (wq < 2) {
                uint32_t axh[4], axl[4], ahh[4], ahl[4];
                ldsm4(axh[0], axh[1], axh[2], axh[3], aXh + ao);
                ldsm4(axl[0], axl[1], axl[2], axl[3], aXl + ao);
                ldsm4(ahh[0], ahh[1], ahh[2], ahh[3], aHh + ao);
                ldsm4(ahl[0], ahl[1], ahl[2], ahl[3], aHl + ao);
                int gih = wq*16, ghh = 48 + wq*16;
                uint32_t bih_h[4], bih_l[4], bhh_h[4], bhh_l[4];
                uint32_t oi = (uint32_t)(((gih + bRowIn)*72)*2) + coff;
                uint32_t oh = (uint32_t)(((ghh + bRowIn)*72)*2) + coff;
                ldsm4(bih_h[0], bih_h[1], bih_h[2], bih_h[3], wBh + oi);
                ldsm4(bih_l[0], bih_l[1], bih_l[2], bih_l[3], wBl + oi);
                ldsm4(bhh_h[0], bhh_h[1], bhh_h[2], bhh_h[3], wBh + oh);
                ldsm4(bhh_l[0], bhh_l[1], bhh_l[2], bhh_l[3], wBl + oh);
                #pragma unroll
                for (int ni = 0; ni < 2; ni++) {
                    mma_bf16(acc[ni], axh, &bih_h[ni*2]);
                    mma_bf16(acc[ni], axh, &bih_l[ni*2]);
                    mma_bf16(acc[ni], axl, &bih_h[ni*2]);
                    mma_bf16(acc[ni], ahh, &bhh_h[ni*2]);
                    mma_bf16(acc[ni], ahh, &bhh_l[ni*2]);
                    mma_bf16(acc[ni], ahl, &bhh_h[ni*2]);
                }
            } else if (wq == 2) {
                uint32_t axh[4], axl[4], bh[4], bl[4];
                ldsm4(axh[0], axh[1], axh[2], axh[3], aXh + ao);
                ldsm4(axl[0], axl[1], axl[2], axl[3], aXl + ao);
                uint32_t oi = (uint32_t)(((32 + bRowIn)*72)*2) + coff;
                ldsm4(bh[0], bh[1], bh[2], bh[3], wBh + oi);
                ldsm4(bl[0], bl[1], bl[2], bl[3], wBl + oi);
                #pragma unroll
                for (int ni = 0; ni < 2; ni++) {
                    mma_bf16(acc[ni], axh, &bh[ni*2]);
                    mma_bf16(acc[ni], axh, &bl[ni*2]);
                    mma_bf16(acc[ni], axl, &bh[ni*2]);
                }
            } else {
                uint32_t ahh[4], ahl[4], bh[4], bl[4];
                ldsm4(ahh[0], ahh[1], ahh[2], ahh[3], aHh + ao);
                ldsm4(ahl[0], ahl[1], ahl[2], ahl[3], aHl + ao);
                uint32_t oh = (uint32_t)(((80 + bRowIn)*72)*2) + coff;
                ldsm4(bh[0], bh[1], bh[2], bh[3], wBh + oh);
                ldsm4(bl[0], bl[1], bl[2], bl[3], wBl + oh);
                #pragma unroll
                for (int ni = 0; ni < 2; ni++) {
                    mma_bf16(acc[ni], ahh, &bh[ni*2]);
                    mma_bf16(acc[ni], ahh, &bl[ni*2]);
                    mma_bf16(acc[ni], ahl, &bh[ni*2]);
                }
            }
        }
        __syncthreads();
    }

    {
        int r0 = wm16 + (lane >> 2);
        #pragma unroll
        for (int ni = 0; ni < 2; ni++) {
            int cb = ni*8 + (lane & 3)*2;
            sAcc[(wq*32 + r0)*17 + cb]       = acc[ni][0];
            sAcc[(wq*32 + r0)*17 + cb + 1]   = acc[ni][1];
            sAcc[(wq*32 + r0+8)*17 + cb]     = acc[ni][2];
            sAcc[(wq*32 + r0+8)*17 + cb + 1] = acc[ni][3];
        }
    }
    __syncthreads();

    #pragma unroll
    for (int j = 0; j < 2; j++) {
        int e = tid + j*256;
        int row = e >> 4, col = e & 15;
        float rv  = sAcc[(0*32 + row)*17 + col];
        float zv  = sAcc[(1*32 + row)*17 + col];
        float nxv = sAcc[(2*32 + row)*17 + col];
        float nhv = sAcc[(3*32 + row)*17 + col];
        int c = gc0 + col, b = row0 + row;
        float rr = 1.f/(1.f + expf(-(rv + __ldg(bih + c) + __ldg(bhh + c))));
        float zz = 1.f/(1.f + expf(-(zv + __ldg(bih + 512 + c) + __ldg(bhh + 512 + c))));
        float nn = tanhf(nxv + __ldg(bih + 1024 + c) + rr*(nhv + __ldg(bhh + 1024 + c)));
        float hp = __ldcg(&g_hd[p][l][(size_t)b*Hq + c]);
        float h = (1.f - zz)*nn + zz*hp;
        g_hd[1-p][l][(size_t)b*Hq + c] = h;
        __nv_bfloat16 bh = __float2bfloat16(h);
        g_hdh[1-p][l][(size_t)b*Hq + c] = bh;
        g_hdl[1-p][l][(size_t)b*Hq + c] = __float2bfloat16(h - __bfloat162float(bh));
    }
}

__device__ void dec_attn_stage(char* sm, int t, int p, float* __restrict__ attn_out) {
    float* qs  = (float*)sm;
    float* red = qs + 512;
    float* wsm = red + 256;
    int b = blockIdx.x;
    int tid = threadIdx.x;

    const float* q = g_hd[1-p][1] + (size_t)b*Hq;
    qs[tid]       = __ldcg(q + tid);
    qs[tid + 256] = __ldcg(q + tid + 256);
    __syncthreads();

    float ss = qs[tid]*qs[tid] + qs[tid+256]*qs[tid+256];
    red[tid] = ss; __syncthreads();
    for (int o = 128; o > 0; o >>= 1) { if (tid < o) red[tid] += red[tid + o]; __syncthreads(); }
    float qn = fmaxf(sqrtf(red[0]), 1e-8f);
    __syncthreads();

    const float4* v4 = (const float4*)(g_v + ((size_t)tid*Bq + b)*Hq);
    const float4* q4 = (const float4*)qs;
    float dot = 0.f;
    #pragma unroll 4
    for (int k = 0; k < Hq/4; k++) {
        float4 a = v4[k], c = q4[k];
        dot = fmaf(a.x, c.x, dot); dot = fmaf(a.y, c.y, dot);
        dot = fmaf(a.z, c.z, dot); dot = fmaf(a.w, c.w, dot);
    }
    float sim = dot / (g_vn[(size_t)tid*Bq + b] * qn);

    red[tid] = sim; __syncthreads();
    for (int o = 128; o > 0; o >>= 1) { if (tid < o) red[tid] = fmaxf(red[tid], red[tid+o]); __syncthreads(); }
    float mx = red[0]; __syncthreads();
    float e = expf(sim - mx);
    red[tid] = e; __syncthreads();
    for (int o = 128; o > 0; o >>= 1) { if (tid < o) red[tid] += red[tid + o]; __syncthreads(); }
    float wv = e / red[0];
    wsm[tid] = wv;
    attn_out[((size_t)b*LCq + tid)*LTq + t] = wv;
    __syncthreads();

    for (int h = tid; h < Hq; h += 256) {
        float acc = 0.f;
        for (int l = 0; l < LCq; l++)
            acc = fmaf(wsm[l], g_v[((size_t)l*Bq + b)*Hq + h], acc);
        g_a[(size_t)b*Hq + h] = acc;
    }
}

__device__ void dec_attfc_stage(char* sm, int p,
        const float* __restrict__ Watt, const float* __restrict__ batt) {
    float* Xs  = (float*)sm;
    float* As2 = Xs + 32*33;
    float* Wqs = As2 + 32*33;
    float* Was = Wqs + 32*17;

    const float* X1 = g_hd[1-p][1];
    const float* X2 = g_a;
    int tid = threadIdx.x;
    int tx = tid & 15, ty = tid >> 4;
    int col0 = (blockIdx.x & 31) * 16, row0 = (blockIdx.x >> 5) * 32;

    float acc[2] = {0,0};
    for (int k0 = 0; k0 < Hq; k0 += KT) {
        {
            int r = tid >> 3, kk = (tid & 7) << 2;
            float4 x4 = __ldcg((const float4*)(X1 + (size_t)(row0 + r)*Hq + k0 + kk));
            Xs[kk*33 + r]=x4.x; Xs[(kk+1)*33 + r]=x4.y; Xs[(kk+2)*33 + r]=x4.z; Xs[(kk+3)*33 + r]=x4.w;
            float4 a4 = __ldcg((const float4*)(X2 + (size_t)(row0 + r)*Hq + k0 + kk));
            As2[kk*33 + r]=a4.x; As2[(kk+1)*33 + r]=a4.y; As2[(kk+2)*33 + r]=a4.z; As2[(kk+3)*33 + r]=a4.w;
        }
        #pragma unroll
        for (int j = 0; j < 2; j++) {
            int lin = tid + j*256;
            int c = lin >> 5, k = lin & 31;
            Wqs[k*17 + c] = __ldg(Watt + (size_t)(col0 + c)*2*Hq + k0 + k);
            Was[k*17 + c] = __ldg(Watt + (size_t)(col0 + c)*2*Hq + Hq + k0 + k);
        }
        __syncthreads();
        #pragma unroll
        for (int k = 0; k < KT; k++) {
            float wq = Wqs[k*17 + tx], wa = Was[k*17 + tx];
            #pragma unroll
            for (int i = 0; i < 2; i++) {
                acc[i] = fmaf(Xs[k*33 + ty + 16*i], wq, acc[i]);
                acc[i] = fmaf(As2[k*33 + ty + 16*i], wa, acc[i]);
            }
        }
        __syncthreads();
    }
    int c = col0 + tx;
    #pragma unroll
    for (int i = 0; i < 2; i++) {
        int b = row0 + ty + 16*i;
        g_hid[(size_t)b*Hq + c] = acc[i] + __ldg(batt + c);
    }
}

__device__ void dec_out_stage(char* sm, int t,
        const float* __restrict__ Wout, const float* __restrict__ bout,
        float* __restrict__ vecout) {
    float* hs = (float*)sm;
    float* lg = hs + 512;
    int b = blockIdx.x;
    int tid = threadIdx.x;
    hs[tid]       = __ldcg(&g_hid[(size_t)b*Hq + tid]);
    hs[tid + 256] = __ldcg(&g_hid[(size_t)b*Hq + tid + 256]);
    __syncthreads();

    int wid = tid >> 5, lane = tid & 31;
    for (int j = wid; j < Vq; j += 8) {
        float acc = 0.f;
        for (int k = lane; k < Hq; k += 32)
            acc = fmaf(hs[k], __ldg(Wout + (size_t)j*Hq + k), acc);
        #pragma unroll
        for (int o = 16; o > 0; o >>= 1) acc += __shfl_down_sync(0xffffffffu, acc, o);
        if (lane == 0) lg[j] = acc + __ldg(bout + j);
    }
    __syncthreads();
    if (tid < Vq) vecout[((size_t)b*LTq + t)*Vq + tid] = lg[tid];
    if (tid == 0) {
        int best = 0; float bv = lg[0];
        for (int j = 1; j < Vq; j++) { if (lg[j] > bv) { bv = lg[j]; best = j; } }
        g_vecin[b] = best;
    }
}

__global__ void __launch_bounds__(256, 1) k_dec_pers(
        const float* __restrict__ dec_bih, const float* __restrict__ dec_bhh,
        const float* __restrict__ Watt, const float* __restrict__ batt,
        const float* __restrict__ Wout, const float* __restrict__ bout,
        float* __restrict__ vecout, float* __restrict__ attn_out) {
    extern __shared__ char dsm[];
    unsigned seq = 0;
    for (int t = 0; t < LTq; t++) {
        int p = t & 1;
        dec_gru_stage(dsm, 0, p, g_dwih_h, g_dwih_l, g_dwhh_h, g_dwhh_l,
                      dec_bih, dec_bhh);
        dec_gridbar(++seq);
        dec_gru_stage(dsm, 1, p,
                      g_dwih_h + (size_t)H3q*Hq, g_dwih_l + (size_t)H3q*Hq,
                      g_dwhh_h + (size_t)H3q*Hq, g_dwhh_l + (size_t)H3q*Hq,
                      dec_bih + H3q, dec_bhh + H3q);
        dec_gridbar(++seq);
        dec_attn_stage(dsm, t, p, attn_out);
        dec_gridbar(++seq);
        dec_attfc_stage(dsm, p, Watt, batt);
        dec_gridbar(++seq);
        dec_out_stage(dsm, t, Wout, bout, vecout);
        dec_gridbar(++seq);
    }
}

// ---------------- final hidden copy ----------------
__global__ void k_hfinal(float* __restrict__ out) {
    int idx = blockIdx.x * blockDim.x + threadIdx.x;
    if (idx < NLq*Bq*Hq) out[idx] = (&g_hd[0][0][0])[idx];
}

// ---------------- launch ----------------
extern "C" void kernel_launch(void* const* d_in, const int* in_sizes, int n_in,
                              void* d_out, int out_size) {
    const float* x        = (const float*)d_in[0];
    const float* emb      = (const float*)d_in[2];
    const float* W_enc    = (const float*)d_in[3];
    const float* b_enc    = (const float*)d_in[4];
    const float* enc0_Wih = (const float*)d_in[5];
    const float* enc0_Whh = (const float*)d_in[6];
    const float* enc0_bih = (const float*)d_in[7];
    const float* enc0_bhh = (const float*)d_in[8];
    const float* enc1_Wih = (const float*)d_in[9];
    const float* enc1_Whh = (const float*)d_in[10];
    const float* enc1_bih = (const float*)d_in[11];
    const float* enc1_bhh = (const float*)d_in[12];
    const float* W_bi     = (const float*)d_in[13];
    const float* b_bi     = (const float*)d_in[14];
    const float* dec_Wih  = (const float*)d_in[15];
    const float* dec_Whh  = (const float*)d_in[16];
    const float* dec_bih  = (const float*)d_in[17];
    const float* dec_bhh  = (const float*)d_in[18];
    const float* W_att    = (const float*)d_in[19];
    const float* b_att    = (const float*)d_in[20];
    const float* W_out    = (const float*)d_in[21];
    const float* b_out    = (const float*)d_in[22];

    float* out_vec  = (float*)d_out;
    float* out_h    = out_vec + (size_t)Bq*LTq*Vq;
    float* out_attn = out_h + (size_t)NLq*Bq*Hq;

    cudaFuncSetAttribute(k_enc_mma, cudaFuncAttributeMaxDynamicSharedMemorySize, ENC_SMEM);
    cudaFuncSetAttribute(k_dec_pers, cudaFuncAttributeMaxDynamicSharedMemorySize, DEC_SMEM);
    cudaFuncSetAttribute(k_gemm_mma, cudaFuncAttributeMaxDynamicSharedMemorySize, GEMM_SMEM);

    __nv_bfloat16 *xr_h, *xr_l, *y0_h, *y0_l, *y1_h, *y1_l, *w0_h, *w0_l, *w1_h, *w1_l, *wb_h, *wb_l;
    __nv_bfloat16 *dwih_h, *dwih_l, *dwhh_h, *dwhh_l, *emb_h, *emb_l;
    cudaGetSymbolAddress((void**)&xr_h, g_xr_h); cudaGetSymbolAddress((void**)&xr_l, g_xr_l);
    cudaGetSymbolAddress((void**)&y0_h, g_y0_h); cudaGetSymbolAddress((void**)&y0_l, g_y0_l);
    cudaGetSymbolAddress((void**)&y1_h, g_y1_h); cudaGetSymbolAddress((void**)&y1_l, g_y1_l);
    cudaGetSymbolAddress((void**)&w0_h, g_w0_h); cudaGetSymbolAddress((void**)&w0_l, g_w0_l);
    cudaGetSymbolAddress((void**)&w1_h, g_w1_h); cudaGetSymbolAddress((void**)&w1_l, g_w1_l);
    cudaGetSymbolAddress((void**)&wb_h, g_wb_h); cudaGetSymbolAddress((void**)&wb_l, g_wb_l);
    cudaGetSymbolAddress((void**)&dwih_h, g_dwih_h); cudaGetSymbolAddress((void**)&dwih_l, g_dwih_l);
    cudaGetSymbolAddress((void**)&dwhh_h, g_dwhh_h); cudaGetSymbolAddress((void**)&dwhh_l, g_dwhh_l);
    cudaGetSymbolAddress((void**)&emb_h, g_emb_h); cudaGetSymbolAddress((void**)&emb_l, g_emb_l);
    float* gi_f; cudaGetSymbolAddress((void**)&gi_f, g_gi);
    float* v_f;  cudaGetSymbolAddress((void**)&v_f,  g_v);

    // projections + weight conversions
    k_proj<<<(Mq*Hq + 255)/256, 256>>>(x, W_enc, b_enc);
    k_zerobar<<<1, 1>>>();
    k_cvt<<<(2*H3q*Hq/4 + 255)/256, 256>>>(enc0_Wih, w0_h, w0_l, 2*H3q*Hq/4);
    k_cvt<<<(2*H3q*2*Hq/4 + 255)/256, 256>>>(enc1_Wih, w1_h, w1_l, 2*H3q*2*Hq/4);
    k_cvt<<<(Hq*2*Hq/4 + 255)/256, 256>>>(W_bi, wb_h, wb_l, Hq*2*Hq/4);
    k_cvt<<<(NLq*H3q*Hq/4 + 255)/256, 256>>>(dec_Wih, dwih_h, dwih_l, NLq*H3q*Hq/4);
    k_cvt<<<(NLq*H3q*Hq/4 + 255)/256, 256>>>(dec_Whh, dwhh_h, dwhh_l, NLq*H3q*Hq/4);
    k_cvt<<<(Vq*Hq/4 + 255)/256, 256>>>(emb, emb_h, emb_l, Vq*Hq/4);

    // layer 0: gi GEMM + persistent MMA recurrence
    k_gemm_mma<<<dim3(H3q/64, Mq/128, 2), 256, GEMM_SMEM>>>(
        xr_h, xr_l, w0_h, w0_l, enc0_bih, gi_f,
        Hq, H3q, (size_t)H3q*Hq, H3q, (size_t)Mq*H3q);
    k_enc_mma<<<128, 256, ENC_SMEM>>>(enc0_Whh, enc0_bhh, 0);

    // layer 1
    k_gemm_mma<<<dim3(H3q/64, Mq/128, 2), 256, GEMM_SMEM>>>(
        y0_h, y0_l, w1_h, w1_l, enc1_bih, gi_f,
        2*Hq, H3q, (size_t)H3q*2*Hq, H3q, (size_t)Mq*H3q);
    k_enc_mma<<<128, 256, ENC_SMEM>>>(enc1_Whh, enc1_bhh, 1);

    // bi_fc + norms
    k_gemm_mma<<<dim3(Hq/64, Mq/128, 1), 256, GEMM_SMEM>>>(
        y1_h, y1_l, wb_h, wb_l, b_bi, v_f,
        2*Hq, Hq, 0, 0, 0);
    k_vn<<<Mq, 128>>>();

    // persistent decoder
    k_initdec<<<(Bq*Hq + 255)/256, 256>>>();
    k_dec_pers<<<128, 256, DEC_SMEM>>>(dec_bih, dec_bhh, W_att, b_att,
                                       W_out, b_out, out_vec, out_attn);
    k_hfinal<<<(NLq*Bq*Hq + 255)/256, 256>>>(out_h);
    (void)in_sizes; (void)n_in; (void)out_size;
}